// round 4
// baseline (speedup 1.0000x reference)
#include <cuda_runtime.h>
#include <cuda_bf16.h>
#include <math.h>
#include <cstdint>

constexpr int S = 4096, HID = 2048, HQ = 16, HKV = 8, D = 128, WINDOW = 1024;

// fp32 intermediates
__device__ float g_q[(size_t)S * HQ * D];
__device__ float g_k[(size_t)S * HKV * D];
__device__ float g_v[(size_t)S * HKV * D];
__device__ float g_att[(size_t)S * HQ * D];
// bf16 hi/lo split buffers
__device__ __nv_bfloat16 g_h_hi[(size_t)S * HID],  g_h_lo[(size_t)S * HID];
__device__ __nv_bfloat16 g_wq_hi[(size_t)HQ * D * HID], g_wq_lo[(size_t)HQ * D * HID];
__device__ __nv_bfloat16 g_wk_hi[(size_t)HKV * D * HID], g_wk_lo[(size_t)HKV * D * HID];
__device__ __nv_bfloat16 g_wv_hi[(size_t)HKV * D * HID], g_wv_lo[(size_t)HKV * D * HID];
__device__ __nv_bfloat16 g_wo_hi[(size_t)HID * HQ * D], g_wo_lo[(size_t)HID * HQ * D];
__device__ __nv_bfloat16 g_a_hi[(size_t)S * HQ * D],  g_a_lo[(size_t)S * HQ * D];

// ---------------------------------------------------------------------------
__device__ __forceinline__ uint32_t smem_u32(const void* p) {
    uint32_t a;
    asm("{ .reg .u64 t; cvta.to.shared.u64 t, %1; cvt.u32.u64 %0, t; }" : "=r"(a) : "l"(p));
    return a;
}
__device__ __forceinline__ void mbar_init(uint32_t mbar, uint32_t cnt) {
    asm volatile("mbarrier.init.shared.b64 [%0], %1;" :: "r"(mbar), "r"(cnt) : "memory");
}
__device__ __forceinline__ void mbar_expect_tx(uint32_t mbar, uint32_t tx) {
    asm volatile("mbarrier.arrive.expect_tx.shared.b64 _, [%0], %1;" :: "r"(mbar), "r"(tx) : "memory");
}
__device__ __forceinline__ void mbar_wait(uint32_t mbar, uint32_t parity) {
    asm volatile(
        "{\n\t.reg .pred P1;\n\t"
        "LAB_%=:\n\t"
        "mbarrier.try_wait.parity.acquire.cta.shared::cta.b64 P1, [%0], %1, 0x989680;\n\t"
        "@!P1 bra LAB_%=;\n\t}"
        :: "r"(mbar), "r"(parity) : "memory");
}
__device__ __forceinline__ void bulk_cp(uint32_t dst, const void* src, uint32_t bytes, uint32_t mbar) {
    asm volatile(
        "cp.async.bulk.shared::cluster.global.mbarrier::complete_tx::bytes [%0], [%1], %2, [%3];"
        :: "r"(dst), "l"(src), "r"(bytes), "r"(mbar) : "memory");
}

#define LDSM_X4(r0, r1, r2, r3, addr) \
    asm volatile("ldmatrix.sync.aligned.m8n8.x4.shared.b16 {%0,%1,%2,%3}, [%4];" \
                 : "=r"(r0), "=r"(r1), "=r"(r2), "=r"(r3) : "r"(addr))

#define MMA16816(d, a, b) \
    asm volatile("mma.sync.aligned.m16n8k16.row.col.f32.bf16.bf16.f32 " \
                 "{%0,%1,%2,%3},{%4,%5,%6,%7},{%8,%9},{%0,%1,%2,%3};" \
                 : "+f"((d)[0]), "+f"((d)[1]), "+f"((d)[2]), "+f"((d)[3]) \
                 : "r"((a)[0]), "r"((a)[1]), "r"((a)[2]), "r"((a)[3]), \
                   "r"((b)[0]), "r"((b)[1]))

// ---------------------------------------------------------------------------
// fp32 -> bf16 hi/lo split
// ---------------------------------------------------------------------------
__global__ __launch_bounds__(256)
void split_hilo(const float* __restrict__ x, __nv_bfloat16* __restrict__ hi,
                __nv_bfloat16* __restrict__ lo, int n) {
    int i = (blockIdx.x * 256 + threadIdx.x) * 4;
    if (i >= n) return;
    float4 v = *(const float4*)(x + i);
    __nv_bfloat162 h01, h23, l01, l23;
    h01.x = __float2bfloat16(v.x); h01.y = __float2bfloat16(v.y);
    h23.x = __float2bfloat16(v.z); h23.y = __float2bfloat16(v.w);
    l01.x = __float2bfloat16(v.x - __bfloat162float(h01.x));
    l01.y = __float2bfloat16(v.y - __bfloat162float(h01.y));
    l23.x = __float2bfloat16(v.z - __bfloat162float(h23.x));
    l23.y = __float2bfloat16(v.w - __bfloat162float(h23.y));
    *(__nv_bfloat162*)(hi + i)     = h01;
    *(__nv_bfloat162*)(hi + i + 2) = h23;
    *(__nv_bfloat162*)(lo + i)     = l01;
    *(__nv_bfloat162*)(lo + i + 2) = l23;
}

// ---------------------------------------------------------------------------
// Tensor-core GEMM: C[M,N] = (Ah+Al)[M,K] @ (Bh+Bl)[N,K]^T, fp32 accum.
// 128x128 CTA tile, BK=64, 8 warps (2x4), mma.sync m16n8k16 bf16.
// cp.async.bulk 128B row copies into 144B-pitch smem (conflict-free ldmatrix,
// no swizzle), double-buffered, mbarrier-paced.
// ---------------------------------------------------------------------------
constexpr int ROW_PITCH  = 144;                 // 128B row + 16B rotate pad
constexpr int TILE_BYTES = 128 * ROW_PITCH;     // 18432
constexpr int BUF_BYTES  = 4 * TILE_BYTES;      // 73728 (Ah, Al, Bh, Bl)
constexpr int TILES_OFF  = 64;                  // [0..16) two mbarriers
constexpr int GEMM_SMEM  = TILES_OFF + 2 * BUF_BYTES;
constexpr uint32_t CHUNK_TX = 4 * 128 * 128;    // 65536 bytes copied per chunk

__global__ __launch_bounds__(256, 1)
void gemm_mma(const __nv_bfloat16* __restrict__ Ah, const __nv_bfloat16* __restrict__ Al,
              const __nv_bfloat16* __restrict__ Bh, const __nv_bfloat16* __restrict__ Bl,
              float* __restrict__ C, int N, int K) {
    extern __shared__ char smem[];
    const uint32_t sb = smem_u32(smem);
    const int tid = threadIdx.x;
    const int wid = tid >> 5;
    const int lane = tid & 31;
    const int wm = wid >> 2;          // 0..1  (64-row band)
    const int wn = wid & 3;           // 0..3  (32-col band)
    const int bm = blockIdx.y * 128;
    const int bn = blockIdx.x * 128;

    const __nv_bfloat16* srcs[4] = { Ah, Al, Bh, Bl };
    const int row0s[4] = { bm, bm, bn, bn };

    if (tid == 0) { mbar_init(sb + 0, 1); mbar_init(sb + 8, 1); }
    __syncthreads();

    // copy chunk c (k0 = c*64) into buffer (c&1): 512 rows of 128B, 2 per thread
    auto issue_copy = [&](int c) {
        const int buf = c & 1;
        const uint32_t mbar = sb + buf * 8;
        if (tid == 0) mbar_expect_tx(mbar, CHUNK_TX);
        const uint32_t base = sb + TILES_OFF + (uint32_t)buf * BUF_BYTES;
        const int k0 = c << 6;
#pragma unroll
        for (int i = 0; i < 2; i++) {
            int g = tid + i * 256;            // 0..511
            int t = g >> 7;
            int r = g & 127;
            const void* src = srcs[t] + (size_t)(row0s[t] + r) * K + k0;
            bulk_cp(base + (uint32_t)g * ROW_PITCH, src, 128, mbar);
        }
    };

    float acc[4][4][4];
#pragma unroll
    for (int a = 0; a < 4; a++)
#pragma unroll
        for (int b = 0; b < 4; b++)
#pragma unroll
            for (int x = 0; x < 4; x++) acc[a][b][x] = 0.f;

    // per-lane ldmatrix addressing (144B pitch, no swizzle)
    const int arow = (lane & 15);                 // A sub-row within m16
    const int ahi  = lane >> 4;                   // +chunk for k8 half
    uint32_t a_rowoff[4];
#pragma unroll
    for (int mf = 0; mf < 4; mf++)
        a_rowoff[mf] = (uint32_t)((wm * 64 + mf * 16 + arow) * ROW_PITCH);

    const int bnrow = (lane & 7) + ((lane >> 4) & 1) * 8;  // B sub-row (n) within n16
    const int bhi   = (lane >> 3) & 1;                     // +chunk for k8 half
    uint32_t b_rowoff[2];
#pragma unroll
    for (int bf = 0; bf < 2; bf++)
        b_rowoff[bf] = (uint32_t)((wn * 32 + bf * 16 + bnrow) * ROW_PITCH);

    const int NC = K >> 6;
    issue_copy(0);
    if (NC > 1) issue_copy(1);

    int ph[2] = {0, 0};
    for (int c = 0; c < NC; c++) {
        const int buf = c & 1;
        mbar_wait(sb + buf * 8, ph[buf]);
        ph[buf] ^= 1;

        const uint32_t base = sb + TILES_OFF + (uint32_t)buf * BUF_BYTES;
        const uint32_t A_hi_b = base,                  A_lo_b = base + TILE_BYTES;
        const uint32_t B_hi_b = base + 2 * TILE_BYTES, B_lo_b = base + 3 * TILE_BYTES;

#pragma unroll
        for (int ks = 0; ks < 4; ks++) {
            uint32_t ah[4][4], al[4][4], bh[2][4], bl[2][4];
            const uint32_t aoff = (uint32_t)((ks * 2 + ahi) * 16);
            const uint32_t boff = (uint32_t)((ks * 2 + bhi) * 16);
#pragma unroll
            for (int mf = 0; mf < 4; mf++) {
                uint32_t off = a_rowoff[mf] + aoff;
                LDSM_X4(ah[mf][0], ah[mf][1], ah[mf][2], ah[mf][3], A_hi_b + off);
                LDSM_X4(al[mf][0], al[mf][1], al[mf][2], al[mf][3], A_lo_b + off);
            }
#pragma unroll
            for (int bf = 0; bf < 2; bf++) {
                uint32_t off = b_rowoff[bf] + boff;
                LDSM_X4(bh[bf][0], bh[bf][1], bh[bf][2], bh[bf][3], B_hi_b + off);
                LDSM_X4(bl[bf][0], bl[bf][1], bl[bf][2], bl[bf][3], B_lo_b + off);
            }
#pragma unroll
            for (int mf = 0; mf < 4; mf++)
#pragma unroll
                for (int nf = 0; nf < 4; nf++) {
                    uint32_t* bhp = &bh[nf >> 1][(nf & 1) * 2];
                    uint32_t* blp = &bl[nf >> 1][(nf & 1) * 2];
                    MMA16816(acc[mf][nf], ah[mf], bhp);
                    MMA16816(acc[mf][nf], ah[mf], blp);
                    MMA16816(acc[mf][nf], al[mf], bhp);
                }
        }
        __syncthreads();                 // all warps done reading buffer `buf`
        if (c + 2 < NC) issue_copy(c + 2);
    }

    // epilogue: frag (r = lane>>2 [+8], c = (lane&3)*2)
    const int er = lane >> 2;
    const int ec = (lane & 3) * 2;
#pragma unroll
    for (int mf = 0; mf < 4; mf++) {
        const int r0 = bm + wm * 64 + mf * 16 + er;
#pragma unroll
        for (int nf = 0; nf < 4; nf++) {
            const int cc = bn + wn * 32 + nf * 8 + ec;
            *(float2*)(C + (size_t)r0 * N + cc)       = make_float2(acc[mf][nf][0], acc[mf][nf][1]);
            *(float2*)(C + (size_t)(r0 + 8) * N + cc) = make_float2(acc[mf][nf][2], acc[mf][nf][3]);
        }
    }
}

// ---------------------------------------------------------------------------
// Fused RMSNorm + RoPE (in place on [S, H, D])
// ---------------------------------------------------------------------------
__global__ __launch_bounds__(128)
void rmsnorm_rope(float* __restrict__ X, const float* __restrict__ w,
                  const float* __restrict__ cosp, const float* __restrict__ sinp,
                  int H) {
    const int s = blockIdx.x, h = blockIdx.y, d = threadIdx.x;
    float* row = X + ((size_t)s * H + h) * D;
    float x = row[d];
    float sq = x * x;
#pragma unroll
    for (int o = 16; o > 0; o >>= 1) sq += __shfl_xor_sync(0xffffffffu, sq, o);
    __shared__ float red[4];
    __shared__ float xs[D];
    if ((d & 31) == 0) red[d >> 5] = sq;
    __syncthreads();
    float var = (red[0] + red[1] + red[2] + red[3]) * (1.0f / D);
    float xn = x * rsqrtf(var + 1e-6f) * w[d];
    xs[d] = xn;
    __syncthreads();
    float other = (d < 64) ? -xs[d + 64] : xs[d - 64];
    row[d] = fmaf(xn, cosp[s * D + d], other * sinp[s * D + d]);
}

// ---------------------------------------------------------------------------
// Sliding-window flash attention (fp32), 64 queries x 4 lanes/query per block
// ---------------------------------------------------------------------------
__global__ __launch_bounds__(256, 2)
void attn_kernel() {
    const int h   = blockIdx.y;
    const int kh  = h >> 1;
    const int qt  = blockIdx.x;
    const int tid = threadIdx.x;
    const int qi  = qt * 64 + (tid >> 2);
    const int ld  = tid & 3;

    __shared__ float Ks[32][128];
    __shared__ float Vs[32][128];

    float qr[32];
    const float* qp = g_q + ((size_t)qi * HQ + h) * D;
#pragma unroll
    for (int u = 0; u < 8; u++)
        *(float4*)&qr[u * 4] = *(const float4*)(qp + u * 16 + ld * 4);

    float m = -1e30f, l = 0.f;
    float acc[32];
#pragma unroll
    for (int d = 0; d < 32; d++) acc[d] = 0.f;

    int jlo = qt * 64 - (WINDOW - 1);
    if (jlo < 0) jlo = 0;
    int j0 = jlo & ~31;
    const int jend = qt * 64 + 64;

    for (; j0 < jend; j0 += 32) {
        __syncthreads();
#pragma unroll
        for (int u = 0; u < 4; u++) {
            int idx = tid + u * 256;
            int r = idx >> 5;
            int c = (idx & 31) * 4;
            size_t goff = ((size_t)(j0 + r) * HKV + kh) * D + c;
            *(float4*)&Ks[r][c] = *(const float4*)(g_k + goff);
            *(float4*)&Vs[r][c] = *(const float4*)(g_v + goff);
        }
        __syncthreads();

        for (int j = 0; j < 32; j++) {
            const int jj = j0 + j;
            float sv = 0.f;
#pragma unroll
            for (int u = 0; u < 8; u++) {
                float4 kv = *(const float4*)&Ks[j][u * 16 + ld * 4];
                sv = fmaf(qr[u * 4 + 0], kv.x, sv);
                sv = fmaf(qr[u * 4 + 1], kv.y, sv);
                sv = fmaf(qr[u * 4 + 2], kv.z, sv);
                sv = fmaf(qr[u * 4 + 3], kv.w, sv);
            }
            sv += __shfl_xor_sync(0xffffffffu, sv, 1);
            sv += __shfl_xor_sync(0xffffffffu, sv, 2);
            if (jj <= qi && jj > qi - WINDOW) {
                sv *= 0.088388347648318447f;
                if (sv > m) {
                    const float c = __expf(m - sv);
                    l *= c;
#pragma unroll
                    for (int d = 0; d < 32; d++) acc[d] *= c;
                    m = sv;
                }
                const float p = __expf(sv - m);
                l += p;
#pragma unroll
                for (int u = 0; u < 8; u++) {
                    float4 vv = *(const float4*)&Vs[j][u * 16 + ld * 4];
                    acc[u * 4 + 0] = fmaf(p, vv.x, acc[u * 4 + 0]);
                    acc[u * 4 + 1] = fmaf(p, vv.y, acc[u * 4 + 1]);
                    acc[u * 4 + 2] = fmaf(p, vv.z, acc[u * 4 + 2]);
                    acc[u * 4 + 3] = fmaf(p, vv.w, acc[u * 4 + 3]);
                }
            }
        }
    }

    const float inv = 1.f / l;
    float* op = g_att + ((size_t)qi * HQ + h) * D;
#pragma unroll
    for (int u = 0; u < 8; u++) {
        float4 o = make_float4(acc[u * 4 + 0] * inv, acc[u * 4 + 1] * inv,
                               acc[u * 4 + 2] * inv, acc[u * 4 + 3] * inv);
        *(float4*)(op + u * 16 + ld * 4) = o;
    }
}

// ---------------------------------------------------------------------------
extern "C" void kernel_launch(void* const* d_in, const int* in_sizes, int n_in,
                              void* d_out, int out_size) {
    const float* hidden = (const float*)d_in[0];
    const float* cosp   = (const float*)d_in[1];
    const float* sinp   = (const float*)d_in[2];
    const float* Wq     = (const float*)d_in[3];
    const float* Wk     = (const float*)d_in[4];
    const float* Wv     = (const float*)d_in[5];
    const float* Wo     = (const float*)d_in[6];
    const float* qw     = (const float*)d_in[7];
    const float* kw     = (const float*)d_in[8];
    float* out = (float*)d_out;

    float *q, *k, *v, *att;
    cudaGetSymbolAddress((void**)&q,   g_q);
    cudaGetSymbolAddress((void**)&k,   g_k);
    cudaGetSymbolAddress((void**)&v,   g_v);
    cudaGetSymbolAddress((void**)&att, g_att);
    __nv_bfloat16 *hh, *hl, *qh, *ql, *kh, *kl, *vh, *vl, *oh, *ol, *ah, *al;
    cudaGetSymbolAddress((void**)&hh, g_h_hi);  cudaGetSymbolAddress((void**)&hl, g_h_lo);
    cudaGetSymbolAddress((void**)&qh, g_wq_hi); cudaGetSymbolAddress((void**)&ql, g_wq_lo);
    cudaGetSymbolAddress((void**)&kh, g_wk_hi); cudaGetSymbolAddress((void**)&kl, g_wk_lo);
    cudaGetSymbolAddress((void**)&vh, g_wv_hi); cudaGetSymbolAddress((void**)&vl, g_wv_lo);
    cudaGetSymbolAddress((void**)&oh, g_wo_hi); cudaGetSymbolAddress((void**)&ol, g_wo_lo);
    cudaGetSymbolAddress((void**)&ah, g_a_hi);  cudaGetSymbolAddress((void**)&al, g_a_lo);

    cudaFuncSetAttribute(gemm_mma, cudaFuncAttributeMaxDynamicSharedMemorySize, GEMM_SMEM);

    const int nH = S * HID, nWq = HQ * D * HID, nWk = HKV * D * HID, nWo = HID * HQ * D;
    split_hilo<<<nH  / 1024, 256>>>(hidden, hh, hl, nH);
    split_hilo<<<nWq / 1024, 256>>>(Wq, qh, ql, nWq);
    split_hilo<<<nWk / 1024, 256>>>(Wk, kh, kl, nWk);
    split_hilo<<<nWk / 1024, 256>>>(Wv, vh, vl, nWk);
    split_hilo<<<nWo / 1024, 256>>>(Wo, oh, ol, nWo);

    gemm_mma<<<dim3((HQ * D) / 128, S / 128), 256, GEMM_SMEM>>>(hh, hl, qh, ql, q, HQ * D, HID);
    gemm_mma<<<dim3((HKV * D) / 128, S / 128), 256, GEMM_SMEM>>>(hh, hl, kh, kl, k, HKV * D, HID);
    gemm_mma<<<dim3((HKV * D) / 128, S / 128), 256, GEMM_SMEM>>>(hh, hl, vh, vl, v, HKV * D, HID);

    rmsnorm_rope<<<dim3(S, HQ), D>>>(q, qw, cosp, sinp, HQ);
    rmsnorm_rope<<<dim3(S, HKV), D>>>(k, kw, cosp, sinp, HKV);

    attn_kernel<<<dim3(S / 64, HQ), 256>>>();

    const int nA = S * HQ * D;
    split_hilo<<<nA / 1024, 256>>>(att, ah, al, nA);
    gemm_mma<<<dim3(HID / 128, S / 128), 256, GEMM_SMEM>>>(ah, al, oh, ol, out, HID, HQ * D);
}

// round 6
// speedup vs baseline: 3.1385x; 3.1385x over previous
#include <cuda_runtime.h>
#include <cuda_bf16.h>
#include <math.h>
#include <cstdint>

constexpr int S = 4096, HID = 2048, HQ = 16, HKV = 8, D = 128, WINDOW = 1024;

// fp32 intermediates
__device__ float g_q[(size_t)S * HQ * D];
__device__ float g_k[(size_t)S * HKV * D];
__device__ float g_v[(size_t)S * HKV * D];
__device__ float g_att[(size_t)S * HQ * D];
// bf16 hi/lo split buffers (GEMM inputs)
__device__ __nv_bfloat16 g_h_hi[(size_t)S * HID],  g_h_lo[(size_t)S * HID];
__device__ __nv_bfloat16 g_wq_hi[(size_t)HQ * D * HID], g_wq_lo[(size_t)HQ * D * HID];
__device__ __nv_bfloat16 g_wk_hi[(size_t)HKV * D * HID], g_wk_lo[(size_t)HKV * D * HID];
__device__ __nv_bfloat16 g_wv_hi[(size_t)HKV * D * HID], g_wv_lo[(size_t)HKV * D * HID];
__device__ __nv_bfloat16 g_wo_hi[(size_t)HID * HQ * D], g_wo_lo[(size_t)HID * HQ * D];
__device__ __nv_bfloat16 g_a_hi[(size_t)S * HQ * D],  g_a_lo[(size_t)S * HQ * D];
// bf16 hi/lo attention operands
__device__ __nv_bfloat16 g_qbh[(size_t)S * HQ * D],  g_qbl[(size_t)S * HQ * D];
__device__ __nv_bfloat16 g_kbh[(size_t)S * HKV * D], g_kbl[(size_t)S * HKV * D];
__device__ __nv_bfloat16 g_vbh[(size_t)S * HKV * D], g_vbl[(size_t)S * HKV * D];

// ---------------------------------------------------------------------------
__device__ __forceinline__ uint32_t smem_u32(const void* p) {
    uint32_t a;
    asm("{ .reg .u64 t; cvta.to.shared.u64 t, %1; cvt.u32.u64 %0, t; }" : "=r"(a) : "l"(p));
    return a;
}
__device__ __forceinline__ uint32_t swz(uint32_t o) { return o ^ ((o >> 3) & 0x70); }
// 256B-row swizzle: 16 chunks of 16B, low-3 chunk bits XOR row&7
__device__ __forceinline__ uint32_t sw256(int r, int c) {
    return (uint32_t)(r * 256 + (((c ^ r) & 7) << 4) + ((c & 8) << 4));
}

#define CP_ASYNC16(dst, src) \
    asm volatile("cp.async.cg.shared.global [%0], [%1], 16;" :: "r"(dst), "l"(src))
#define CP_COMMIT() asm volatile("cp.async.commit_group;" ::: "memory")
#define CP_WAIT1()  asm volatile("cp.async.wait_group 1;" ::: "memory")
#define CP_WAIT0()  asm volatile("cp.async.wait_group 0;" ::: "memory")

#define LDSM_X4(r0, r1, r2, r3, addr) \
    asm volatile("ldmatrix.sync.aligned.m8n8.x4.shared.b16 {%0,%1,%2,%3}, [%4];" \
                 : "=r"(r0), "=r"(r1), "=r"(r2), "=r"(r3) : "r"(addr))
#define LDSM_X4_T(r0, r1, r2, r3, addr) \
    asm volatile("ldmatrix.sync.aligned.m8n8.x4.trans.shared.b16 {%0,%1,%2,%3}, [%4];" \
                 : "=r"(r0), "=r"(r1), "=r"(r2), "=r"(r3) : "r"(addr))

#define MMA16816(d, a, b) \
    asm volatile("mma.sync.aligned.m16n8k16.row.col.f32.bf16.bf16.f32 " \
                 "{%0,%1,%2,%3},{%4,%5,%6,%7},{%8,%9},{%0,%1,%2,%3};" \
                 : "+f"((d)[0]), "+f"((d)[1]), "+f"((d)[2]), "+f"((d)[3]) \
                 : "r"((a)[0]), "r"((a)[1]), "r"((a)[2]), "r"((a)[3]), \
                   "r"((b)[0]), "r"((b)[1]))

__device__ __forceinline__ uint32_t pack_bf16(float a, float b) {
    __nv_bfloat162 t;
    t.x = __float2bfloat16(a); t.y = __float2bfloat16(b);
    return *(uint32_t*)&t;
}

// ---------------------------------------------------------------------------
// fp32 -> bf16 hi/lo split
// ---------------------------------------------------------------------------
__global__ __launch_bounds__(256)
void split_hilo(const float* __restrict__ x, __nv_bfloat16* __restrict__ hi,
                __nv_bfloat16* __restrict__ lo, int n) {
    int i = (blockIdx.x * 256 + threadIdx.x) * 4;
    if (i >= n) return;
    float4 v = *(const float4*)(x + i);
    __nv_bfloat162 h01, h23, l01, l23;
    h01.x = __float2bfloat16(v.x); h01.y = __float2bfloat16(v.y);
    h23.x = __float2bfloat16(v.z); h23.y = __float2bfloat16(v.w);
    l01.x = __float2bfloat16(v.x - __bfloat162float(h01.x));
    l01.y = __float2bfloat16(v.y - __bfloat162float(h01.y));
    l23.x = __float2bfloat16(v.z - __bfloat162float(h23.x));
    l23.y = __float2bfloat16(v.w - __bfloat162float(h23.y));
    *(__nv_bfloat162*)(hi + i)     = h01;
    *(__nv_bfloat162*)(hi + i + 2) = h23;
    *(__nv_bfloat162*)(lo + i)     = l01;
    *(__nv_bfloat162*)(lo + i + 2) = l23;
}

// ---------------------------------------------------------------------------
// Tensor-core GEMM (round-3 version): C = (Ah+Al)(Bh+Bl)^T, 3-term split.
// ---------------------------------------------------------------------------
constexpr int TILE_BYTES = 128 * 64 * 2;
constexpr int BUF_BYTES  = 4 * TILE_BYTES;
constexpr int GEMM_SMEM  = 2 * BUF_BYTES;

__global__ __launch_bounds__(256, 1)
void gemm_mma(const __nv_bfloat16* __restrict__ Ah, const __nv_bfloat16* __restrict__ Al,
              const __nv_bfloat16* __restrict__ Bh, const __nv_bfloat16* __restrict__ Bl,
              float* __restrict__ C, int N, int K) {
    extern __shared__ char smem[];
    const uint32_t sb = smem_u32(smem);
    const int tid = threadIdx.x;
    const int wid = tid >> 5;
    const int lane = tid & 31;
    const int wm = wid >> 2;
    const int wn = wid & 3;
    const int bm = blockIdx.y * 128;
    const int bn = blockIdx.x * 128;

    const __nv_bfloat16* srcs[4] = { Ah, Al, Bh, Bl };
    const int row0s[4] = { bm, bm, bn, bn };

    auto issue_copy = [&](int c) {
        const uint32_t base = sb + (uint32_t)(c & 1) * BUF_BYTES;
        const int k0 = c << 6;
#pragma unroll
        for (int t = 0; t < 4; t++) {
            const __nv_bfloat16* src = srcs[t];
            const int row0 = row0s[t];
            const uint32_t tbase = base + t * TILE_BYTES;
#pragma unroll
            for (int i = 0; i < 4; i++) {
                int idx = tid + i * 256;
                int r  = idx >> 3;
                int cc = idx & 7;
                uint32_t dst = tbase + swz((uint32_t)(r * 128 + cc * 16));
                const void* s = src + (size_t)(row0 + r) * K + k0 + cc * 8;
                CP_ASYNC16(dst, s);
            }
        }
        CP_COMMIT();
    };

    float acc[4][4][4];
#pragma unroll
    for (int a = 0; a < 4; a++)
#pragma unroll
        for (int b = 0; b < 4; b++)
#pragma unroll
            for (int x = 0; x < 4; x++) acc[a][b][x] = 0.f;

    const int arow = (lane & 15);
    const int ahi  = lane >> 4;
    uint32_t a_rowoff[4];
#pragma unroll
    for (int mf = 0; mf < 4; mf++)
        a_rowoff[mf] = (uint32_t)((wm * 64 + mf * 16 + arow) * 128);
    const uint32_t arx = (uint32_t)(arow & 7);

    const int bnrow = (lane & 7) + ((lane >> 4) & 1) * 8;
    const int bhi   = (lane >> 3) & 1;
    uint32_t b_rowoff[2];
#pragma unroll
    for (int bf = 0; bf < 2; bf++)
        b_rowoff[bf] = (uint32_t)((wn * 32 + bf * 16 + bnrow) * 128);
    const uint32_t brx = (uint32_t)(bnrow & 7);

    const int NC = K >> 6;
    issue_copy(0);
    if (NC > 1) issue_copy(1);

    for (int c = 0; c < NC; c++) {
        if (c < NC - 1) { CP_WAIT1(); } else { CP_WAIT0(); }
        __syncthreads();

        const uint32_t base = sb + (uint32_t)(c & 1) * BUF_BYTES;
        const uint32_t A_hi_b = base,                  A_lo_b = base + TILE_BYTES;
        const uint32_t B_hi_b = base + 2 * TILE_BYTES, B_lo_b = base + 3 * TILE_BYTES;

#pragma unroll
        for (int ks = 0; ks < 4; ks++) {
            uint32_t ah[4][4], al[4][4], bh[2][4], bl[2][4];
            const uint32_t ac = (uint32_t)(ks * 2 + ahi);
            const uint32_t bc = (uint32_t)(ks * 2 + bhi);
#pragma unroll
            for (int mf = 0; mf < 4; mf++) {
                uint32_t off = a_rowoff[mf] + ((ac ^ arx) << 4);
                LDSM_X4(ah[mf][0], ah[mf][1], ah[mf][2], ah[mf][3], A_hi_b + off);
                LDSM_X4(al[mf][0], al[mf][1], al[mf][2], al[mf][3], A_lo_b + off);
            }
#pragma unroll
            for (int bf = 0; bf < 2; bf++) {
                uint32_t off = b_rowoff[bf] + ((bc ^ brx) << 4);
                LDSM_X4(bh[bf][0], bh[bf][1], bh[bf][2], bh[bf][3], B_hi_b + off);
                LDSM_X4(bl[bf][0], bl[bf][1], bl[bf][2], bl[bf][3], B_lo_b + off);
            }
#pragma unroll
            for (int mf = 0; mf < 4; mf++)
#pragma unroll
                for (int nf = 0; nf < 4; nf++) {
                    uint32_t* bhp = &bh[nf >> 1][(nf & 1) * 2];
                    uint32_t* blp = &bl[nf >> 1][(nf & 1) * 2];
                    MMA16816(acc[mf][nf], ah[mf], bhp);
                    MMA16816(acc[mf][nf], ah[mf], blp);
                    MMA16816(acc[mf][nf], al[mf], bhp);
                }
        }
        __syncthreads();
        if (c + 2 < NC) issue_copy(c + 2);
    }

    const int er = lane >> 2;
    const int ec = (lane & 3) * 2;
#pragma unroll
    for (int mf = 0; mf < 4; mf++) {
        const int r0 = bm + wm * 64 + mf * 16 + er;
#pragma unroll
        for (int nf = 0; nf < 4; nf++) {
            const int cc = bn + wn * 32 + nf * 8 + ec;
            *(float2*)(C + (size_t)r0 * N + cc)       = make_float2(acc[mf][nf][0], acc[mf][nf][1]);
            *(float2*)(C + (size_t)(r0 + 8) * N + cc) = make_float2(acc[mf][nf][2], acc[mf][nf][3]);
        }
    }
}

// ---------------------------------------------------------------------------
// Fused RMSNorm + RoPE, output split to bf16 hi/lo
// ---------------------------------------------------------------------------
__global__ __launch_bounds__(128)
void rmsnorm_rope_split(const float* __restrict__ X, const float* __restrict__ w,
                        const float* __restrict__ cosp, const float* __restrict__ sinp,
                        int H, __nv_bfloat16* __restrict__ hi, __nv_bfloat16* __restrict__ lo) {
    const int s = blockIdx.x, h = blockIdx.y, d = threadIdx.x;
    const float* row = X + ((size_t)s * H + h) * D;
    float x = row[d];
    float sq = x * x;
#pragma unroll
    for (int o = 16; o > 0; o >>= 1) sq += __shfl_xor_sync(0xffffffffu, sq, o);
    __shared__ float red[4];
    __shared__ float xs[D];
    if ((d & 31) == 0) red[d >> 5] = sq;
    __syncthreads();
    float var = (red[0] + red[1] + red[2] + red[3]) * (1.0f / D);
    float xn = x * rsqrtf(var + 1e-6f) * w[d];
    xs[d] = xn;
    __syncthreads();
    float other = (d < 64) ? -xs[d + 64] : xs[d - 64];
    float val = fmaf(xn, cosp[s * D + d], other * sinp[s * D + d]);
    size_t idx = ((size_t)s * H + h) * D + d;
    __nv_bfloat16 hb = __float2bfloat16(val);
    hi[idx] = hb;
    lo[idx] = __float2bfloat16(val - __bfloat162float(hb));
}

// ---------------------------------------------------------------------------
// MMA flash attention: 4 warps, 64 queries/CTA (16 per warp), 32-key tiles.
// hi/lo bf16 3-term products for QK and PV. fp32 softmax in fragments.
// ---------------------------------------------------------------------------
constexpr int AT_SMEM = 98304;   // 2 x 32KB KV buffers + 32KB Q staging
constexpr float SCALE = 0.088388347648318447f;
constexpr float L2E   = 1.4426950408889634f;

__global__ __launch_bounds__(128, 1)
void attn_mma(const __nv_bfloat16* __restrict__ Qh, const __nv_bfloat16* __restrict__ Ql,
              const __nv_bfloat16* __restrict__ Kh, const __nv_bfloat16* __restrict__ Kl,
              const __nv_bfloat16* __restrict__ Vh, const __nv_bfloat16* __restrict__ Vl,
              float* __restrict__ Out) {
    extern __shared__ char smem[];
    const uint32_t sb = smem_u32(smem);
    const int tid = threadIdx.x;
    const int w = tid >> 5, lane = tid & 31;
    const int h = blockIdx.y, kvh = h >> 1;
    const int q0 = blockIdx.x * 64;

    const uint32_t QHI = sb + 65536, QLO = sb + 81920;

    // stage Q hi/lo (64 rows x 16 chunks x 2 tensors)
#pragma unroll
    for (int i = 0; i < 16; i++) {
        int idx = tid + i * 128;
        int ten = idx >> 10;
        int rem = idx & 1023;
        int r = rem >> 4, c = rem & 15;
        const __nv_bfloat16* src = (ten ? Ql : Qh) + ((size_t)(q0 + r) * HQ + h) * D + c * 8;
        CP_ASYNC16((ten ? QLO : QHI) + sw256(r, c), src);
    }
    CP_COMMIT();
    CP_WAIT0();
    __syncthreads();

    // Q fragments (A layout), 8 k-steps
    uint32_t qfh[8][4], qfl[8][4];
    {
        const int arow = lane & 15, ahi = lane >> 4;
#pragma unroll
        for (int ks = 0; ks < 8; ks++) {
            uint32_t off = sw256(w * 16 + arow, 2 * ks + ahi);
            LDSM_X4(qfh[ks][0], qfh[ks][1], qfh[ks][2], qfh[ks][3], QHI + off);
            LDSM_X4(qfl[ks][0], qfl[ks][1], qfl[ks][2], qfl[ks][3], QLO + off);
        }
    }

    float o[16][4];
#pragma unroll
    for (int nf = 0; nf < 16; nf++)
#pragma unroll
        for (int x = 0; x < 4; x++) o[nf][x] = 0.f;
    float m0 = 0.f, m1 = 0.f, l0 = 0.f, l1 = 0.f;

    int jlo = q0 - (WINDOW - 1);
    if (jlo < 0) jlo = 0;
    jlo &= ~31;
    const int NT = (q0 + 64 - jlo) >> 5;

    auto issue_kv = [&](int t) {
        const int j0 = jlo + t * 32;
        const uint32_t base = sb + (uint32_t)(t & 1) * 32768;
        const __nv_bfloat16* srcs[4] = { Kh, Kl, Vh, Vl };
#pragma unroll
        for (int i = 0; i < 16; i++) {
            int idx = tid + i * 128;
            int ten = idx >> 9;
            int rem = idx & 511;
            int r = rem >> 4, c = rem & 15;
            const __nv_bfloat16* src = srcs[ten] + ((size_t)(j0 + r) * HKV + kvh) * D + c * 8;
            CP_ASYNC16(base + ten * 8192 + sw256(r, c), src);
        }
        CP_COMMIT();
    };

    issue_kv(0);
    if (NT > 1) issue_kv(1);

    const int bnrow = (lane & 7) + ((lane >> 4) & 1) * 8;
    const int bhi = (lane >> 3) & 1;
    const int er = lane >> 2, ec = (lane & 3) * 2;
    const int r0g = q0 + w * 16 + er, r1g = r0g + 8;
    const int vg = lane >> 3, vr = lane & 7;

    for (int t = 0; t < NT; t++) {
        if (t < NT - 1) { CP_WAIT1(); } else { CP_WAIT0(); }
        __syncthreads();
        const int j0 = jlo + t * 32;
        const uint32_t base = sb + (uint32_t)(t & 1) * 32768;
        const uint32_t KHB = base, KLB = base + 8192, VHB = base + 16384, VLB = base + 24576;

        // ---- S = Q @ K^T (3-term) ----
        float s[4][4];
#pragma unroll
        for (int nf = 0; nf < 4; nf++)
#pragma unroll
            for (int x = 0; x < 4; x++) s[nf][x] = 0.f;
#pragma unroll
        for (int ks = 0; ks < 8; ks++) {
            uint32_t kfh[2][4], kfl[2][4];
            const int ch = 2 * ks + bhi;
            uint32_t off0 = sw256(bnrow, ch), off1 = sw256(16 + bnrow, ch);
            LDSM_X4(kfh[0][0], kfh[0][1], kfh[0][2], kfh[0][3], KHB + off0);
            LDSM_X4(kfh[1][0], kfh[1][1], kfh[1][2], kfh[1][3], KHB + off1);
            LDSM_X4(kfl[0][0], kfl[0][1], kfl[0][2], kfl[0][3], KLB + off0);
            LDSM_X4(kfl[1][0], kfl[1][1], kfl[1][2], kfl[1][3], KLB + off1);
#pragma unroll
            for (int nf = 0; nf < 4; nf++) {
                uint32_t* bhp = &kfh[nf >> 1][(nf & 1) * 2];
                uint32_t* blp = &kfl[nf >> 1][(nf & 1) * 2];
                MMA16816(s[nf], qfh[ks], bhp);
                MMA16816(s[nf], qfh[ks], blp);
                MMA16816(s[nf], qfl[ks], bhp);
            }
        }

        // ---- mask + scale + row max ----
        float mn0 = m0, mn1 = m1;
#pragma unroll
        for (int nf = 0; nf < 4; nf++) {
#pragma unroll
            for (int cx = 0; cx < 2; cx++) {
                const int jj = j0 + nf * 8 + ec + cx;
                s[nf][cx]     = (jj <= r0g && jj > r0g - WINDOW) ? s[nf][cx] * SCALE     : -1e9f;
                s[nf][2 + cx] = (jj <= r1g && jj > r1g - WINDOW) ? s[nf][2 + cx] * SCALE : -1e9f;
            }
            mn0 = fmaxf(mn0, fmaxf(s[nf][0], s[nf][1]));
            mn1 = fmaxf(mn1, fmaxf(s[nf][2], s[nf][3]));
        }
        mn0 = fmaxf(mn0, __shfl_xor_sync(0xffffffffu, mn0, 1));
        mn0 = fmaxf(mn0, __shfl_xor_sync(0xffffffffu, mn0, 2));
        mn1 = fmaxf(mn1, __shfl_xor_sync(0xffffffffu, mn1, 1));
        mn1 = fmaxf(mn1, __shfl_xor_sync(0xffffffffu, mn1, 2));
        const float a0 = exp2f((m0 - mn0) * L2E);
        const float a1 = exp2f((m1 - mn1) * L2E);
        m0 = mn0; m1 = mn1;

        // ---- P = exp(S - m), pack hi/lo A-fragments ----
        float rs0 = 0.f, rs1 = 0.f;
        uint32_t ph[2][4], pl[2][4];
#pragma unroll
        for (int kk = 0; kk < 2; kk++) {
            float p[2][4];
#pragma unroll
            for (int q2 = 0; q2 < 2; q2++) {
                const int nf = 2 * kk + q2;
                p[q2][0] = exp2f((s[nf][0] - m0) * L2E);
                p[q2][1] = exp2f((s[nf][1] - m0) * L2E);
                p[q2][2] = exp2f((s[nf][2] - m1) * L2E);
                p[q2][3] = exp2f((s[nf][3] - m1) * L2E);
                rs0 += p[q2][0] + p[q2][1];
                rs1 += p[q2][2] + p[q2][3];
            }
            // A-frag: a0=(er,k0..7 pair), a1=(er+8,k0..7), a2=(er,k8..15), a3=(er+8,k8..15)
            ph[kk][0] = pack_bf16(p[0][0], p[0][1]);
            ph[kk][1] = pack_bf16(p[0][2], p[0][3]);
            ph[kk][2] = pack_bf16(p[1][0], p[1][1]);
            ph[kk][3] = pack_bf16(p[1][2], p[1][3]);
            float r00 = p[0][0] - __bfloat162float(__float2bfloat16(p[0][0]));
            float r01 = p[0][1] - __bfloat162float(__float2bfloat16(p[0][1]));
            float r02 = p[0][2] - __bfloat162float(__float2bfloat16(p[0][2]));
            float r03 = p[0][3] - __bfloat162float(__float2bfloat16(p[0][3]));
            float r10 = p[1][0] - __bfloat162float(__float2bfloat16(p[1][0]));
            float r11 = p[1][1] - __bfloat162float(__float2bfloat16(p[1][1]));
            float r12 = p[1][2] - __bfloat162float(__float2bfloat16(p[1][2]));
            float r13 = p[1][3] - __bfloat162float(__float2bfloat16(p[1][3]));
            pl[kk][0] = pack_bf16(r00, r01);
            pl[kk][1] = pack_bf16(r02, r03);
            pl[kk][2] = pack_bf16(r10, r11);
            pl[kk][3] = pack_bf16(r12, r13);
        }
        rs0 += __shfl_xor_sync(0xffffffffu, rs0, 1);
        rs0 += __shfl_xor_sync(0xffffffffu, rs0, 2);
        rs1 += __shfl_xor_sync(0xffffffffu, rs1, 1);
        rs1 += __shfl_xor_sync(0xffffffffu, rs1, 2);
        l0 = l0 * a0 + rs0;
        l1 = l1 * a1 + rs1;

        // ---- rescale O ----
#pragma unroll
        for (int nf = 0; nf < 16; nf++) {
            o[nf][0] *= a0; o[nf][1] *= a0;
            o[nf][2] *= a1; o[nf][3] *= a1;
        }

        // ---- O += P @ V (3-term), V via ldmatrix.trans ----
#pragma unroll
        for (int kk = 0; kk < 2; kk++) {
            const int vrow = kk * 16 + (vg & 1) * 8 + vr;
#pragma unroll
            for (int nc = 0; nc < 8; nc++) {
                uint32_t vfh[4], vfl[4];
                uint32_t off = sw256(vrow, nc * 2 + (vg >> 1));
                LDSM_X4_T(vfh[0], vfh[1], vfh[2], vfh[3], VHB + off);
                LDSM_X4_T(vfl[0], vfl[1], vfl[2], vfl[3], VLB + off);
                MMA16816(o[nc * 2],     ph[kk], &vfh[0]);
                MMA16816(o[nc * 2],     pl[kk], &vfh[0]);
                MMA16816(o[nc * 2],     ph[kk], &vfl[0]);
                MMA16816(o[nc * 2 + 1], ph[kk], &vfh[2]);
                MMA16816(o[nc * 2 + 1], pl[kk], &vfh[2]);
                MMA16816(o[nc * 2 + 1], ph[kk], &vfl[2]);
            }
        }
        __syncthreads();
        if (t + 2 < NT) issue_kv(t + 2);
    }

    // epilogue
    const float i0 = 1.f / l0, i1 = 1.f / l1;
#pragma unroll
    for (int nf = 0; nf < 16; nf++) {
        const int cc = nf * 8 + ec;
        *(float2*)(Out + ((size_t)r0g * HQ + h) * D + cc) = make_float2(o[nf][0] * i0, o[nf][1] * i0);
        *(float2*)(Out + ((size_t)r1g * HQ + h) * D + cc) = make_float2(o[nf][2] * i1, o[nf][3] * i1);
    }
}

// ---------------------------------------------------------------------------
extern "C" void kernel_launch(void* const* d_in, const int* in_sizes, int n_in,
                              void* d_out, int out_size) {
    const float* hidden = (const float*)d_in[0];
    const float* cosp   = (const float*)d_in[1];
    const float* sinp   = (const float*)d_in[2];
    const float* Wq     = (const float*)d_in[3];
    const float* Wk     = (const float*)d_in[4];
    const float* Wv     = (const float*)d_in[5];
    const float* Wo     = (const float*)d_in[6];
    const float* qw     = (const float*)d_in[7];
    const float* kw     = (const float*)d_in[8];
    float* out = (float*)d_out;

    float *q, *k, *v, *att;
    cudaGetSymbolAddress((void**)&q,   g_q);
    cudaGetSymbolAddress((void**)&k,   g_k);
    cudaGetSymbolAddress((void**)&v,   g_v);
    cudaGetSymbolAddress((void**)&att, g_att);
    __nv_bfloat16 *hh, *hl, *qh, *ql, *kh, *kl, *vh, *vl, *oh, *ol, *ah, *al;
    __nv_bfloat16 *qbh, *qbl, *kbh, *kbl, *vbh, *vbl;
    cudaGetSymbolAddress((void**)&hh, g_h_hi);  cudaGetSymbolAddress((void**)&hl, g_h_lo);
    cudaGetSymbolAddress((void**)&qh, g_wq_hi); cudaGetSymbolAddress((void**)&ql, g_wq_lo);
    cudaGetSymbolAddress((void**)&kh, g_wk_hi); cudaGetSymbolAddress((void**)&kl, g_wk_lo);
    cudaGetSymbolAddress((void**)&vh, g_wv_hi); cudaGetSymbolAddress((void**)&vl, g_wv_lo);
    cudaGetSymbolAddress((void**)&oh, g_wo_hi); cudaGetSymbolAddress((void**)&ol, g_wo_lo);
    cudaGetSymbolAddress((void**)&ah, g_a_hi);  cudaGetSymbolAddress((void**)&al, g_a_lo);
    cudaGetSymbolAddress((void**)&qbh, g_qbh);  cudaGetSymbolAddress((void**)&qbl, g_qbl);
    cudaGetSymbolAddress((void**)&kbh, g_kbh);  cudaGetSymbolAddress((void**)&kbl, g_kbl);
    cudaGetSymbolAddress((void**)&vbh, g_vbh);  cudaGetSymbolAddress((void**)&vbl, g_vbl);

    cudaFuncSetAttribute(gemm_mma, cudaFuncAttributeMaxDynamicSharedMemorySize, GEMM_SMEM);
    cudaFuncSetAttribute(attn_mma, cudaFuncAttributeMaxDynamicSharedMemorySize, AT_SMEM);

    const int nH = S * HID, nWq = HQ * D * HID, nWk = HKV * D * HID, nWo = HID * HQ * D;
    // launches 1-4
    split_hilo<<<nH  / 1024, 256>>>(hidden, hh, hl, nH);
    split_hilo<<<nWq / 1024, 256>>>(Wq, qh, ql, nWq);
    split_hilo<<<nWk / 1024, 256>>>(Wk, kh, kl, nWk);
    split_hilo<<<nWk / 1024, 256>>>(Wv, vh, vl, nWk);
    // launch 5 (profiled)
    gemm_mma<<<dim3((HQ * D) / 128, S / 128), 256, GEMM_SMEM>>>(hh, hl, qh, ql, q, HQ * D, HID);
    gemm_mma<<<dim3((HKV * D) / 128, S / 128), 256, GEMM_SMEM>>>(hh, hl, kh, kl, k, HKV * D, HID);
    gemm_mma<<<dim3((HKV * D) / 128, S / 128), 256, GEMM_SMEM>>>(hh, hl, vh, vl, v, HKV * D, HID);
    split_hilo<<<nWo / 1024, 256>>>(Wo, oh, ol, nWo);

    rmsnorm_rope_split<<<dim3(S, HQ), D>>>(q, qw, cosp, sinp, HQ, qbh, qbl);
    rmsnorm_rope_split<<<dim3(S, HKV), D>>>(k, kw, cosp, sinp, HKV, kbh, kbl);
    split_hilo<<<(S * HKV * D) / 1024, 256>>>(v, vbh, vbl, S * HKV * D);

    attn_mma<<<dim3(S / 64, HQ), 128, AT_SMEM>>>(qbh, qbl, kbh, kbl, vbh, vbl, att);

    const int nA = S * HQ * D;
    split_hilo<<<nA / 1024, 256>>>(att, ah, al, nA);
    gemm_mma<<<dim3(HID / 128, S / 128), 256, GEMM_SMEM>>>(ah, al, oh, ol, out, HID, HQ * D);
}

// round 7
// speedup vs baseline: 4.1511x; 1.3227x over previous
#include <cuda_runtime.h>
#include <cuda_bf16.h>
#include <cuda_fp16.h>
#include <math.h>
#include <cstdint>

constexpr int S = 4096, HID = 2048, HQ = 16, HKV = 8, D = 128, WINDOW = 1024;

// fp32 intermediates
__device__ float g_q[(size_t)S * HQ * D];
__device__ float g_k[(size_t)S * HKV * D];
__device__ float g_v[(size_t)S * HKV * D];
// fp16 GEMM operands
__device__ __half g_hh[(size_t)S * HID];                              // hidden hi (A-side)
__device__ __half g_wq_h[(size_t)HQ * D * HID], g_wq_l[(size_t)HQ * D * HID];
__device__ __half g_wk_h[(size_t)HKV * D * HID], g_wk_l[(size_t)HKV * D * HID];
__device__ __half g_wv_h[(size_t)HKV * D * HID], g_wv_l[(size_t)HKV * D * HID];
__device__ __half g_wo_h[(size_t)HID * HQ * D],  g_wo_l[(size_t)HID * HQ * D];
__device__ __half g_ah[(size_t)S * HQ * D];                           // attn out hi (A-side)
// bf16 hi/lo attention operands
__device__ __nv_bfloat16 g_qbh[(size_t)S * HQ * D],  g_qbl[(size_t)S * HQ * D];
__device__ __nv_bfloat16 g_kbh[(size_t)S * HKV * D], g_kbl[(size_t)S * HKV * D];
__device__ __nv_bfloat16 g_vbh[(size_t)S * HKV * D], g_vbl[(size_t)S * HKV * D];

// ---------------------------------------------------------------------------
__device__ __forceinline__ uint32_t smem_u32(const void* p) {
    uint32_t a;
    asm("{ .reg .u64 t; cvta.to.shared.u64 t, %1; cvt.u32.u64 %0, t; }" : "=r"(a) : "l"(p));
    return a;
}
__device__ __forceinline__ uint32_t swz(uint32_t o) { return o ^ ((o >> 3) & 0x70); }
__device__ __forceinline__ uint32_t sw256(int r, int c) {
    return (uint32_t)(r * 256 + (((c ^ r) & 7) << 4) + ((c & 8) << 4));
}

#define CP_ASYNC16(dst, src) \
    asm volatile("cp.async.cg.shared.global [%0], [%1], 16;" :: "r"(dst), "l"(src))
#define CP_COMMIT() asm volatile("cp.async.commit_group;" ::: "memory")
#define CP_WAIT1()  asm volatile("cp.async.wait_group 1;" ::: "memory")
#define CP_WAIT0()  asm volatile("cp.async.wait_group 0;" ::: "memory")

#define LDSM_X4(r0, r1, r2, r3, addr) \
    asm volatile("ldmatrix.sync.aligned.m8n8.x4.shared.b16 {%0,%1,%2,%3}, [%4];" \
                 : "=r"(r0), "=r"(r1), "=r"(r2), "=r"(r3) : "r"(addr))
#define LDSM_X4_T(r0, r1, r2, r3, addr) \
    asm volatile("ldmatrix.sync.aligned.m8n8.x4.trans.shared.b16 {%0,%1,%2,%3}, [%4];" \
                 : "=r"(r0), "=r"(r1), "=r"(r2), "=r"(r3) : "r"(addr))

#define MMA_BF16(d, a, b) \
    asm volatile("mma.sync.aligned.m16n8k16.row.col.f32.bf16.bf16.f32 " \
                 "{%0,%1,%2,%3},{%4,%5,%6,%7},{%8,%9},{%0,%1,%2,%3};" \
                 : "+f"((d)[0]), "+f"((d)[1]), "+f"((d)[2]), "+f"((d)[3]) \
                 : "r"((a)[0]), "r"((a)[1]), "r"((a)[2]), "r"((a)[3]), \
                   "r"((b)[0]), "r"((b)[1]))
#define MMA_F16(d, a, b) \
    asm volatile("mma.sync.aligned.m16n8k16.row.col.f32.f16.f16.f32 " \
                 "{%0,%1,%2,%3},{%4,%5,%6,%7},{%8,%9},{%0,%1,%2,%3};" \
                 : "+f"((d)[0]), "+f"((d)[1]), "+f"((d)[2]), "+f"((d)[3]) \
                 : "r"((a)[0]), "r"((a)[1]), "r"((a)[2]), "r"((a)[3]), \
                   "r"((b)[0]), "r"((b)[1]))

__device__ __forceinline__ uint32_t pack_bf16(float a, float b) {
    __nv_bfloat162 t;
    t.x = __float2bfloat16(a); t.y = __float2bfloat16(b);
    return *(uint32_t*)&t;
}

// ---------------------------------------------------------------------------
// fp32 -> fp16 hi/lo split (weights, B-side)
// ---------------------------------------------------------------------------
__global__ __launch_bounds__(256)
void split_hilo_h(const float* __restrict__ x, __half* __restrict__ hi,
                  __half* __restrict__ lo, int n) {
    int i = (blockIdx.x * 256 + threadIdx.x) * 4;
    if (i >= n) return;
    float4 v = *(const float4*)(x + i);
    __half2 h01 = __floats2half2_rn(v.x, v.y);
    __half2 h23 = __floats2half2_rn(v.z, v.w);
    __half2 l01 = __floats2half2_rn(v.x - __half2float(h01.x), v.y - __half2float(h01.y));
    __half2 l23 = __floats2half2_rn(v.z - __half2float(h23.x), v.w - __half2float(h23.y));
    *(__half2*)(hi + i)     = h01;
    *(__half2*)(hi + i + 2) = h23;
    *(__half2*)(lo + i)     = l01;
    *(__half2*)(lo + i + 2) = l23;
}
// fp32 -> fp16 (A-side, hi only)
__global__ __launch_bounds__(256)
void conv_h(const float* __restrict__ x, __half* __restrict__ hi, int n) {
    int i = (blockIdx.x * 256 + threadIdx.x) * 4;
    if (i >= n) return;
    float4 v = *(const float4*)(x + i);
    *(__half2*)(hi + i)     = __floats2half2_rn(v.x, v.y);
    *(__half2*)(hi + i + 2) = __floats2half2_rn(v.z, v.w);
}
// fp32 -> bf16 hi/lo (V for attention)
__global__ __launch_bounds__(256)
void split_hilo_bf(const float* __restrict__ x, __nv_bfloat16* __restrict__ hi,
                   __nv_bfloat16* __restrict__ lo, int n) {
    int i = (blockIdx.x * 256 + threadIdx.x) * 4;
    if (i >= n) return;
    float4 v = *(const float4*)(x + i);
    __nv_bfloat162 h01, h23, l01, l23;
    h01.x = __float2bfloat16(v.x); h01.y = __float2bfloat16(v.y);
    h23.x = __float2bfloat16(v.z); h23.y = __float2bfloat16(v.w);
    l01.x = __float2bfloat16(v.x - __bfloat162float(h01.x));
    l01.y = __float2bfloat16(v.y - __bfloat162float(h01.y));
    l23.x = __float2bfloat16(v.z - __bfloat162float(h23.x));
    l23.y = __float2bfloat16(v.w - __bfloat162float(h23.y));
    *(__nv_bfloat162*)(hi + i)     = h01;
    *(__nv_bfloat162*)(hi + i + 2) = h23;
    *(__nv_bfloat162*)(lo + i)     = l01;
    *(__nv_bfloat162*)(lo + i + 2) = l23;
}

// ---------------------------------------------------------------------------
// fp16 2-term GEMM: C[M,N] = Ah[M,K] @ (Bh+Bl)[N,K]^T, fp32 accum.
// 128x128 CTA tile, BK=64, 8 warps, 2 MMAs per microtile step. 96KB smem.
// ---------------------------------------------------------------------------
constexpr int TILE_BYTES = 128 * 64 * 2;
constexpr int BUF_BYTES  = 3 * TILE_BYTES;   // Ah, Bh, Bl
constexpr int GEMM_SMEM  = 2 * BUF_BYTES;    // 96KB

__global__ __launch_bounds__(256, 2)
void gemm_f16(const __half* __restrict__ Ah, const __half* __restrict__ Bh,
              const __half* __restrict__ Bl, float* __restrict__ C, int N, int K) {
    extern __shared__ char smem[];
    const uint32_t sb = smem_u32(smem);
    const int tid = threadIdx.x;
    const int wid = tid >> 5;
    const int lane = tid & 31;
    const int wm = wid >> 2;
    const int wn = wid & 3;
    const int bm = blockIdx.y * 128;
    const int bn = blockIdx.x * 128;

    const __half* srcs[3] = { Ah, Bh, Bl };
    const int row0s[3] = { bm, bn, bn };

    auto issue_copy = [&](int c) {
        const uint32_t base = sb + (uint32_t)(c & 1) * BUF_BYTES;
        const int k0 = c << 6;
#pragma unroll
        for (int t = 0; t < 3; t++) {
            const __half* src = srcs[t];
            const int row0 = row0s[t];
            const uint32_t tbase = base + t * TILE_BYTES;
#pragma unroll
            for (int i = 0; i < 4; i++) {
                int idx = tid + i * 256;
                int r  = idx >> 3;
                int cc = idx & 7;
                uint32_t dst = tbase + swz((uint32_t)(r * 128 + cc * 16));
                const void* s = src + (size_t)(row0 + r) * K + k0 + cc * 8;
                CP_ASYNC16(dst, s);
            }
        }
        CP_COMMIT();
    };

    float acc[4][4][4];
#pragma unroll
    for (int a = 0; a < 4; a++)
#pragma unroll
        for (int b = 0; b < 4; b++)
#pragma unroll
            for (int x = 0; x < 4; x++) acc[a][b][x] = 0.f;

    const int arow = (lane & 15);
    const int ahi  = lane >> 4;
    uint32_t a_rowoff[4];
#pragma unroll
    for (int mf = 0; mf < 4; mf++)
        a_rowoff[mf] = (uint32_t)((wm * 64 + mf * 16 + arow) * 128);
    const uint32_t arx = (uint32_t)(arow & 7);

    const int bnrow = (lane & 7) + ((lane >> 4) & 1) * 8;
    const int bhi   = (lane >> 3) & 1;
    uint32_t b_rowoff[2];
#pragma unroll
    for (int bf = 0; bf < 2; bf++)
        b_rowoff[bf] = (uint32_t)((wn * 32 + bf * 16 + bnrow) * 128);
    const uint32_t brx = (uint32_t)(bnrow & 7);

    const int NC = K >> 6;
    issue_copy(0);
    if (NC > 1) issue_copy(1);

    for (int c = 0; c < NC; c++) {
        if (c < NC - 1) { CP_WAIT1(); } else { CP_WAIT0(); }
        __syncthreads();

        const uint32_t base = sb + (uint32_t)(c & 1) * BUF_BYTES;
        const uint32_t A_b = base;
        const uint32_t B_hi_b = base + TILE_BYTES, B_lo_b = base + 2 * TILE_BYTES;

#pragma unroll
        for (int ks = 0; ks < 4; ks++) {
            uint32_t ah[4][4], bh[2][4], bl[2][4];
            const uint32_t ac = (uint32_t)(ks * 2 + ahi);
            const uint32_t bc = (uint32_t)(ks * 2 + bhi);
#pragma unroll
            for (int mf = 0; mf < 4; mf++) {
                uint32_t off = a_rowoff[mf] + ((ac ^ arx) << 4);
                LDSM_X4(ah[mf][0], ah[mf][1], ah[mf][2], ah[mf][3], A_b + off);
            }
#pragma unroll
            for (int bf = 0; bf < 2; bf++) {
                uint32_t off = b_rowoff[bf] + ((bc ^ brx) << 4);
                LDSM_X4(bh[bf][0], bh[bf][1], bh[bf][2], bh[bf][3], B_hi_b + off);
                LDSM_X4(bl[bf][0], bl[bf][1], bl[bf][2], bl[bf][3], B_lo_b + off);
            }
#pragma unroll
            for (int mf = 0; mf < 4; mf++)
#pragma unroll
                for (int nf = 0; nf < 4; nf++) {
                    uint32_t* bhp = &bh[nf >> 1][(nf & 1) * 2];
                    uint32_t* blp = &bl[nf >> 1][(nf & 1) * 2];
                    MMA_F16(acc[mf][nf], ah[mf], bhp);
                    MMA_F16(acc[mf][nf], ah[mf], blp);
                }
        }
        __syncthreads();
        if (c + 2 < NC) issue_copy(c + 2);
    }

    const int er = lane >> 2;
    const int ec = (lane & 3) * 2;
#pragma unroll
    for (int mf = 0; mf < 4; mf++) {
        const int r0 = bm + wm * 64 + mf * 16 + er;
#pragma unroll
        for (int nf = 0; nf < 4; nf++) {
            const int cc = bn + wn * 32 + nf * 8 + ec;
            *(float2*)(C + (size_t)r0 * N + cc)       = make_float2(acc[mf][nf][0], acc[mf][nf][1]);
            *(float2*)(C + (size_t)(r0 + 8) * N + cc) = make_float2(acc[mf][nf][2], acc[mf][nf][3]);
        }
    }
}

// ---------------------------------------------------------------------------
// Fused RMSNorm + RoPE, output split to bf16 hi/lo (for attention)
// ---------------------------------------------------------------------------
__global__ __launch_bounds__(128)
void rmsnorm_rope_split(const float* __restrict__ X, const float* __restrict__ w,
                        const float* __restrict__ cosp, const float* __restrict__ sinp,
                        int H, __nv_bfloat16* __restrict__ hi, __nv_bfloat16* __restrict__ lo) {
    const int s = blockIdx.x, h = blockIdx.y, d = threadIdx.x;
    const float* row = X + ((size_t)s * H + h) * D;
    float x = row[d];
    float sq = x * x;
#pragma unroll
    for (int o = 16; o > 0; o >>= 1) sq += __shfl_xor_sync(0xffffffffu, sq, o);
    __shared__ float red[4];
    __shared__ float xs[D];
    if ((d & 31) == 0) red[d >> 5] = sq;
    __syncthreads();
    float var = (red[0] + red[1] + red[2] + red[3]) * (1.0f / D);
    float xn = x * rsqrtf(var + 1e-6f) * w[d];
    xs[d] = xn;
    __syncthreads();
    float other = (d < 64) ? -xs[d + 64] : xs[d - 64];
    float val = fmaf(xn, cosp[s * D + d], other * sinp[s * D + d]);
    size_t idx = ((size_t)s * H + h) * D + d;
    __nv_bfloat16 hb = __float2bfloat16(val);
    hi[idx] = hb;
    lo[idx] = __float2bfloat16(val - __bfloat162float(hb));
}

// ---------------------------------------------------------------------------
// MMA flash attention (bf16 3-term), epilogue emits fp16 (A-side of Wo GEMM).
// ---------------------------------------------------------------------------
constexpr int AT_SMEM = 98304;
constexpr float SCALE = 0.088388347648318447f;
constexpr float L2E   = 1.4426950408889634f;

__global__ __launch_bounds__(128, 1)
void attn_mma(const __nv_bfloat16* __restrict__ Qh, const __nv_bfloat16* __restrict__ Ql,
              const __nv_bfloat16* __restrict__ Kh, const __nv_bfloat16* __restrict__ Kl,
              const __nv_bfloat16* __restrict__ Vh, const __nv_bfloat16* __restrict__ Vl,
              __half* __restrict__ Out) {
    extern __shared__ char smem[];
    const uint32_t sb = smem_u32(smem);
    const int tid = threadIdx.x;
    const int w = tid >> 5, lane = tid & 31;
    const int h = blockIdx.y, kvh = h >> 1;
    const int q0 = blockIdx.x * 64;

    const uint32_t QHI = sb + 65536, QLO = sb + 81920;

#pragma unroll
    for (int i = 0; i < 16; i++) {
        int idx = tid + i * 128;
        int ten = idx >> 10;
        int rem = idx & 1023;
        int r = rem >> 4, c = rem & 15;
        const __nv_bfloat16* src = (ten ? Ql : Qh) + ((size_t)(q0 + r) * HQ + h) * D + c * 8;
        CP_ASYNC16((ten ? QLO : QHI) + sw256(r, c), src);
    }
    CP_COMMIT();
    CP_WAIT0();
    __syncthreads();

    uint32_t qfh[8][4], qfl[8][4];
    {
        const int arow = lane & 15, ahi = lane >> 4;
#pragma unroll
        for (int ks = 0; ks < 8; ks++) {
            uint32_t off = sw256(w * 16 + arow, 2 * ks + ahi);
            LDSM_X4(qfh[ks][0], qfh[ks][1], qfh[ks][2], qfh[ks][3], QHI + off);
            LDSM_X4(qfl[ks][0], qfl[ks][1], qfl[ks][2], qfl[ks][3], QLO + off);
        }
    }

    float o[16][4];
#pragma unroll
    for (int nf = 0; nf < 16; nf++)
#pragma unroll
        for (int x = 0; x < 4; x++) o[nf][x] = 0.f;
    float m0 = 0.f, m1 = 0.f, l0 = 0.f, l1 = 0.f;

    int jlo = q0 - (WINDOW - 1);
    if (jlo < 0) jlo = 0;
    jlo &= ~31;
    const int NT = (q0 + 64 - jlo) >> 5;

    auto issue_kv = [&](int t) {
        const int j0 = jlo + t * 32;
        const uint32_t base = sb + (uint32_t)(t & 1) * 32768;
        const __nv_bfloat16* srcs[4] = { Kh, Kl, Vh, Vl };
#pragma unroll
        for (int i = 0; i < 16; i++) {
            int idx = tid + i * 128;
            int ten = idx >> 9;
            int rem = idx & 511;
            int r = rem >> 4, c = rem & 15;
            const __nv_bfloat16* src = srcs[ten] + ((size_t)(j0 + r) * HKV + kvh) * D + c * 8;
            CP_ASYNC16(base + ten * 8192 + sw256(r, c), src);
        }
        CP_COMMIT();
    };

    issue_kv(0);
    if (NT > 1) issue_kv(1);

    const int bnrow = (lane & 7) + ((lane >> 4) & 1) * 8;
    const int bhi = (lane >> 3) & 1;
    const int er = lane >> 2, ec = (lane & 3) * 2;
    const int r0g = q0 + w * 16 + er, r1g = r0g + 8;
    const int vg = lane >> 3, vr = lane & 7;

    for (int t = 0; t < NT; t++) {
        if (t < NT - 1) { CP_WAIT1(); } else { CP_WAIT0(); }
        __syncthreads();
        const int j0 = jlo + t * 32;
        const uint32_t base = sb + (uint32_t)(t & 1) * 32768;
        const uint32_t KHB = base, KLB = base + 8192, VHB = base + 16384, VLB = base + 24576;

        float s[4][4];
#pragma unroll
        for (int nf = 0; nf < 4; nf++)
#pragma unroll
            for (int x = 0; x < 4; x++) s[nf][x] = 0.f;
#pragma unroll
        for (int ks = 0; ks < 8; ks++) {
            uint32_t kfh[2][4], kfl[2][4];
            const int ch = 2 * ks + bhi;
            uint32_t off0 = sw256(bnrow, ch), off1 = sw256(16 + bnrow, ch);
            LDSM_X4(kfh[0][0], kfh[0][1], kfh[0][2], kfh[0][3], KHB + off0);
            LDSM_X4(kfh[1][0], kfh[1][1], kfh[1][2], kfh[1][3], KHB + off1);
            LDSM_X4(kfl[0][0], kfl[0][1], kfl[0][2], kfl[0][3], KLB + off0);
            LDSM_X4(kfl[1][0], kfl[1][1], kfl[1][2], kfl[1][3], KLB + off1);
#pragma unroll
            for (int nf = 0; nf < 4; nf++) {
                uint32_t* bhp = &kfh[nf >> 1][(nf & 1) * 2];
                uint32_t* blp = &kfl[nf >> 1][(nf & 1) * 2];
                MMA_BF16(s[nf], qfh[ks], bhp);
                MMA_BF16(s[nf], qfh[ks], blp);
                MMA_BF16(s[nf], qfl[ks], bhp);
            }
        }

        float mn0 = m0, mn1 = m1;
#pragma unroll
        for (int nf = 0; nf < 4; nf++) {
#pragma unroll
            for (int cx = 0; cx < 2; cx++) {
                const int jj = j0 + nf * 8 + ec + cx;
                s[nf][cx]     = (jj <= r0g && jj > r0g - WINDOW) ? s[nf][cx] * SCALE     : -1e9f;
                s[nf][2 + cx] = (jj <= r1g && jj > r1g - WINDOW) ? s[nf][2 + cx] * SCALE : -1e9f;
            }
            mn0 = fmaxf(mn0, fmaxf(s[nf][0], s[nf][1]));
            mn1 = fmaxf(mn1, fmaxf(s[nf][2], s[nf][3]));
        }
        mn0 = fmaxf(mn0, __shfl_xor_sync(0xffffffffu, mn0, 1));
        mn0 = fmaxf(mn0, __shfl_xor_sync(0xffffffffu, mn0, 2));
        mn1 = fmaxf(mn1, __shfl_xor_sync(0xffffffffu, mn1, 1));
        mn1 = fmaxf(mn1, __shfl_xor_sync(0xffffffffu, mn1, 2));
        const float a0 = exp2f((m0 - mn0) * L2E);
        const float a1 = exp2f((m1 - mn1) * L2E);
        m0 = mn0; m1 = mn1;

        float rs0 = 0.f, rs1 = 0.f;
        uint32_t ph[2][4], pl[2][4];
#pragma unroll
        for (int kk = 0; kk < 2; kk++) {
            float p[2][4];
#pragma unroll
            for (int q2 = 0; q2 < 2; q2++) {
                const int nf = 2 * kk + q2;
                p[q2][0] = exp2f((s[nf][0] - m0) * L2E);
                p[q2][1] = exp2f((s[nf][1] - m0) * L2E);
                p[q2][2] = exp2f((s[nf][2] - m1) * L2E);
                p[q2][3] = exp2f((s[nf][3] - m1) * L2E);
                rs0 += p[q2][0] + p[q2][1];
                rs1 += p[q2][2] + p[q2][3];
            }
            ph[kk][0] = pack_bf16(p[0][0], p[0][1]);
            ph[kk][1] = pack_bf16(p[0][2], p[0][3]);
            ph[kk][2] = pack_bf16(p[1][0], p[1][1]);
            ph[kk][3] = pack_bf16(p[1][2], p[1][3]);
            float r00 = p[0][0] - __bfloat162float(__float2bfloat16(p[0][0]));
            float r01 = p[0][1] - __bfloat162float(__float2bfloat16(p[0][1]));
            float r02 = p[0][2] - __bfloat162float(__float2bfloat16(p[0][2]));
            float r03 = p[0][3] - __bfloat162float(__float2bfloat16(p[0][3]));
            float r10 = p[1][0] - __bfloat162float(__float2bfloat16(p[1][0]));
            float r11 = p[1][1] - __bfloat162float(__float2bfloat16(p[1][1]));
            float r12 = p[1][2] - __bfloat162float(__float2bfloat16(p[1][2]));
            float r13 = p[1][3] - __bfloat162float(__float2bfloat16(p[1][3]));
            pl[kk][0] = pack_bf16(r00, r01);
            pl[kk][1] = pack_bf16(r02, r03);
            pl[kk][2] = pack_bf16(r10, r11);
            pl[kk][3] = pack_bf16(r12, r13);
        }
        rs0 += __shfl_xor_sync(0xffffffffu, rs0, 1);
        rs0 += __shfl_xor_sync(0xffffffffu, rs0, 2);
        rs1 += __shfl_xor_sync(0xffffffffu, rs1, 1);
        rs1 += __shfl_xor_sync(0xffffffffu, rs1, 2);
        l0 = l0 * a0 + rs0;
        l1 = l1 * a1 + rs1;

#pragma unroll
        for (int nf = 0; nf < 16; nf++) {
            o[nf][0] *= a0; o[nf][1] *= a0;
            o[nf][2] *= a1; o[nf][3] *= a1;
        }

#pragma unroll
        for (int kk = 0; kk < 2; kk++) {
            const int vrow = kk * 16 + (vg & 1) * 8 + vr;
#pragma unroll
            for (int nc = 0; nc < 8; nc++) {
                uint32_t vfh[4], vfl[4];
                uint32_t off = sw256(vrow, nc * 2 + (vg >> 1));
                LDSM_X4_T(vfh[0], vfh[1], vfh[2], vfh[3], VHB + off);
                LDSM_X4_T(vfl[0], vfl[1], vfl[2], vfl[3], VLB + off);
                MMA_BF16(o[nc * 2],     ph[kk], &vfh[0]);
                MMA_BF16(o[nc * 2],     pl[kk], &vfh[0]);
                MMA_BF16(o[nc * 2],     ph[kk], &vfl[0]);
                MMA_BF16(o[nc * 2 + 1], ph[kk], &vfh[2]);
                MMA_BF16(o[nc * 2 + 1], pl[kk], &vfh[2]);
                MMA_BF16(o[nc * 2 + 1], ph[kk], &vfl[2]);
            }
        }
        __syncthreads();
        if (t + 2 < NT) issue_kv(t + 2);
    }

    // epilogue: write fp16 directly (A-side of Wo GEMM)
    const float i0 = 1.f / l0, i1 = 1.f / l1;
#pragma unroll
    for (int nf = 0; nf < 16; nf++) {
        const int cc = nf * 8 + ec;
        *(__half2*)(Out + ((size_t)r0g * HQ + h) * D + cc) = __floats2half2_rn(o[nf][0] * i0, o[nf][1] * i0);
        *(__half2*)(Out + ((size_t)r1g * HQ + h) * D + cc) = __floats2half2_rn(o[nf][2] * i1, o[nf][3] * i1);
    }
}

// ---------------------------------------------------------------------------
extern "C" void kernel_launch(void* const* d_in, const int* in_sizes, int n_in,
                              void* d_out, int out_size) {
    const float* hidden = (const float*)d_in[0];
    const float* cosp   = (const float*)d_in[1];
    const float* sinp   = (const float*)d_in[2];
    const float* Wq     = (const float*)d_in[3];
    const float* Wk     = (const float*)d_in[4];
    const float* Wv     = (const float*)d_in[5];
    const float* Wo     = (const float*)d_in[6];
    const float* qw     = (const float*)d_in[7];
    const float* kw     = (const float*)d_in[8];
    float* out = (float*)d_out;

    float *q, *k, *v;
    cudaGetSymbolAddress((void**)&q, g_q);
    cudaGetSymbolAddress((void**)&k, g_k);
    cudaGetSymbolAddress((void**)&v, g_v);
    __half *hh, *wqh, *wql, *wkh, *wkl, *wvh, *wvl, *woh, *wol, *ah;
    cudaGetSymbolAddress((void**)&hh,  g_hh);
    cudaGetSymbolAddress((void**)&wqh, g_wq_h); cudaGetSymbolAddress((void**)&wql, g_wq_l);
    cudaGetSymbolAddress((void**)&wkh, g_wk_h); cudaGetSymbolAddress((void**)&wkl, g_wk_l);
    cudaGetSymbolAddress((void**)&wvh, g_wv_h); cudaGetSymbolAddress((void**)&wvl, g_wv_l);
    cudaGetSymbolAddress((void**)&woh, g_wo_h); cudaGetSymbolAddress((void**)&wol, g_wo_l);
    cudaGetSymbolAddress((void**)&ah,  g_ah);
    __nv_bfloat16 *qbh, *qbl, *kbh, *kbl, *vbh, *vbl;
    cudaGetSymbolAddress((void**)&qbh, g_qbh); cudaGetSymbolAddress((void**)&qbl, g_qbl);
    cudaGetSymbolAddress((void**)&kbh, g_kbh); cudaGetSymbolAddress((void**)&kbl, g_kbl);
    cudaGetSymbolAddress((void**)&vbh, g_vbh); cudaGetSymbolAddress((void**)&vbl, g_vbl);

    cudaFuncSetAttribute(gemm_f16, cudaFuncAttributeMaxDynamicSharedMemorySize, GEMM_SMEM);
    cudaFuncSetAttribute(attn_mma, cudaFuncAttributeMaxDynamicSharedMemorySize, AT_SMEM);

    const int nH = S * HID, nWq = HQ * D * HID, nWk = HKV * D * HID, nWo = HID * HQ * D;
    conv_h<<<nH / 1024, 256>>>(hidden, hh, nH);
    split_hilo_h<<<nWq / 1024, 256>>>(Wq, wqh, wql, nWq);
    split_hilo_h<<<nWk / 1024, 256>>>(Wk, wkh, wkl, nWk);
    split_hilo_h<<<nWk / 1024, 256>>>(Wv, wvh, wvl, nWk);
    split_hilo_h<<<nWo / 1024, 256>>>(Wo, woh, wol, nWo);

    gemm_f16<<<dim3((HQ * D) / 128, S / 128), 256, GEMM_SMEM>>>(hh, wqh, wql, q, HQ * D, HID);
    gemm_f16<<<dim3((HKV * D) / 128, S / 128), 256, GEMM_SMEM>>>(hh, wkh, wkl, k, HKV * D, HID);
    gemm_f16<<<dim3((HKV * D) / 128, S / 128), 256, GEMM_SMEM>>>(hh, wvh, wvl, v, HKV * D, HID);

    rmsnorm_rope_split<<<dim3(S, HQ), D>>>(q, qw, cosp, sinp, HQ, qbh, qbl);
    rmsnorm_rope_split<<<dim3(S, HKV), D>>>(k, kw, cosp, sinp, HKV, kbh, kbl);
    split_hilo_bf<<<(S * HKV * D) / 1024, 256>>>(v, vbh, vbl, S * HKV * D);

    attn_mma<<<dim3(S / 64, HQ), 128, AT_SMEM>>>(qbh, qbl, kbh, kbl, vbh, vbl, ah);

    gemm_f16<<<dim3(HID / 128, S / 128), 256, GEMM_SMEM>>>(ah, woh, wol, out, HID, HQ * D);
}

// round 8
// speedup vs baseline: 4.5206x; 1.0890x over previous
#include <cuda_runtime.h>
#include <cuda_bf16.h>
#include <cuda_fp16.h>
#include <math.h>
#include <cstdint>

constexpr int S = 4096, HID = 2048, HQ = 16, HKV = 8, D = 128, WINDOW = 1024;

// fp32 intermediates
__device__ float g_q[(size_t)S * HQ * D];
__device__ float g_k[(size_t)S * HKV * D];
__device__ float g_v[(size_t)S * HKV * D];
// fp16 GEMM operands
__device__ __half g_hh[(size_t)S * HID];
__device__ __half g_wq_h[(size_t)HQ * D * HID], g_wq_l[(size_t)HQ * D * HID];
__device__ __half g_wk_h[(size_t)HKV * D * HID], g_wk_l[(size_t)HKV * D * HID];
__device__ __half g_wv_h[(size_t)HKV * D * HID], g_wv_l[(size_t)HKV * D * HID];
__device__ __half g_wo_h[(size_t)HID * HQ * D],  g_wo_l[(size_t)HID * HQ * D];
__device__ __half g_ah[(size_t)S * HQ * D];
// fp16 attention operands
__device__ __half g_qf[(size_t)S * HQ * D];
__device__ __half g_kfh[(size_t)S * HKV * D], g_kfl[(size_t)S * HKV * D];
__device__ __half g_vfh[(size_t)S * HKV * D], g_vfl[(size_t)S * HKV * D];

// ---------------------------------------------------------------------------
__device__ __forceinline__ uint32_t smem_u32(const void* p) {
    uint32_t a;
    asm("{ .reg .u64 t; cvta.to.shared.u64 t, %1; cvt.u32.u64 %0, t; }" : "=r"(a) : "l"(p));
    return a;
}
__device__ __forceinline__ uint32_t swz(uint32_t o) { return o ^ ((o >> 3) & 0x70); }
__device__ __forceinline__ uint32_t sw256(int r, int c) {
    return (uint32_t)(r * 256 + (((c ^ r) & 7) << 4) + ((c & 8) << 4));
}

#define CP_ASYNC16(dst, src) \
    asm volatile("cp.async.cg.shared.global [%0], [%1], 16;" :: "r"(dst), "l"(src))
#define CP_COMMIT() asm volatile("cp.async.commit_group;" ::: "memory")
#define CP_WAIT1()  asm volatile("cp.async.wait_group 1;" ::: "memory")
#define CP_WAIT0()  asm volatile("cp.async.wait_group 0;" ::: "memory")

#define LDSM_X4(r0, r1, r2, r3, addr) \
    asm volatile("ldmatrix.sync.aligned.m8n8.x4.shared.b16 {%0,%1,%2,%3}, [%4];" \
                 : "=r"(r0), "=r"(r1), "=r"(r2), "=r"(r3) : "r"(addr))
#define LDSM_X4_T(r0, r1, r2, r3, addr) \
    asm volatile("ldmatrix.sync.aligned.m8n8.x4.trans.shared.b16 {%0,%1,%2,%3}, [%4];" \
                 : "=r"(r0), "=r"(r1), "=r"(r2), "=r"(r3) : "r"(addr))

#define MMA_F16(d, a, b) \
    asm volatile("mma.sync.aligned.m16n8k16.row.col.f32.f16.f16.f32 " \
                 "{%0,%1,%2,%3},{%4,%5,%6,%7},{%8,%9},{%0,%1,%2,%3};" \
                 : "+f"((d)[0]), "+f"((d)[1]), "+f"((d)[2]), "+f"((d)[3]) \
                 : "r"((a)[0]), "r"((a)[1]), "r"((a)[2]), "r"((a)[3]), \
                   "r"((b)[0]), "r"((b)[1]))

__device__ __forceinline__ uint32_t pack_h2(float a, float b) {
    __half2 t = __floats2half2_rn(a, b);
    return *(uint32_t*)&t;
}

// ---------------------------------------------------------------------------
// fp32 -> fp16 hi/lo split
// ---------------------------------------------------------------------------
__global__ __launch_bounds__(256)
void split_hilo_h(const float* __restrict__ x, __half* __restrict__ hi,
                  __half* __restrict__ lo, int n) {
    int i = (blockIdx.x * 256 + threadIdx.x) * 4;
    if (i >= n) return;
    float4 v = *(const float4*)(x + i);
    __half2 h01 = __floats2half2_rn(v.x, v.y);
    __half2 h23 = __floats2half2_rn(v.z, v.w);
    __half2 l01 = __floats2half2_rn(v.x - __half2float(h01.x), v.y - __half2float(h01.y));
    __half2 l23 = __floats2half2_rn(v.z - __half2float(h23.x), v.w - __half2float(h23.y));
    *(__half2*)(hi + i)     = h01;
    *(__half2*)(hi + i + 2) = h23;
    *(__half2*)(lo + i)     = l01;
    *(__half2*)(lo + i + 2) = l23;
}
// fp32 -> fp16 (hi only)
__global__ __launch_bounds__(256)
void conv_h(const float* __restrict__ x, __half* __restrict__ hi, int n) {
    int i = (blockIdx.x * 256 + threadIdx.x) * 4;
    if (i >= n) return;
    float4 v = *(const float4*)(x + i);
    *(__half2*)(hi + i)     = __floats2half2_rn(v.x, v.y);
    *(__half2*)(hi + i + 2) = __floats2half2_rn(v.z, v.w);
}

// ---------------------------------------------------------------------------
// fp16 2-term GEMM: C[M,N] = Ah[M,K] @ (Bh+Bl)[N,K]^T, fp32 accum.
// ---------------------------------------------------------------------------
constexpr int TILE_BYTES = 128 * 64 * 2;
constexpr int BUF_BYTES  = 3 * TILE_BYTES;
constexpr int GEMM_SMEM  = 2 * BUF_BYTES;

__global__ __launch_bounds__(256, 2)
void gemm_f16(const __half* __restrict__ Ah, const __half* __restrict__ Bh,
              const __half* __restrict__ Bl, float* __restrict__ C, int N, int K) {
    extern __shared__ char smem[];
    const uint32_t sb = smem_u32(smem);
    const int tid = threadIdx.x;
    const int wid = tid >> 5;
    const int lane = tid & 31;
    const int wm = wid >> 2;
    const int wn = wid & 3;
    const int bm = blockIdx.y * 128;
    const int bn = blockIdx.x * 128;

    const __half* srcs[3] = { Ah, Bh, Bl };
    const int row0s[3] = { bm, bn, bn };

    auto issue_copy = [&](int c) {
        const uint32_t base = sb + (uint32_t)(c & 1) * BUF_BYTES;
        const int k0 = c << 6;
#pragma unroll
        for (int t = 0; t < 3; t++) {
            const __half* src = srcs[t];
            const int row0 = row0s[t];
            const uint32_t tbase = base + t * TILE_BYTES;
#pragma unroll
            for (int i = 0; i < 4; i++) {
                int idx = tid + i * 256;
                int r  = idx >> 3;
                int cc = idx & 7;
                uint32_t dst = tbase + swz((uint32_t)(r * 128 + cc * 16));
                const void* s = src + (size_t)(row0 + r) * K + k0 + cc * 8;
                CP_ASYNC16(dst, s);
            }
        }
        CP_COMMIT();
    };

    float acc[4][4][4];
#pragma unroll
    for (int a = 0; a < 4; a++)
#pragma unroll
        for (int b = 0; b < 4; b++)
#pragma unroll
            for (int x = 0; x < 4; x++) acc[a][b][x] = 0.f;

    const int arow = (lane & 15);
    const int ahi  = lane >> 4;
    uint32_t a_rowoff[4];
#pragma unroll
    for (int mf = 0; mf < 4; mf++)
        a_rowoff[mf] = (uint32_t)((wm * 64 + mf * 16 + arow) * 128);
    const uint32_t arx = (uint32_t)(arow & 7);

    const int bnrow = (lane & 7) + ((lane >> 4) & 1) * 8;
    const int bhi   = (lane >> 3) & 1;
    uint32_t b_rowoff[2];
#pragma unroll
    for (int bf = 0; bf < 2; bf++)
        b_rowoff[bf] = (uint32_t)((wn * 32 + bf * 16 + bnrow) * 128);
    const uint32_t brx = (uint32_t)(bnrow & 7);

    const int NC = K >> 6;
    issue_copy(0);
    if (NC > 1) issue_copy(1);

    for (int c = 0; c < NC; c++) {
        if (c < NC - 1) { CP_WAIT1(); } else { CP_WAIT0(); }
        __syncthreads();

        const uint32_t base = sb + (uint32_t)(c & 1) * BUF_BYTES;
        const uint32_t A_b = base;
        const uint32_t B_hi_b = base + TILE_BYTES, B_lo_b = base + 2 * TILE_BYTES;

#pragma unroll
        for (int ks = 0; ks < 4; ks++) {
            uint32_t ah[4][4], bh[2][4], bl[2][4];
            const uint32_t ac = (uint32_t)(ks * 2 + ahi);
            const uint32_t bc = (uint32_t)(ks * 2 + bhi);
#pragma unroll
            for (int mf = 0; mf < 4; mf++) {
                uint32_t off = a_rowoff[mf] + ((ac ^ arx) << 4);
                LDSM_X4(ah[mf][0], ah[mf][1], ah[mf][2], ah[mf][3], A_b + off);
            }
#pragma unroll
            for (int bf = 0; bf < 2; bf++) {
                uint32_t off = b_rowoff[bf] + ((bc ^ brx) << 4);
                LDSM_X4(bh[bf][0], bh[bf][1], bh[bf][2], bh[bf][3], B_hi_b + off);
                LDSM_X4(bl[bf][0], bl[bf][1], bl[bf][2], bl[bf][3], B_lo_b + off);
            }
#pragma unroll
            for (int mf = 0; mf < 4; mf++)
#pragma unroll
                for (int nf = 0; nf < 4; nf++) {
                    uint32_t* bhp = &bh[nf >> 1][(nf & 1) * 2];
                    uint32_t* blp = &bl[nf >> 1][(nf & 1) * 2];
                    MMA_F16(acc[mf][nf], ah[mf], bhp);
                    MMA_F16(acc[mf][nf], ah[mf], blp);
                }
        }
        __syncthreads();
        if (c + 2 < NC) issue_copy(c + 2);
    }

    const int er = lane >> 2;
    const int ec = (lane & 3) * 2;
#pragma unroll
    for (int mf = 0; mf < 4; mf++) {
        const int r0 = bm + wm * 64 + mf * 16 + er;
#pragma unroll
        for (int nf = 0; nf < 4; nf++) {
            const int cc = bn + wn * 32 + nf * 8 + ec;
            *(float2*)(C + (size_t)r0 * N + cc)       = make_float2(acc[mf][nf][0], acc[mf][nf][1]);
            *(float2*)(C + (size_t)(r0 + 8) * N + cc) = make_float2(acc[mf][nf][2], acc[mf][nf][3]);
        }
    }
}

// ---------------------------------------------------------------------------
// Fused RMSNorm + RoPE, output fp16 hi/lo
// ---------------------------------------------------------------------------
__global__ __launch_bounds__(128)
void rmsnorm_rope_h(const float* __restrict__ X, const float* __restrict__ w,
                    const float* __restrict__ cosp, const float* __restrict__ sinp,
                    int H, __half* __restrict__ hi, __half* __restrict__ lo) {
    const int s = blockIdx.x, h = blockIdx.y, d = threadIdx.x;
    const float* row = X + ((size_t)s * H + h) * D;
    float x = row[d];
    float sq = x * x;
#pragma unroll
    for (int o = 16; o > 0; o >>= 1) sq += __shfl_xor_sync(0xffffffffu, sq, o);
    __shared__ float red[4];
    __shared__ float xs[D];
    if ((d & 31) == 0) red[d >> 5] = sq;
    __syncthreads();
    float var = (red[0] + red[1] + red[2] + red[3]) * (1.0f / D);
    float xn = x * rsqrtf(var + 1e-6f) * w[d];
    xs[d] = xn;
    __syncthreads();
    float other = (d < 64) ? -xs[d + 64] : xs[d - 64];
    float val = fmaf(xn, cosp[s * D + d], other * sinp[s * D + d]);
    size_t idx = ((size_t)s * H + h) * D + d;
    __half hb = __float2half_rn(val);
    hi[idx] = hb;
    if (lo) lo[idx] = __float2half_rn(val - __half2float(hb));
}

// ---------------------------------------------------------------------------
// MMA flash attention, fp16 2-term: S = Qh(Kh+Kl), O = Ph(Vh+Vl).
// 4 warps, 64 queries/CTA, 32-key tiles, fp32 softmax.
// ---------------------------------------------------------------------------
constexpr int AT_SMEM = 81920;   // 2 x 32KB KV + 16KB Q
constexpr float SCALE = 0.088388347648318447f;
constexpr float L2E   = 1.4426950408889634f;

__global__ __launch_bounds__(128, 1)
void attn_mma(const __half* __restrict__ Qf,
              const __half* __restrict__ Kh, const __half* __restrict__ Kl,
              const __half* __restrict__ Vh, const __half* __restrict__ Vl,
              __half* __restrict__ Out) {
    extern __shared__ char smem[];
    const uint32_t sb = smem_u32(smem);
    const int tid = threadIdx.x;
    const int w = tid >> 5, lane = tid & 31;
    const int h = blockIdx.y, kvh = h >> 1;
    const int q0 = blockIdx.x * 64;

    const uint32_t QB = sb + 65536;

    // stage Q (64 rows x 16 16B-chunks)
#pragma unroll
    for (int i = 0; i < 8; i++) {
        int idx = tid + i * 128;
        int r = idx >> 4, c = idx & 15;
        const __half* src = Qf + ((size_t)(q0 + r) * HQ + h) * D + c * 8;
        CP_ASYNC16(QB + sw256(r, c), src);
    }
    CP_COMMIT();
    CP_WAIT0();
    __syncthreads();

    uint32_t qf[8][4];
    {
        const int arow = lane & 15, ahi = lane >> 4;
#pragma unroll
        for (int ks = 0; ks < 8; ks++) {
            uint32_t off = sw256(w * 16 + arow, 2 * ks + ahi);
            LDSM_X4(qf[ks][0], qf[ks][1], qf[ks][2], qf[ks][3], QB + off);
        }
    }

    float o[16][4];
#pragma unroll
    for (int nf = 0; nf < 16; nf++)
#pragma unroll
        for (int x = 0; x < 4; x++) o[nf][x] = 0.f;
    float m0 = 0.f, m1 = 0.f, l0 = 0.f, l1 = 0.f;

    int jlo = q0 - (WINDOW - 1);
    if (jlo < 0) jlo = 0;
    jlo &= ~31;
    const int NT = (q0 + 64 - jlo) >> 5;

    auto issue_kv = [&](int t) {
        const int j0 = jlo + t * 32;
        const uint32_t base = sb + (uint32_t)(t & 1) * 32768;
        const __half* srcs[4] = { Kh, Kl, Vh, Vl };
#pragma unroll
        for (int i = 0; i < 16; i++) {
            int idx = tid + i * 128;
            int ten = idx >> 9;
            int rem = idx & 511;
            int r = rem >> 4, c = rem & 15;
            const __half* src = srcs[ten] + ((size_t)(j0 + r) * HKV + kvh) * D + c * 8;
            CP_ASYNC16(base + ten * 8192 + sw256(r, c), src);
        }
        CP_COMMIT();
    };

    issue_kv(0);
    if (NT > 1) issue_kv(1);

    const int bnrow = (lane & 7) + ((lane >> 4) & 1) * 8;
    const int bhi = (lane >> 3) & 1;
    const int er = lane >> 2, ec = (lane & 3) * 2;
    const int r0g = q0 + w * 16 + er, r1g = r0g + 8;
    const int vg = lane >> 3, vr = lane & 7;

    for (int t = 0; t < NT; t++) {
        if (t < NT - 1) { CP_WAIT1(); } else { CP_WAIT0(); }
        __syncthreads();
        const int j0 = jlo + t * 32;
        const uint32_t base = sb + (uint32_t)(t & 1) * 32768;
        const uint32_t KHB = base, KLB = base + 8192, VHB = base + 16384, VLB = base + 24576;

        // ---- S = Qh @ (Kh + Kl)^T ----
        float s[4][4];
#pragma unroll
        for (int nf = 0; nf < 4; nf++)
#pragma unroll
            for (int x = 0; x < 4; x++) s[nf][x] = 0.f;
#pragma unroll
        for (int ks = 0; ks < 8; ks++) {
            uint32_t kfh[2][4], kfl[2][4];
            const int ch = 2 * ks + bhi;
            uint32_t off0 = sw256(bnrow, ch), off1 = sw256(16 + bnrow, ch);
            LDSM_X4(kfh[0][0], kfh[0][1], kfh[0][2], kfh[0][3], KHB + off0);
            LDSM_X4(kfh[1][0], kfh[1][1], kfh[1][2], kfh[1][3], KHB + off1);
            LDSM_X4(kfl[0][0], kfl[0][1], kfl[0][2], kfl[0][3], KLB + off0);
            LDSM_X4(kfl[1][0], kfl[1][1], kfl[1][2], kfl[1][3], KLB + off1);
#pragma unroll
            for (int nf = 0; nf < 4; nf++) {
                uint32_t* bhp = &kfh[nf >> 1][(nf & 1) * 2];
                uint32_t* blp = &kfl[nf >> 1][(nf & 1) * 2];
                MMA_F16(s[nf], qf[ks], bhp);
                MMA_F16(s[nf], qf[ks], blp);
            }
        }

        // ---- mask + scale + row max ----
        float mn0 = m0, mn1 = m1;
#pragma unroll
        for (int nf = 0; nf < 4; nf++) {
#pragma unroll
            for (int cx = 0; cx < 2; cx++) {
                const int jj = j0 + nf * 8 + ec + cx;
                s[nf][cx]     = (jj <= r0g && jj > r0g - WINDOW) ? s[nf][cx] * SCALE     : -1e9f;
                s[nf][2 + cx] = (jj <= r1g && jj > r1g - WINDOW) ? s[nf][2 + cx] * SCALE : -1e9f;
            }
            mn0 = fmaxf(mn0, fmaxf(s[nf][0], s[nf][1]));
            mn1 = fmaxf(mn1, fmaxf(s[nf][2], s[nf][3]));
        }
        mn0 = fmaxf(mn0, __shfl_xor_sync(0xffffffffu, mn0, 1));
        mn0 = fmaxf(mn0, __shfl_xor_sync(0xffffffffu, mn0, 2));
        mn1 = fmaxf(mn1, __shfl_xor_sync(0xffffffffu, mn1, 1));
        mn1 = fmaxf(mn1, __shfl_xor_sync(0xffffffffu, mn1, 2));
        const float a0 = exp2f((m0 - mn0) * L2E);
        const float a1 = exp2f((m1 - mn1) * L2E);
        m0 = mn0; m1 = mn1;

        // ---- P = exp(S - m), pack fp16 A-fragments ----
        float rs0 = 0.f, rs1 = 0.f;
        uint32_t ph[2][4];
#pragma unroll
        for (int kk = 0; kk < 2; kk++) {
            float p[2][4];
#pragma unroll
            for (int q2 = 0; q2 < 2; q2++) {
                const int nf = 2 * kk + q2;
                p[q2][0] = exp2f((s[nf][0] - m0) * L2E);
                p[q2][1] = exp2f((s[nf][1] - m0) * L2E);
                p[q2][2] = exp2f((s[nf][2] - m1) * L2E);
                p[q2][3] = exp2f((s[nf][3] - m1) * L2E);
                rs0 += p[q2][0] + p[q2][1];
                rs1 += p[q2][2] + p[q2][3];
            }
            ph[kk][0] = pack_h2(p[0][0], p[0][1]);
            ph[kk][1] = pack_h2(p[0][2], p[0][3]);
            ph[kk][2] = pack_h2(p[1][0], p[1][1]);
            ph[kk][3] = pack_h2(p[1][2], p[1][3]);
        }
        rs0 += __shfl_xor_sync(0xffffffffu, rs0, 1);
        rs0 += __shfl_xor_sync(0xffffffffu, rs0, 2);
        rs1 += __shfl_xor_sync(0xffffffffu, rs1, 1);
        rs1 += __shfl_xor_sync(0xffffffffu, rs1, 2);
        l0 = l0 * a0 + rs0;
        l1 = l1 * a1 + rs1;

#pragma unroll
        for (int nf = 0; nf < 16; nf++) {
            o[nf][0] *= a0; o[nf][1] *= a0;
            o[nf][2] *= a1; o[nf][3] *= a1;
        }

        // ---- O += Ph @ (Vh + Vl) ----
#pragma unroll
        for (int kk = 0; kk < 2; kk++) {
            const int vrow = kk * 16 + (vg & 1) * 8 + vr;
#pragma unroll
            for (int nc = 0; nc < 8; nc++) {
                uint32_t vfh[4], vfl[4];
                uint32_t off = sw256(vrow, nc * 2 + (vg >> 1));
                LDSM_X4_T(vfh[0], vfh[1], vfh[2], vfh[3], VHB + off);
                LDSM_X4_T(vfl[0], vfl[1], vfl[2], vfl[3], VLB + off);
                MMA_F16(o[nc * 2],     ph[kk], &vfh[0]);
                MMA_F16(o[nc * 2],     ph[kk], &vfl[0]);
                MMA_F16(o[nc * 2 + 1], ph[kk], &vfh[2]);
                MMA_F16(o[nc * 2 + 1], ph[kk], &vfl[2]);
            }
        }
        __syncthreads();
        if (t + 2 < NT) issue_kv(t + 2);
    }

    const float i0 = 1.f / l0, i1 = 1.f / l1;
#pragma unroll
    for (int nf = 0; nf < 16; nf++) {
        const int cc = nf * 8 + ec;
        *(__half2*)(Out + ((size_t)r0g * HQ + h) * D + cc) = __floats2half2_rn(o[nf][0] * i0, o[nf][1] * i0);
        *(__half2*)(Out + ((size_t)r1g * HQ + h) * D + cc) = __floats2half2_rn(o[nf][2] * i1, o[nf][3] * i1);
    }
}

// ---------------------------------------------------------------------------
extern "C" void kernel_launch(void* const* d_in, const int* in_sizes, int n_in,
                              void* d_out, int out_size) {
    const float* hidden = (const float*)d_in[0];
    const float* cosp   = (const float*)d_in[1];
    const float* sinp   = (const float*)d_in[2];
    const float* Wq     = (const float*)d_in[3];
    const float* Wk     = (const float*)d_in[4];
    const float* Wv     = (const float*)d_in[5];
    const float* Wo     = (const float*)d_in[6];
    const float* qw     = (const float*)d_in[7];
    const float* kw     = (const float*)d_in[8];
    float* out = (float*)d_out;

    float *q, *k, *v;
    cudaGetSymbolAddress((void**)&q, g_q);
    cudaGetSymbolAddress((void**)&k, g_k);
    cudaGetSymbolAddress((void**)&v, g_v);
    __half *hh, *wqh, *wql, *wkh, *wkl, *wvh, *wvl, *woh, *wol, *ah;
    __half *qf, *kfh, *kfl, *vfh, *vfl;
    cudaGetSymbolAddress((void**)&hh,  g_hh);
    cudaGetSymbolAddress((void**)&wqh, g_wq_h); cudaGetSymbolAddress((void**)&wql, g_wq_l);
    cudaGetSymbolAddress((void**)&wkh, g_wk_h); cudaGetSymbolAddress((void**)&wkl, g_wk_l);
    cudaGetSymbolAddress((void**)&wvh, g_wv_h); cudaGetSymbolAddress((void**)&wvl, g_wv_l);
    cudaGetSymbolAddress((void**)&woh, g_wo_h); cudaGetSymbolAddress((void**)&wol, g_wo_l);
    cudaGetSymbolAddress((void**)&ah,  g_ah);
    cudaGetSymbolAddress((void**)&qf,  g_qf);
    cudaGetSymbolAddress((void**)&kfh, g_kfh); cudaGetSymbolAddress((void**)&kfl, g_kfl);
    cudaGetSymbolAddress((void**)&vfh, g_vfh); cudaGetSymbolAddress((void**)&vfl, g_vfl);

    cudaFuncSetAttribute(gemm_f16, cudaFuncAttributeMaxDynamicSharedMemorySize, GEMM_SMEM);
    cudaFuncSetAttribute(attn_mma, cudaFuncAttributeMaxDynamicSharedMemorySize, AT_SMEM);

    const int nH = S * HID, nWq = HQ * D * HID, nWk = HKV * D * HID, nWo = HID * HQ * D;
    conv_h<<<nH / 1024, 256>>>(hidden, hh, nH);
    split_hilo_h<<<nWq / 1024, 256>>>(Wq, wqh, wql, nWq);
    split_hilo_h<<<nWk / 1024, 256>>>(Wk, wkh, wkl, nWk);
    split_hilo_h<<<nWk / 1024, 256>>>(Wv, wvh, wvl, nWk);
    split_hilo_h<<<nWo / 1024, 256>>>(Wo, woh, wol, nWo);

    gemm_f16<<<dim3((HQ * D) / 128, S / 128), 256, GEMM_SMEM>>>(hh, wqh, wql, q, HQ * D, HID);
    gemm_f16<<<dim3((HKV * D) / 128, S / 128), 256, GEMM_SMEM>>>(hh, wkh, wkl, k, HKV * D, HID);
    gemm_f16<<<dim3((HKV * D) / 128, S / 128), 256, GEMM_SMEM>>>(hh, wvh, wvl, v, HKV * D, HID);

    rmsnorm_rope_h<<<dim3(S, HQ), D>>>(q, qw, cosp, sinp, HQ, qf, nullptr);
    rmsnorm_rope_h<<<dim3(S, HKV), D>>>(k, kw, cosp, sinp, HKV, kfh, kfl);
    split_hilo_h<<<(S * HKV * D) / 1024, 256>>>(v, vfh, vfl, S * HKV * D);

    attn_mma<<<dim3(S / 64, HQ), 128, AT_SMEM>>>(qf, kfh, kfl, vfh, vfl, ah);

    gemm_f16<<<dim3(HID / 128, S / 128), 256, GEMM_SMEM>>>(ah, woh, wol, out, HID, HQ * D);
}

// round 9
// speedup vs baseline: 6.2925x; 1.3920x over previous
#include <cuda_runtime.h>
#include <cuda_bf16.h>
#include <cuda_fp16.h>
#include <math.h>
#include <cstdint>

constexpr int S = 4096, HID = 2048, HQ = 16, HKV = 8, D = 128, WINDOW = 1024;

// fp32 intermediates
__device__ float g_q[(size_t)S * HQ * D];
__device__ float g_k[(size_t)S * HKV * D];
__device__ float g_v[(size_t)S * HKV * D];
// fp16 GEMM operands
__device__ __half g_hh[(size_t)S * HID];
__device__ __half g_wq[(size_t)HQ * D * HID];
__device__ __half g_wk[(size_t)HKV * D * HID];
__device__ __half g_wv[(size_t)HKV * D * HID];
__device__ __half g_wo[(size_t)HID * HQ * D];
__device__ __half g_ah[(size_t)S * HQ * D];
// fp16 attention operands
__device__ __half g_qf[(size_t)S * HQ * D];
__device__ __half g_kfh[(size_t)S * HKV * D], g_kfl[(size_t)S * HKV * D];
__device__ __half g_vfh[(size_t)S * HKV * D], g_vfl[(size_t)S * HKV * D];

// ---------------------------------------------------------------------------
__device__ __forceinline__ uint32_t smem_u32(const void* p) {
    uint32_t a;
    asm("{ .reg .u64 t; cvta.to.shared.u64 t, %1; cvt.u32.u64 %0, t; }" : "=r"(a) : "l"(p));
    return a;
}
__device__ __forceinline__ uint32_t swz(uint32_t o) { return o ^ ((o >> 3) & 0x70); }
__device__ __forceinline__ uint32_t sw256(int r, int c) {
    return (uint32_t)(r * 256 + (((c ^ r) & 7) << 4) + ((c & 8) << 4));
}

#define CP_ASYNC16(dst, src) \
    asm volatile("cp.async.cg.shared.global [%0], [%1], 16;" :: "r"(dst), "l"(src))
#define CP_COMMIT() asm volatile("cp.async.commit_group;" ::: "memory")
#define CP_WAIT1()  asm volatile("cp.async.wait_group 1;" ::: "memory")
#define CP_WAIT0()  asm volatile("cp.async.wait_group 0;" ::: "memory")

#define LDSM_X4(r0, r1, r2, r3, addr) \
    asm volatile("ldmatrix.sync.aligned.m8n8.x4.shared.b16 {%0,%1,%2,%3}, [%4];" \
                 : "=r"(r0), "=r"(r1), "=r"(r2), "=r"(r3) : "r"(addr))
#define LDSM_X4_T(r0, r1, r2, r3, addr) \
    asm volatile("ldmatrix.sync.aligned.m8n8.x4.trans.shared.b16 {%0,%1,%2,%3}, [%4];" \
                 : "=r"(r0), "=r"(r1), "=r"(r2), "=r"(r3) : "r"(addr))

#define MMA_F16(d, a, b) \
    asm volatile("mma.sync.aligned.m16n8k16.row.col.f32.f16.f16.f32 " \
                 "{%0,%1,%2,%3},{%4,%5,%6,%7},{%8,%9},{%0,%1,%2,%3};" \
                 : "+f"((d)[0]), "+f"((d)[1]), "+f"((d)[2]), "+f"((d)[3]) \
                 : "r"((a)[0]), "r"((a)[1]), "r"((a)[2]), "r"((a)[3]), \
                   "r"((b)[0]), "r"((b)[1]))

__device__ __forceinline__ uint32_t pack_h2(float a, float b) {
    __half2 t = __floats2half2_rn(a, b);
    return *(uint32_t*)&t;
}

// ---------------------------------------------------------------------------
// converts
// ---------------------------------------------------------------------------
__global__ __launch_bounds__(256)
void conv_h(const float* __restrict__ x, __half* __restrict__ hi, int n) {
    int i = (blockIdx.x * 256 + threadIdx.x) * 4;
    if (i >= n) return;
    float4 v = *(const float4*)(x + i);
    *(__half2*)(hi + i)     = __floats2half2_rn(v.x, v.y);
    *(__half2*)(hi + i + 2) = __floats2half2_rn(v.z, v.w);
}
__global__ __launch_bounds__(256)
void split_hilo_h(const float* __restrict__ x, __half* __restrict__ hi,
                  __half* __restrict__ lo, int n) {
    int i = (blockIdx.x * 256 + threadIdx.x) * 4;
    if (i >= n) return;
    float4 v = *(const float4*)(x + i);
    __half2 h01 = __floats2half2_rn(v.x, v.y);
    __half2 h23 = __floats2half2_rn(v.z, v.w);
    __half2 l01 = __floats2half2_rn(v.x - __half2float(h01.x), v.y - __half2float(h01.y));
    __half2 l23 = __floats2half2_rn(v.z - __half2float(h23.x), v.w - __half2float(h23.y));
    *(__half2*)(hi + i)     = h01;
    *(__half2*)(hi + i + 2) = h23;
    *(__half2*)(lo + i)     = l01;
    *(__half2*)(lo + i + 2) = l23;
}

// ---------------------------------------------------------------------------
// fp16 GEMM: C[M,N] = A[M,K] @ B[N,K]^T, fp32 accum.
// 128x128 CTA tile, BK=64, 8 warps, 64KB smem double-buffered.
// ---------------------------------------------------------------------------
constexpr int TILE_BYTES = 128 * 64 * 2;
constexpr int BUF_BYTES  = 2 * TILE_BYTES;   // A, B
constexpr int GEMM_SMEM  = 2 * BUF_BYTES;    // 64KB

__global__ __launch_bounds__(256, 2)
void gemm_f16(const __half* __restrict__ A, const __half* __restrict__ B,
              float* __restrict__ C, int N, int K) {
    extern __shared__ char smem[];
    const uint32_t sb = smem_u32(smem);
    const int tid = threadIdx.x;
    const int wid = tid >> 5;
    const int lane = tid & 31;
    const int wm = wid >> 2;
    const int wn = wid & 3;
    const int bm = blockIdx.y * 128;
    const int bn = blockIdx.x * 128;

    const __half* srcs[2] = { A, B };
    const int row0s[2] = { bm, bn };

    auto issue_copy = [&](int c) {
        const uint32_t base = sb + (uint32_t)(c & 1) * BUF_BYTES;
        const int k0 = c << 6;
#pragma unroll
        for (int t = 0; t < 2; t++) {
            const __half* src = srcs[t];
            const int row0 = row0s[t];
            const uint32_t tbase = base + t * TILE_BYTES;
#pragma unroll
            for (int i = 0; i < 4; i++) {
                int idx = tid + i * 256;
                int r  = idx >> 3;
                int cc = idx & 7;
                uint32_t dst = tbase + swz((uint32_t)(r * 128 + cc * 16));
                const void* s = src + (size_t)(row0 + r) * K + k0 + cc * 8;
                CP_ASYNC16(dst, s);
            }
        }
        CP_COMMIT();
    };

    float acc[4][4][4];
#pragma unroll
    for (int a = 0; a < 4; a++)
#pragma unroll
        for (int b = 0; b < 4; b++)
#pragma unroll
            for (int x = 0; x < 4; x++) acc[a][b][x] = 0.f;

    const int arow = (lane & 15);
    const int ahi  = lane >> 4;
    uint32_t a_rowoff[4];
#pragma unroll
    for (int mf = 0; mf < 4; mf++)
        a_rowoff[mf] = (uint32_t)((wm * 64 + mf * 16 + arow) * 128);
    const uint32_t arx = (uint32_t)(arow & 7);

    const int bnrow = (lane & 7) + ((lane >> 4) & 1) * 8;
    const int bhi   = (lane >> 3) & 1;
    uint32_t b_rowoff[2];
#pragma unroll
    for (int bf = 0; bf < 2; bf++)
        b_rowoff[bf] = (uint32_t)((wn * 32 + bf * 16 + bnrow) * 128);
    const uint32_t brx = (uint32_t)(bnrow & 7);

    const int NC = K >> 6;
    issue_copy(0);
    if (NC > 1) issue_copy(1);

    for (int c = 0; c < NC; c++) {
        if (c < NC - 1) { CP_WAIT1(); } else { CP_WAIT0(); }
        __syncthreads();

        const uint32_t base = sb + (uint32_t)(c & 1) * BUF_BYTES;
        const uint32_t A_b = base;
        const uint32_t B_b = base + TILE_BYTES;

#pragma unroll
        for (int ks = 0; ks < 4; ks++) {
            uint32_t ah[4][4], bh[2][4];
            const uint32_t ac = (uint32_t)(ks * 2 + ahi);
            const uint32_t bc = (uint32_t)(ks * 2 + bhi);
#pragma unroll
            for (int mf = 0; mf < 4; mf++) {
                uint32_t off = a_rowoff[mf] + ((ac ^ arx) << 4);
                LDSM_X4(ah[mf][0], ah[mf][1], ah[mf][2], ah[mf][3], A_b + off);
            }
#pragma unroll
            for (int bf = 0; bf < 2; bf++) {
                uint32_t off = b_rowoff[bf] + ((bc ^ brx) << 4);
                LDSM_X4(bh[bf][0], bh[bf][1], bh[bf][2], bh[bf][3], B_b + off);
            }
#pragma unroll
            for (int mf = 0; mf < 4; mf++)
#pragma unroll
                for (int nf = 0; nf < 4; nf++) {
                    MMA_F16(acc[mf][nf], ah[mf], (&bh[nf >> 1][(nf & 1) * 2]));
                }
        }
        __syncthreads();
        if (c + 2 < NC) issue_copy(c + 2);
    }

    const int er = lane >> 2;
    const int ec = (lane & 3) * 2;
#pragma unroll
    for (int mf = 0; mf < 4; mf++) {
        const int r0 = bm + wm * 64 + mf * 16 + er;
#pragma unroll
        for (int nf = 0; nf < 4; nf++) {
            const int cc = bn + wn * 32 + nf * 8 + ec;
            *(float2*)(C + (size_t)r0 * N + cc)       = make_float2(acc[mf][nf][0], acc[mf][nf][1]);
            *(float2*)(C + (size_t)(r0 + 8) * N + cc) = make_float2(acc[mf][nf][2], acc[mf][nf][3]);
        }
    }
}

// ---------------------------------------------------------------------------
// Fused RMSNorm + RoPE, output fp16 hi/lo
// ---------------------------------------------------------------------------
__global__ __launch_bounds__(128)
void rmsnorm_rope_h(const float* __restrict__ X, const float* __restrict__ w,
                    const float* __restrict__ cosp, const float* __restrict__ sinp,
                    int H, __half* __restrict__ hi, __half* __restrict__ lo) {
    const int s = blockIdx.x, h = blockIdx.y, d = threadIdx.x;
    const float* row = X + ((size_t)s * H + h) * D;
    float x = row[d];
    float sq = x * x;
#pragma unroll
    for (int o = 16; o > 0; o >>= 1) sq += __shfl_xor_sync(0xffffffffu, sq, o);
    __shared__ float red[4];
    __shared__ float xs[D];
    if ((d & 31) == 0) red[d >> 5] = sq;
    __syncthreads();
    float var = (red[0] + red[1] + red[2] + red[3]) * (1.0f / D);
    float xn = x * rsqrtf(var + 1e-6f) * w[d];
    xs[d] = xn;
    __syncthreads();
    float other = (d < 64) ? -xs[d + 64] : xs[d - 64];
    float val = fmaf(xn, cosp[s * D + d], other * sinp[s * D + d]);
    size_t idx = ((size_t)s * H + h) * D + d;
    __half hb = __float2half_rn(val);
    hi[idx] = hb;
    if (lo) lo[idx] = __float2half_rn(val - __half2float(hb));
}

// ---------------------------------------------------------------------------
// MMA flash attention, fp16 2-term: S = Qh(Kh+Kl), O = Ph(Vh+Vl).
// ---------------------------------------------------------------------------
constexpr int AT_SMEM = 81920;
constexpr float SCALE = 0.088388347648318447f;
constexpr float L2E   = 1.4426950408889634f;

__global__ __launch_bounds__(128, 1)
void attn_mma(const __half* __restrict__ Qf,
              const __half* __restrict__ Kh, const __half* __restrict__ Kl,
              const __half* __restrict__ Vh, const __half* __restrict__ Vl,
              __half* __restrict__ Out) {
    extern __shared__ char smem[];
    const uint32_t sb = smem_u32(smem);
    const int tid = threadIdx.x;
    const int w = tid >> 5, lane = tid & 31;
    const int h = blockIdx.y, kvh = h >> 1;
    const int q0 = blockIdx.x * 64;

    const uint32_t QB = sb + 65536;

#pragma unroll
    for (int i = 0; i < 8; i++) {
        int idx = tid + i * 128;
        int r = idx >> 4, c = idx & 15;
        const __half* src = Qf + ((size_t)(q0 + r) * HQ + h) * D + c * 8;
        CP_ASYNC16(QB + sw256(r, c), src);
    }
    CP_COMMIT();
    CP_WAIT0();
    __syncthreads();

    uint32_t qf[8][4];
    {
        const int arow = lane & 15, ahi = lane >> 4;
#pragma unroll
        for (int ks = 0; ks < 8; ks++) {
            uint32_t off = sw256(w * 16 + arow, 2 * ks + ahi);
            LDSM_X4(qf[ks][0], qf[ks][1], qf[ks][2], qf[ks][3], QB + off);
        }
    }

    float o[16][4];
#pragma unroll
    for (int nf = 0; nf < 16; nf++)
#pragma unroll
        for (int x = 0; x < 4; x++) o[nf][x] = 0.f;
    float m0 = 0.f, m1 = 0.f, l0 = 0.f, l1 = 0.f;

    int jlo = q0 - (WINDOW - 1);
    if (jlo < 0) jlo = 0;
    jlo &= ~31;
    const int NT = (q0 + 64 - jlo) >> 5;

    auto issue_kv = [&](int t) {
        const int j0 = jlo + t * 32;
        const uint32_t base = sb + (uint32_t)(t & 1) * 32768;
        const __half* srcs[4] = { Kh, Kl, Vh, Vl };
#pragma unroll
        for (int i = 0; i < 16; i++) {
            int idx = tid + i * 128;
            int ten = idx >> 9;
            int rem = idx & 511;
            int r = rem >> 4, c = rem & 15;
            const __half* src = srcs[ten] + ((size_t)(j0 + r) * HKV + kvh) * D + c * 8;
            CP_ASYNC16(base + ten * 8192 + sw256(r, c), src);
        }
        CP_COMMIT();
    };

    issue_kv(0);
    if (NT > 1) issue_kv(1);

    const int bnrow = (lane & 7) + ((lane >> 4) & 1) * 8;
    const int bhi = (lane >> 3) & 1;
    const int er = lane >> 2, ec = (lane & 3) * 2;
    const int r0g = q0 + w * 16 + er, r1g = r0g + 8;
    const int vg = lane >> 3, vr = lane & 7;

    for (int t = 0; t < NT; t++) {
        if (t < NT - 1) { CP_WAIT1(); } else { CP_WAIT0(); }
        __syncthreads();
        const int j0 = jlo + t * 32;
        const uint32_t base = sb + (uint32_t)(t & 1) * 32768;
        const uint32_t KHB = base, KLB = base + 8192, VHB = base + 16384, VLB = base + 24576;

        float s[4][4];
#pragma unroll
        for (int nf = 0; nf < 4; nf++)
#pragma unroll
            for (int x = 0; x < 4; x++) s[nf][x] = 0.f;
#pragma unroll
        for (int ks = 0; ks < 8; ks++) {
            uint32_t kfh[2][4], kfl[2][4];
            const int ch = 2 * ks + bhi;
            uint32_t off0 = sw256(bnrow, ch), off1 = sw256(16 + bnrow, ch);
            LDSM_X4(kfh[0][0], kfh[0][1], kfh[0][2], kfh[0][3], KHB + off0);
            LDSM_X4(kfh[1][0], kfh[1][1], kfh[1][2], kfh[1][3], KHB + off1);
            LDSM_X4(kfl[0][0], kfl[0][1], kfl[0][2], kfl[0][3], KLB + off0);
            LDSM_X4(kfl[1][0], kfl[1][1], kfl[1][2], kfl[1][3], KLB + off1);
#pragma unroll
            for (int nf = 0; nf < 4; nf++) {
                uint32_t* bhp = &kfh[nf >> 1][(nf & 1) * 2];
                uint32_t* blp = &kfl[nf >> 1][(nf & 1) * 2];
                MMA_F16(s[nf], qf[ks], bhp);
                MMA_F16(s[nf], qf[ks], blp);
            }
        }

        float mn0 = m0, mn1 = m1;
#pragma unroll
        for (int nf = 0; nf < 4; nf++) {
#pragma unroll
            for (int cx = 0; cx < 2; cx++) {
                const int jj = j0 + nf * 8 + ec + cx;
                s[nf][cx]     = (jj <= r0g && jj > r0g - WINDOW) ? s[nf][cx] * SCALE     : -1e9f;
                s[nf][2 + cx] = (jj <= r1g && jj > r1g - WINDOW) ? s[nf][2 + cx] * SCALE : -1e9f;
            }
            mn0 = fmaxf(mn0, fmaxf(s[nf][0], s[nf][1]));
            mn1 = fmaxf(mn1, fmaxf(s[nf][2], s[nf][3]));
        }
        mn0 = fmaxf(mn0, __shfl_xor_sync(0xffffffffu, mn0, 1));
        mn0 = fmaxf(mn0, __shfl_xor_sync(0xffffffffu, mn0, 2));
        mn1 = fmaxf(mn1, __shfl_xor_sync(0xffffffffu, mn1, 1));
        mn1 = fmaxf(mn1, __shfl_xor_sync(0xffffffffu, mn1, 2));
        const float a0 = exp2f((m0 - mn0) * L2E);
        const float a1 = exp2f((m1 - mn1) * L2E);
        m0 = mn0; m1 = mn1;

        float rs0 = 0.f, rs1 = 0.f;
        uint32_t ph[2][4];
#pragma unroll
        for (int kk = 0; kk < 2; kk++) {
            float p[2][4];
#pragma unroll
            for (int q2 = 0; q2 < 2; q2++) {
                const int nf = 2 * kk + q2;
                p[q2][0] = exp2f((s[nf][0] - m0) * L2E);
                p[q2][1] = exp2f((s[nf][1] - m0) * L2E);
                p[q2][2] = exp2f((s[nf][2] - m1) * L2E);
                p[q2][3] = exp2f((s[nf][3] - m1) * L2E);
                rs0 += p[q2][0] + p[q2][1];
                rs1 += p[q2][2] + p[q2][3];
            }
            ph[kk][0] = pack_h2(p[0][0], p[0][1]);
            ph[kk][1] = pack_h2(p[0][2], p[0][3]);
            ph[kk][2] = pack_h2(p[1][0], p[1][1]);
            ph[kk][3] = pack_h2(p[1][2], p[1][3]);
        }
        rs0 += __shfl_xor_sync(0xffffffffu, rs0, 1);
        rs0 += __shfl_xor_sync(0xffffffffu, rs0, 2);
        rs1 += __shfl_xor_sync(0xffffffffu, rs1, 1);
        rs1 += __shfl_xor_sync(0xffffffffu, rs1, 2);
        l0 = l0 * a0 + rs0;
        l1 = l1 * a1 + rs1;

#pragma unroll
        for (int nf = 0; nf < 16; nf++) {
            o[nf][0] *= a0; o[nf][1] *= a0;
            o[nf][2] *= a1; o[nf][3] *= a1;
        }

#pragma unroll
        for (int kk = 0; kk < 2; kk++) {
            const int vrow = kk * 16 + (vg & 1) * 8 + vr;
#pragma unroll
            for (int nc = 0; nc < 8; nc++) {
                uint32_t vfh[4], vfl[4];
                uint32_t off = sw256(vrow, nc * 2 + (vg >> 1));
                LDSM_X4_T(vfh[0], vfh[1], vfh[2], vfh[3], VHB + off);
                LDSM_X4_T(vfl[0], vfl[1], vfl[2], vfl[3], VLB + off);
                MMA_F16(o[nc * 2],     ph[kk], &vfh[0]);
                MMA_F16(o[nc * 2],     ph[kk], &vfl[0]);
                MMA_F16(o[nc * 2 + 1], ph[kk], &vfh[2]);
                MMA_F16(o[nc * 2 + 1], ph[kk], &vfl[2]);
            }
        }
        __syncthreads();
        if (t + 2 < NT) issue_kv(t + 2);
    }

    const float i0 = 1.f / l0, i1 = 1.f / l1;
#pragma unroll
    for (int nf = 0; nf < 16; nf++) {
        const int cc = nf * 8 + ec;
        *(__half2*)(Out + ((size_t)r0g * HQ + h) * D + cc) = __floats2half2_rn(o[nf][0] * i0, o[nf][1] * i0);
        *(__half2*)(Out + ((size_t)r1g * HQ + h) * D + cc) = __floats2half2_rn(o[nf][2] * i1, o[nf][3] * i1);
    }
}

// ---------------------------------------------------------------------------
extern "C" void kernel_launch(void* const* d_in, const int* in_sizes, int n_in,
                              void* d_out, int out_size) {
    const float* hidden = (const float*)d_in[0];
    const float* cosp   = (const float*)d_in[1];
    const float* sinp   = (const float*)d_in[2];
    const float* Wq     = (const float*)d_in[3];
    const float* Wk     = (const float*)d_in[4];
    const float* Wv     = (const float*)d_in[5];
    const float* Wo     = (const float*)d_in[6];
    const float* qw     = (const float*)d_in[7];
    const float* kw     = (const float*)d_in[8];
    float* out = (float*)d_out;

    float *q, *k, *v;
    cudaGetSymbolAddress((void**)&q, g_q);
    cudaGetSymbolAddress((void**)&k, g_k);
    cudaGetSymbolAddress((void**)&v, g_v);
    __half *hh, *wq, *wk, *wv, *wo, *ah;
    __half *qf, *kfh, *kfl, *vfh, *vfl;
    cudaGetSymbolAddress((void**)&hh, g_hh);
    cudaGetSymbolAddress((void**)&wq, g_wq);
    cudaGetSymbolAddress((void**)&wk, g_wk);
    cudaGetSymbolAddress((void**)&wv, g_wv);
    cudaGetSymbolAddress((void**)&wo, g_wo);
    cudaGetSymbolAddress((void**)&ah, g_ah);
    cudaGetSymbolAddress((void**)&qf,  g_qf);
    cudaGetSymbolAddress((void**)&kfh, g_kfh); cudaGetSymbolAddress((void**)&kfl, g_kfl);
    cudaGetSymbolAddress((void**)&vfh, g_vfh); cudaGetSymbolAddress((void**)&vfl, g_vfl);

    cudaFuncSetAttribute(gemm_f16, cudaFuncAttributeMaxDynamicSharedMemorySize, GEMM_SMEM);
    cudaFuncSetAttribute(attn_mma, cudaFuncAttributeMaxDynamicSharedMemorySize, AT_SMEM);

    const int nH = S * HID, nWq = HQ * D * HID, nWk = HKV * D * HID, nWo = HID * HQ * D;
    conv_h<<<nH / 1024, 256>>>(hidden, hh, nH);
    conv_h<<<nWq / 1024, 256>>>(Wq, wq, nWq);
    conv_h<<<nWk / 1024, 256>>>(Wk, wk, nWk);
    conv_h<<<nWk / 1024, 256>>>(Wv, wv, nWk);
    conv_h<<<nWo / 1024, 256>>>(Wo, wo, nWo);

    gemm_f16<<<dim3((HQ * D) / 128, S / 128), 256, GEMM_SMEM>>>(hh, wq, q, HQ * D, HID);
    gemm_f16<<<dim3((HKV * D) / 128, S / 128), 256, GEMM_SMEM>>>(hh, wk, k, HKV * D, HID);
    gemm_f16<<<dim3((HKV * D) / 128, S / 128), 256, GEMM_SMEM>>>(hh, wv, v, HKV * D, HID);

    rmsnorm_rope_h<<<dim3(S, HQ), D>>>(q, qw, cosp, sinp, HQ, qf, nullptr);
    rmsnorm_rope_h<<<dim3(S, HKV), D>>>(k, kw, cosp, sinp, HKV, kfh, kfl);
    split_hilo_h<<<(S * HKV * D) / 1024, 256>>>(v, vfh, vfl, S * HKV * D);

    attn_mma<<<dim3(S / 64, HQ), 128, AT_SMEM>>>(qf, kfh, kfl, vfh, vfl, ah);

    gemm_f16<<<dim3(HID / 128, S / 128), 256, GEMM_SMEM>>>(ah, wo, out, HID, HQ * D);
}

// round 11
// speedup vs baseline: 6.5036x; 1.0335x over previous
#include <cuda_runtime.h>
#include <cuda_bf16.h>
#include <cuda_fp16.h>
#include <math.h>
#include <cstdint>

constexpr int S = 4096, HID = 2048, HQ = 16, HKV = 8, D = 128, WINDOW = 1024;

// fp16 operands
__device__ __half g_hh[(size_t)S * HID];
__device__ __half g_wq[(size_t)HQ * D * HID];
__device__ __half g_wk[(size_t)HKV * D * HID];
__device__ __half g_wv[(size_t)HKV * D * HID];
__device__ __half g_wo[(size_t)HID * HQ * D];
__device__ __half g_ah[(size_t)S * HQ * D];
__device__ __half g_qf[(size_t)S * HQ * D];
__device__ __half g_kfh[(size_t)S * HKV * D], g_kfl[(size_t)S * HKV * D];
__device__ __half g_vfh[(size_t)S * HKV * D], g_vfl[(size_t)S * HKV * D];

// ---------------------------------------------------------------------------
__device__ __forceinline__ uint32_t smem_u32(const void* p) {
    uint32_t a;
    asm("{ .reg .u64 t; cvta.to.shared.u64 t, %1; cvt.u32.u64 %0, t; }" : "=r"(a) : "l"(p));
    return a;
}
__device__ __forceinline__ uint32_t swz(uint32_t o) { return o ^ ((o >> 3) & 0x70); }
__device__ __forceinline__ uint32_t sw256(int r, int c) {
    return (uint32_t)(r * 256 + (((c ^ r) & 7) << 4) + ((c & 8) << 4));
}

#define CP_ASYNC16(dst, src) \
    asm volatile("cp.async.cg.shared.global [%0], [%1], 16;" :: "r"(dst), "l"(src))
#define CP_COMMIT() asm volatile("cp.async.commit_group;" ::: "memory")
#define CP_WAIT1()  asm volatile("cp.async.wait_group 1;" ::: "memory")
#define CP_WAIT0()  asm volatile("cp.async.wait_group 0;" ::: "memory")

#define LDSM_X4(r0, r1, r2, r3, addr) \
    asm volatile("ldmatrix.sync.aligned.m8n8.x4.shared.b16 {%0,%1,%2,%3}, [%4];" \
                 : "=r"(r0), "=r"(r1), "=r"(r2), "=r"(r3) : "r"(addr))
#define LDSM_X4_T(r0, r1, r2, r3, addr) \
    asm volatile("ldmatrix.sync.aligned.m8n8.x4.trans.shared.b16 {%0,%1,%2,%3}, [%4];" \
                 : "=r"(r0), "=r"(r1), "=r"(r2), "=r"(r3) : "r"(addr))

#define MMA_F16(d, a, b) \
    asm volatile("mma.sync.aligned.m16n8k16.row.col.f32.f16.f16.f32 " \
                 "{%0,%1,%2,%3},{%4,%5,%6,%7},{%8,%9},{%0,%1,%2,%3};" \
                 : "+f"((d)[0]), "+f"((d)[1]), "+f"((d)[2]), "+f"((d)[3]) \
                 : "r"((a)[0]), "r"((a)[1]), "r"((a)[2]), "r"((a)[3]), \
                   "r"((b)[0]), "r"((b)[1]))

__device__ __forceinline__ uint32_t pack_h2(float a, float b) {
    __half2 t = __floats2half2_rn(a, b);
    return *(uint32_t*)&t;
}

// ---------------------------------------------------------------------------
__global__ __launch_bounds__(256)
void conv_h(const float* __restrict__ x, __half* __restrict__ hi, int n) {
    int i = (blockIdx.x * 256 + threadIdx.x) * 4;
    if (i >= n) return;
    float4 v = *(const float4*)(x + i);
    *(__half2*)(hi + i)     = __floats2half2_rn(v.x, v.y);
    *(__half2*)(hi + i + 2) = __floats2half2_rn(v.z, v.w);
}

// ---------------------------------------------------------------------------
// fp16 GEMM with fused epilogues.
// MODE 0: plain fp32 C              (Wo projection)
// MODE 1: RMSNorm+RoPE -> fp16 Oh   (Q)
// MODE 2: RMSNorm+RoPE -> fp16 Oh+Ol (K)
// MODE 3: hi/lo split  -> fp16 Oh+Ol (V)
// ---------------------------------------------------------------------------
constexpr int TILE_BYTES = 128 * 64 * 2;
constexpr int BUF_BYTES  = 2 * TILE_BYTES;
constexpr int XT_STRIDE  = 132;                        // padded fp32 row
constexpr int GEMM_SMEM  = 128 * XT_STRIDE * 4 + 2048; // 69632 >= 64KB pipeline

template<int MODE>
__global__ __launch_bounds__(256, 2)
void gemm_fused(const __half* __restrict__ A, const __half* __restrict__ B,
                float* __restrict__ Cf, __half* __restrict__ Oh, __half* __restrict__ Ol,
                const float* __restrict__ normw,
                const float* __restrict__ cosp, const float* __restrict__ sinp,
                int N, int K, int Hh) {
    extern __shared__ char smem[];
    const uint32_t sb = smem_u32(smem);
    const int tid = threadIdx.x;
    const int wid = tid >> 5;
    const int lane = tid & 31;
    const int wm = wid >> 2;
    const int wn = wid & 3;
    const int bm = blockIdx.y * 128;
    const int bn = blockIdx.x * 128;

    const __half* srcs[2] = { A, B };
    const int row0s[2] = { bm, bn };

    auto issue_copy = [&](int c) {
        const uint32_t base = sb + (uint32_t)(c & 1) * BUF_BYTES;
        const int k0 = c << 6;
#pragma unroll
        for (int t = 0; t < 2; t++) {
            const __half* src = srcs[t];
            const int row0 = row0s[t];
            const uint32_t tbase = base + t * TILE_BYTES;
#pragma unroll
            for (int i = 0; i < 4; i++) {
                int idx = tid + i * 256;
                int r  = idx >> 3;
                int cc = idx & 7;
                uint32_t dst = tbase + swz((uint32_t)(r * 128 + cc * 16));
                const void* s = src + (size_t)(row0 + r) * K + k0 + cc * 8;
                CP_ASYNC16(dst, s);
            }
        }
        CP_COMMIT();
    };

    float acc[4][4][4];
#pragma unroll
    for (int a = 0; a < 4; a++)
#pragma unroll
        for (int b = 0; b < 4; b++)
#pragma unroll
            for (int x = 0; x < 4; x++) acc[a][b][x] = 0.f;

    const int arow = (lane & 15);
    const int ahi  = lane >> 4;
    uint32_t a_rowoff[4];
#pragma unroll
    for (int mf = 0; mf < 4; mf++)
        a_rowoff[mf] = (uint32_t)((wm * 64 + mf * 16 + arow) * 128);
    const uint32_t arx = (uint32_t)(arow & 7);

    const int bnrow = (lane & 7) + ((lane >> 4) & 1) * 8;
    const int bhi   = (lane >> 3) & 1;
    uint32_t b_rowoff[2];
#pragma unroll
    for (int bf = 0; bf < 2; bf++)
        b_rowoff[bf] = (uint32_t)((wn * 32 + bf * 16 + bnrow) * 128);
    const uint32_t brx = (uint32_t)(bnrow & 7);

    const int NC = K >> 6;
    issue_copy(0);
    if (NC > 1) issue_copy(1);

    for (int c = 0; c < NC; c++) {
        if (c < NC - 1) { CP_WAIT1(); } else { CP_WAIT0(); }
        __syncthreads();

        const uint32_t base = sb + (uint32_t)(c & 1) * BUF_BYTES;
        const uint32_t A_b = base;
        const uint32_t B_b = base + TILE_BYTES;

#pragma unroll
        for (int ks = 0; ks < 4; ks++) {
            uint32_t ah[4][4], bh[2][4];
            const uint32_t ac = (uint32_t)(ks * 2 + ahi);
            const uint32_t bc = (uint32_t)(ks * 2 + bhi);
#pragma unroll
            for (int mf = 0; mf < 4; mf++) {
                uint32_t off = a_rowoff[mf] + ((ac ^ arx) << 4);
                LDSM_X4(ah[mf][0], ah[mf][1], ah[mf][2], ah[mf][3], A_b + off);
            }
#pragma unroll
            for (int bf = 0; bf < 2; bf++) {
                uint32_t off = b_rowoff[bf] + ((bc ^ brx) << 4);
                LDSM_X4(bh[bf][0], bh[bf][1], bh[bf][2], bh[bf][3], B_b + off);
            }
#pragma unroll
            for (int mf = 0; mf < 4; mf++)
#pragma unroll
                for (int nf = 0; nf < 4; nf++) {
                    MMA_F16(acc[mf][nf], ah[mf], (&bh[nf >> 1][(nf & 1) * 2]));
                }
        }
        __syncthreads();
        if (c + 2 < NC) issue_copy(c + 2);
    }

    const int er = lane >> 2;
    const int ec = (lane & 3) * 2;

    if (MODE == 0) {
#pragma unroll
        for (int mf = 0; mf < 4; mf++) {
            const int r0 = bm + wm * 64 + mf * 16 + er;
#pragma unroll
            for (int nf = 0; nf < 4; nf++) {
                const int cc = bn + wn * 32 + nf * 8 + ec;
                *(float2*)(Cf + (size_t)r0 * N + cc)       = make_float2(acc[mf][nf][0], acc[mf][nf][1]);
                *(float2*)(Cf + (size_t)(r0 + 8) * N + cc) = make_float2(acc[mf][nf][2], acc[mf][nf][3]);
            }
        }
        return;
    }

    const int hHead = bn >> 7;   // one head per 128-col tile

    if (MODE == 3) {
#pragma unroll
        for (int mf = 0; mf < 4; mf++) {
            const int s0 = bm + wm * 64 + mf * 16 + er;
#pragma unroll
            for (int nf = 0; nf < 4; nf++) {
                const int col = wn * 32 + nf * 8 + ec;
#pragma unroll
                for (int half2i = 0; half2i < 2; half2i++) {
                    const int sg = s0 + half2i * 8;
                    float v0 = acc[mf][nf][half2i * 2], v1 = acc[mf][nf][half2i * 2 + 1];
                    __half2 h2 = __floats2half2_rn(v0, v1);
                    __half2 l2 = __floats2half2_rn(v0 - __half2float(h2.x), v1 - __half2float(h2.y));
                    size_t idx = ((size_t)sg * Hh + hHead) * D + col;
                    *(__half2*)(Oh + idx) = h2;
                    *(__half2*)(Ol + idx) = l2;
                }
            }
        }
        return;
    }

    // MODE 1/2: RMSNorm + RoPE
    float* xt  = (float*)smem;                         // [128][XT_STRIDE]
    float* ssm = (float*)(smem + 128 * XT_STRIDE * 4); // [128][4]

#pragma unroll
    for (int mf = 0; mf < 4; mf++) {
        float s0 = 0.f, s1 = 0.f;
#pragma unroll
        for (int nf = 0; nf < 4; nf++) {
            s0 += acc[mf][nf][0] * acc[mf][nf][0] + acc[mf][nf][1] * acc[mf][nf][1];
            s1 += acc[mf][nf][2] * acc[mf][nf][2] + acc[mf][nf][3] * acc[mf][nf][3];
        }
        s0 += __shfl_xor_sync(0xffffffffu, s0, 1);
        s0 += __shfl_xor_sync(0xffffffffu, s0, 2);
        s1 += __shfl_xor_sync(0xffffffffu, s1, 1);
        s1 += __shfl_xor_sync(0xffffffffu, s1, 2);
        if ((lane & 3) == 0) {
            int r = wm * 64 + mf * 16 + er;
            ssm[r * 4 + wn]       = s0;
            ssm[(r + 8) * 4 + wn] = s1;
        }
    }
    __syncthreads();

    float wv[8];
#pragma unroll
    for (int nf = 0; nf < 4; nf++) {
        wv[nf * 2]     = normw[wn * 32 + nf * 8 + ec];
        wv[nf * 2 + 1] = normw[wn * 32 + nf * 8 + ec + 1];
    }

#pragma unroll
    for (int mf = 0; mf < 4; mf++) {
        const int r0 = wm * 64 + mf * 16 + er, r1 = r0 + 8;
        float inv0 = rsqrtf((ssm[r0 * 4] + ssm[r0 * 4 + 1] + ssm[r0 * 4 + 2] + ssm[r0 * 4 + 3]) * (1.f / D) + 1e-6f);
        float inv1 = rsqrtf((ssm[r1 * 4] + ssm[r1 * 4 + 1] + ssm[r1 * 4 + 2] + ssm[r1 * 4 + 3]) * (1.f / D) + 1e-6f);
#pragma unroll
        for (int nf = 0; nf < 4; nf++) {
            const int col = wn * 32 + nf * 8 + ec;
            xt[r0 * XT_STRIDE + col]     = acc[mf][nf][0] * inv0 * wv[nf * 2];
            xt[r0 * XT_STRIDE + col + 1] = acc[mf][nf][1] * inv0 * wv[nf * 2 + 1];
            xt[r1 * XT_STRIDE + col]     = acc[mf][nf][2] * inv1 * wv[nf * 2];
            xt[r1 * XT_STRIDE + col + 1] = acc[mf][nf][3] * inv1 * wv[nf * 2 + 1];
        }
    }
    __syncthreads();

#pragma unroll
    for (int mf = 0; mf < 4; mf++) {
        const int rbase = wm * 64 + mf * 16 + er;
#pragma unroll
        for (int half2i = 0; half2i < 2; half2i++) {
            const int r = rbase + half2i * 8;
            const int sg = bm + r;
#pragma unroll
            for (int nf = 0; nf < 4; nf++) {
                const int col = wn * 32 + nf * 8 + ec;
                float x0 = xt[r * XT_STRIDE + col];
                float x1 = xt[r * XT_STRIDE + col + 1];
                float p0, p1;
                if (col < 64) {
                    p0 = -xt[r * XT_STRIDE + col + 64];
                    p1 = -xt[r * XT_STRIDE + col + 65];
                } else {
                    p0 = xt[r * XT_STRIDE + col - 64];
                    p1 = xt[r * XT_STRIDE + col - 63];
                }
                float c0 = cosp[(size_t)sg * D + col],     sn0 = sinp[(size_t)sg * D + col];
                float c1 = cosp[(size_t)sg * D + col + 1], sn1 = sinp[(size_t)sg * D + col + 1];
                float v0 = fmaf(x0, c0, p0 * sn0);
                float v1 = fmaf(x1, c1, p1 * sn1);
                __half2 h2 = __floats2half2_rn(v0, v1);
                size_t idx = ((size_t)sg * Hh + hHead) * D + col;
                *(__half2*)(Oh + idx) = h2;
                if (MODE == 2) {
                    __half2 l2 = __floats2half2_rn(v0 - __half2float(h2.x), v1 - __half2float(h2.y));
                    *(__half2*)(Ol + idx) = l2;
                }
            }
        }
    }
}

// ---------------------------------------------------------------------------
// MMA flash attention, fp16 2-term: S = Qh(Kh+Kl), O = Ph(Vh+Vl).
// ---------------------------------------------------------------------------
constexpr int AT_SMEM = 81920;
constexpr float SCALE = 0.088388347648318447f;
constexpr float L2E   = 1.4426950408889634f;

__global__ __launch_bounds__(128, 1)
void attn_mma(const __half* __restrict__ Qf,
              const __half* __restrict__ Kh, const __half* __restrict__ Kl,
              const __half* __restrict__ Vh, const __half* __restrict__ Vl,
              __half* __restrict__ Out) {
    extern __shared__ char smem[];
    const uint32_t sb = smem_u32(smem);
    const int tid = threadIdx.x;
    const int w = tid >> 5, lane = tid & 31;
    const int h = blockIdx.y, kvh = h >> 1;
    const int q0 = blockIdx.x * 64;

    const uint32_t QB = sb + 65536;

#pragma unroll
    for (int i = 0; i < 8; i++) {
        int idx = tid + i * 128;
        int r = idx >> 4, c = idx & 15;
        const __half* src = Qf + ((size_t)(q0 + r) * HQ + h) * D + c * 8;
        CP_ASYNC16(QB + sw256(r, c), src);
    }
    CP_COMMIT();
    CP_WAIT0();
    __syncthreads();

    uint32_t qf[8][4];
    {
        const int arow = lane & 15, ahi = lane >> 4;
#pragma unroll
        for (int ks = 0; ks < 8; ks++) {
            uint32_t off = sw256(w * 16 + arow, 2 * ks + ahi);
            LDSM_X4(qf[ks][0], qf[ks][1], qf[ks][2], qf[ks][3], QB + off);
        }
    }

    float o[16][4];
#pragma unroll
    for (int nf = 0; nf < 16; nf++)
#pragma unroll
        for (int x = 0; x < 4; x++) o[nf][x] = 0.f;
    float m0 = 0.f, m1 = 0.f, l0 = 0.f, l1 = 0.f;

    int jlo = q0 - (WINDOW - 1);
    if (jlo < 0) jlo = 0;
    jlo &= ~31;
    const int NT = (q0 + 64 - jlo) >> 5;

    auto issue_kv = [&](int t) {
        const int j0 = jlo + t * 32;
        const uint32_t base = sb + (uint32_t)(t & 1) * 32768;
        const __half* srcs[4] = { Kh, Kl, Vh, Vl };
#pragma unroll
        for (int i = 0; i < 16; i++) {
            int idx = tid + i * 128;
            int ten = idx >> 9;
            int rem = idx & 511;
            int r = rem >> 4, c = rem & 15;
            const __half* src = srcs[ten] + ((size_t)(j0 + r) * HKV + kvh) * D + c * 8;
            CP_ASYNC16(base + ten * 8192 + sw256(r, c), src);
        }
        CP_COMMIT();
    };

    issue_kv(0);
    if (NT > 1) issue_kv(1);

    const int bnrow = (lane & 7) + ((lane >> 4) & 1) * 8;
    const int bhi = (lane >> 3) & 1;
    const int er = lane >> 2, ec = (lane & 3) * 2;
    const int r0g = q0 + w * 16 + er, r1g = r0g + 8;
    const int vg = lane >> 3, vr = lane & 7;

    for (int t = 0; t < NT; t++) {
        if (t < NT - 1) { CP_WAIT1(); } else { CP_WAIT0(); }
        __syncthreads();
        const int j0 = jlo + t * 32;
        const uint32_t base = sb + (uint32_t)(t & 1) * 32768;
        const uint32_t KHB = base, KLB = base + 8192, VHB = base + 16384, VLB = base + 24576;

        float s[4][4];
#pragma unroll
        for (int nf = 0; nf < 4; nf++)
#pragma unroll
            for (int x = 0; x < 4; x++) s[nf][x] = 0.f;
#pragma unroll
        for (int ks = 0; ks < 8; ks++) {
            uint32_t kfh[2][4], kfl[2][4];
            const int ch = 2 * ks + bhi;
            uint32_t off0 = sw256(bnrow, ch), off1 = sw256(16 + bnrow, ch);
            LDSM_X4(kfh[0][0], kfh[0][1], kfh[0][2], kfh[0][3], KHB + off0);
            LDSM_X4(kfh[1][0], kfh[1][1], kfh[1][2], kfh[1][3], KHB + off1);
            LDSM_X4(kfl[0][0], kfl[0][1], kfl[0][2], kfl[0][3], KLB + off0);
            LDSM_X4(kfl[1][0], kfl[1][1], kfl[1][2], kfl[1][3], KLB + off1);
#pragma unroll
            for (int nf = 0; nf < 4; nf++) {
                uint32_t* bhp = &kfh[nf >> 1][(nf & 1) * 2];
                uint32_t* blp = &kfl[nf >> 1][(nf & 1) * 2];
                MMA_F16(s[nf], qf[ks], bhp);
                MMA_F16(s[nf], qf[ks], blp);
            }
        }

        float mn0 = m0, mn1 = m1;
#pragma unroll
        for (int nf = 0; nf < 4; nf++) {
#pragma unroll
            for (int cx = 0; cx < 2; cx++) {
                const int jj = j0 + nf * 8 + ec + cx;
                s[nf][cx]     = (jj <= r0g && jj > r0g - WINDOW) ? s[nf][cx] * SCALE     : -1e9f;
                s[nf][2 + cx] = (jj <= r1g && jj > r1g - WINDOW) ? s[nf][2 + cx] * SCALE : -1e9f;
            }
            mn0 = fmaxf(mn0, fmaxf(s[nf][0], s[nf][1]));
            mn1 = fmaxf(mn1, fmaxf(s[nf][2], s[nf][3]));
        }
        mn0 = fmaxf(mn0, __shfl_xor_sync(0xffffffffu, mn0, 1));
        mn0 = fmaxf(mn0, __shfl_xor_sync(0xffffffffu, mn0, 2));
        mn1 = fmaxf(mn1, __shfl_xor_sync(0xffffffffu, mn1, 1));
        mn1 = fmaxf(mn1, __shfl_xor_sync(0xffffffffu, mn1, 2));
        const float a0 = exp2f((m0 - mn0) * L2E);
        const float a1 = exp2f((m1 - mn1) * L2E);
        m0 = mn0; m1 = mn1;

        float rs0 = 0.f, rs1 = 0.f;
        uint32_t ph[2][4];
#pragma unroll
        for (int kk = 0; kk < 2; kk++) {
            float p[2][4];
#pragma unroll
            for (int q2 = 0; q2 < 2; q2++) {
                const int nf = 2 * kk + q2;
                p[q2][0] = exp2f((s[nf][0] - m0) * L2E);
                p[q2][1] = exp2f((s[nf][1] - m0) * L2E);
                p[q2][2] = exp2f((s[nf][2] - m1) * L2E);
                p[q2][3] = exp2f((s[nf][3] - m1) * L2E);
                rs0 += p[q2][0] + p[q2][1];
                rs1 += p[q2][2] + p[q2][3];
            }
            ph[kk][0] = pack_h2(p[0][0], p[0][1]);
            ph[kk][1] = pack_h2(p[0][2], p[0][3]);
            ph[kk][2] = pack_h2(p[1][0], p[1][1]);
            ph[kk][3] = pack_h2(p[1][2], p[1][3]);
        }
        rs0 += __shfl_xor_sync(0xffffffffu, rs0, 1);
        rs0 += __shfl_xor_sync(0xffffffffu, rs0, 2);
        rs1 += __shfl_xor_sync(0xffffffffu, rs1, 1);
        rs1 += __shfl_xor_sync(0xffffffffu, rs1, 2);
        l0 = l0 * a0 + rs0;
        l1 = l1 * a1 + rs1;

#pragma unroll
        for (int nf = 0; nf < 16; nf++) {
            o[nf][0] *= a0; o[nf][1] *= a0;
            o[nf][2] *= a1; o[nf][3] *= a1;
        }

#pragma unroll
        for (int kk = 0; kk < 2; kk++) {
            const int vrow = kk * 16 + (vg & 1) * 8 + vr;
#pragma unroll
            for (int nc = 0; nc < 8; nc++) {
                uint32_t vfh[4], vfl[4];
                uint32_t off = sw256(vrow, nc * 2 + (vg >> 1));
                LDSM_X4_T(vfh[0], vfh[1], vfh[2], vfh[3], VHB + off);
                LDSM_X4_T(vfl[0], vfl[1], vfl[2], vfl[3], VLB + off);
                MMA_F16(o[nc * 2],     ph[kk], &vfh[0]);
                MMA_F16(o[nc * 2],     ph[kk], &vfl[0]);
                MMA_F16(o[nc * 2 + 1], ph[kk], &vfh[2]);
                MMA_F16(o[nc * 2 + 1], ph[kk], &vfl[2]);
            }
        }
        __syncthreads();
        if (t + 2 < NT) issue_kv(t + 2);
    }

    const float i0 = 1.f / l0, i1 = 1.f / l1;
#pragma unroll
    for (int nf = 0; nf < 16; nf++) {
        const int cc = nf * 8 + ec;
        *(__half2*)(Out + ((size_t)r0g * HQ + h) * D + cc) = __floats2half2_rn(o[nf][0] * i0, o[nf][1] * i0);
        *(__half2*)(Out + ((size_t)r1g * HQ + h) * D + cc) = __floats2half2_rn(o[nf][2] * i1, o[nf][3] * i1);
    }
}

// ---------------------------------------------------------------------------
extern "C" void kernel_launch(void* const* d_in, const int* in_sizes, int n_in,
                              void* d_out, int out_size) {
    const float* hidden = (const float*)d_in[0];
    const float* cosp   = (const float*)d_in[1];
    const float* sinp   = (const float*)d_in[2];
    const float* Wq     = (const float*)d_in[3];
    const float* Wk     = (const float*)d_in[4];
    const float* Wv     = (const float*)d_in[5];
    const float* Wo     = (const float*)d_in[6];
    const float* qw     = (const float*)d_in[7];
    const float* kw     = (const float*)d_in[8];
    float* out = (float*)d_out;

    __half *hh, *wq, *wk, *wv, *wo, *ah;
    __half *qf, *kfh, *kfl, *vfh, *vfl;
    cudaGetSymbolAddress((void**)&hh, g_hh);
    cudaGetSymbolAddress((void**)&wq, g_wq);
    cudaGetSymbolAddress((void**)&wk, g_wk);
    cudaGetSymbolAddress((void**)&wv, g_wv);
    cudaGetSymbolAddress((void**)&wo, g_wo);
    cudaGetSymbolAddress((void**)&ah, g_ah);
    cudaGetSymbolAddress((void**)&qf,  g_qf);
    cudaGetSymbolAddress((void**)&kfh, g_kfh); cudaGetSymbolAddress((void**)&kfl, g_kfl);
    cudaGetSymbolAddress((void**)&vfh, g_vfh); cudaGetSymbolAddress((void**)&vfl, g_vfl);

    cudaFuncSetAttribute(gemm_fused<0>, cudaFuncAttributeMaxDynamicSharedMemorySize, GEMM_SMEM);
    cudaFuncSetAttribute(gemm_fused<1>, cudaFuncAttributeMaxDynamicSharedMemorySize, GEMM_SMEM);
    cudaFuncSetAttribute(gemm_fused<2>, cudaFuncAttributeMaxDynamicSharedMemorySize, GEMM_SMEM);
    cudaFuncSetAttribute(gemm_fused<3>, cudaFuncAttributeMaxDynamicSharedMemorySize, GEMM_SMEM);
    cudaFuncSetAttribute(attn_mma, cudaFuncAttributeMaxDynamicSharedMemorySize, AT_SMEM);

    const int nH = S * HID, nWq = HQ * D * HID, nWk = HKV * D * HID, nWo = HID * HQ * D;
    conv_h<<<nH / 1024, 256>>>(hidden, hh, nH);
    conv_h<<<nWq / 1024, 256>>>(Wq, wq, nWq);
    conv_h<<<nWk / 1024, 256>>>(Wk, wk, nWk);
    conv_h<<<nWk / 1024, 256>>>(Wv, wv, nWk);
    conv_h<<<nWo / 1024, 256>>>(Wo, wo, nWo);

    // QKV projections with fused epilogues
    gemm_fused<1><<<dim3((HQ * D) / 128, S / 128), 256, GEMM_SMEM>>>(
        hh, wq, nullptr, qf, nullptr, qw, cosp, sinp, HQ * D, HID, HQ);
    gemm_fused<2><<<dim3((HKV * D) / 128, S / 128), 256, GEMM_SMEM>>>(
        hh, wk, nullptr, kfh, kfl, kw, cosp, sinp, HKV * D, HID, HKV);
    gemm_fused<3><<<dim3((HKV * D) / 128, S / 128), 256, GEMM_SMEM>>>(
        hh, wv, nullptr, vfh, vfl, nullptr, nullptr, nullptr, HKV * D, HID, HKV);

    attn_mma<<<dim3(S / 64, HQ), 128, AT_SMEM>>>(qf, kfh, kfl, vfh, vfl, ah);

    gemm_fused<0><<<dim3(HID / 128, S / 128), 256, GEMM_SMEM>>>(
        ah, wo, out, nullptr, nullptr, nullptr, nullptr, nullptr, HID, HQ * D, 0);
}

// round 12
// speedup vs baseline: 7.4944x; 1.1524x over previous
#include <cuda_runtime.h>
#include <cuda_bf16.h>
#include <cuda_fp16.h>
#include <math.h>
#include <cstdint>

constexpr int S = 4096, HID = 2048, HQ = 16, HKV = 8, D = 128, WINDOW = 1024;

// fp16 operands
__device__ __half g_hh[(size_t)S * HID];
__device__ __half g_wq[(size_t)HQ * D * HID];
__device__ __half g_wk[(size_t)HKV * D * HID];
__device__ __half g_wv[(size_t)HKV * D * HID];
__device__ __half g_wo[(size_t)HID * HQ * D];
__device__ __half g_ah[(size_t)S * HQ * D];
__device__ __half g_qf[(size_t)S * HQ * D];
__device__ __half g_kf[(size_t)S * HKV * D];
__device__ __half g_vf[(size_t)S * HKV * D];

// ---------------------------------------------------------------------------
__device__ __forceinline__ uint32_t smem_u32(const void* p) {
    uint32_t a;
    asm("{ .reg .u64 t; cvta.to.shared.u64 t, %1; cvt.u32.u64 %0, t; }" : "=r"(a) : "l"(p));
    return a;
}
__device__ __forceinline__ uint32_t swz(uint32_t o) { return o ^ ((o >> 3) & 0x70); }
__device__ __forceinline__ uint32_t sw256(int r, int c) {
    return (uint32_t)(r * 256 + (((c ^ r) & 7) << 4) + ((c & 8) << 4));
}

#define CP_ASYNC16(dst, src) \
    asm volatile("cp.async.cg.shared.global [%0], [%1], 16;" :: "r"(dst), "l"(src))
#define CP_COMMIT() asm volatile("cp.async.commit_group;" ::: "memory")
#define CP_WAIT1()  asm volatile("cp.async.wait_group 1;" ::: "memory")
#define CP_WAIT0()  asm volatile("cp.async.wait_group 0;" ::: "memory")

#define LDSM_X4(r0, r1, r2, r3, addr) \
    asm volatile("ldmatrix.sync.aligned.m8n8.x4.shared.b16 {%0,%1,%2,%3}, [%4];" \
                 : "=r"(r0), "=r"(r1), "=r"(r2), "=r"(r3) : "r"(addr))
#define LDSM_X4_T(r0, r1, r2, r3, addr) \
    asm volatile("ldmatrix.sync.aligned.m8n8.x4.trans.shared.b16 {%0,%1,%2,%3}, [%4];" \
                 : "=r"(r0), "=r"(r1), "=r"(r2), "=r"(r3) : "r"(addr))

#define MMA_F16(d, a, b) \
    asm volatile("mma.sync.aligned.m16n8k16.row.col.f32.f16.f16.f32 " \
                 "{%0,%1,%2,%3},{%4,%5,%6,%7},{%8,%9},{%0,%1,%2,%3};" \
                 : "+f"((d)[0]), "+f"((d)[1]), "+f"((d)[2]), "+f"((d)[3]) \
                 : "r"((a)[0]), "r"((a)[1]), "r"((a)[2]), "r"((a)[3]), \
                   "r"((b)[0]), "r"((b)[1]))

__device__ __forceinline__ uint32_t pack_h2(float a, float b) {
    __half2 t = __floats2half2_rn(a, b);
    return *(uint32_t*)&t;
}

// ---------------------------------------------------------------------------
__global__ __launch_bounds__(256)
void conv_h(const float* __restrict__ x, __half* __restrict__ hi, int n) {
    int i = (blockIdx.x * 256 + threadIdx.x) * 4;
    if (i >= n) return;
    float4 v = *(const float4*)(x + i);
    *(__half2*)(hi + i)     = __floats2half2_rn(v.x, v.y);
    *(__half2*)(hi + i + 2) = __floats2half2_rn(v.z, v.w);
}

// ---------------------------------------------------------------------------
// fp16 GEMM with fused epilogues.
// MODE 0: plain fp32 C              (Wo projection)
// MODE 1: RMSNorm+RoPE -> fp16 Oh   (Q and K)
// MODE 3: fp16 convert -> Oh        (V)
// ---------------------------------------------------------------------------
constexpr int TILE_BYTES = 128 * 64 * 2;
constexpr int BUF_BYTES  = 2 * TILE_BYTES;
constexpr int XT_STRIDE  = 132;                        // padded fp32 row
constexpr int GEMM_SMEM  = 128 * XT_STRIDE * 4 + 2048; // 69632 >= 64KB pipeline

template<int MODE>
__global__ __launch_bounds__(256, 2)
void gemm_fused(const __half* __restrict__ A, const __half* __restrict__ B,
                float* __restrict__ Cf, __half* __restrict__ Oh,
                const float* __restrict__ normw,
                const float* __restrict__ cosp, const float* __restrict__ sinp,
                int N, int K, int Hh) {
    extern __shared__ char smem[];
    const uint32_t sb = smem_u32(smem);
    const int tid = threadIdx.x;
    const int wid = tid >> 5;
    const int lane = tid & 31;
    const int wm = wid >> 2;
    const int wn = wid & 3;
    const int bm = blockIdx.y * 128;
    const int bn = blockIdx.x * 128;

    const __half* srcs[2] = { A, B };
    const int row0s[2] = { bm, bn };

    auto issue_copy = [&](int c) {
        const uint32_t base = sb + (uint32_t)(c & 1) * BUF_BYTES;
        const int k0 = c << 6;
#pragma unroll
        for (int t = 0; t < 2; t++) {
            const __half* src = srcs[t];
            const int row0 = row0s[t];
            const uint32_t tbase = base + t * TILE_BYTES;
#pragma unroll
            for (int i = 0; i < 4; i++) {
                int idx = tid + i * 256;
                int r  = idx >> 3;
                int cc = idx & 7;
                uint32_t dst = tbase + swz((uint32_t)(r * 128 + cc * 16));
                const void* s = src + (size_t)(row0 + r) * K + k0 + cc * 8;
                CP_ASYNC16(dst, s);
            }
        }
        CP_COMMIT();
    };

    float acc[4][4][4];
#pragma unroll
    for (int a = 0; a < 4; a++)
#pragma unroll
        for (int b = 0; b < 4; b++)
#pragma unroll
            for (int x = 0; x < 4; x++) acc[a][b][x] = 0.f;

    const int arow = (lane & 15);
    const int ahi  = lane >> 4;
    uint32_t a_rowoff[4];
#pragma unroll
    for (int mf = 0; mf < 4; mf++)
        a_rowoff[mf] = (uint32_t)((wm * 64 + mf * 16 + arow) * 128);
    const uint32_t arx = (uint32_t)(arow & 7);

    const int bnrow = (lane & 7) + ((lane >> 4) & 1) * 8;
    const int bhi   = (lane >> 3) & 1;
    uint32_t b_rowoff[2];
#pragma unroll
    for (int bf = 0; bf < 2; bf++)
        b_rowoff[bf] = (uint32_t)((wn * 32 + bf * 16 + bnrow) * 128);
    const uint32_t brx = (uint32_t)(bnrow & 7);

    const int NC = K >> 6;
    issue_copy(0);
    if (NC > 1) issue_copy(1);

    for (int c = 0; c < NC; c++) {
        if (c < NC - 1) { CP_WAIT1(); } else { CP_WAIT0(); }
        __syncthreads();

        const uint32_t base = sb + (uint32_t)(c & 1) * BUF_BYTES;
        const uint32_t A_b = base;
        const uint32_t B_b = base + TILE_BYTES;

#pragma unroll
        for (int ks = 0; ks < 4; ks++) {
            uint32_t ah[4][4], bh[2][4];
            const uint32_t ac = (uint32_t)(ks * 2 + ahi);
            const uint32_t bc = (uint32_t)(ks * 2 + bhi);
#pragma unroll
            for (int mf = 0; mf < 4; mf++) {
                uint32_t off = a_rowoff[mf] + ((ac ^ arx) << 4);
                LDSM_X4(ah[mf][0], ah[mf][1], ah[mf][2], ah[mf][3], A_b + off);
            }
#pragma unroll
            for (int bf = 0; bf < 2; bf++) {
                uint32_t off = b_rowoff[bf] + ((bc ^ brx) << 4);
                LDSM_X4(bh[bf][0], bh[bf][1], bh[bf][2], bh[bf][3], B_b + off);
            }
#pragma unroll
            for (int mf = 0; mf < 4; mf++)
#pragma unroll
                for (int nf = 0; nf < 4; nf++) {
                    MMA_F16(acc[mf][nf], ah[mf], (&bh[nf >> 1][(nf & 1) * 2]));
                }
        }
        __syncthreads();
        if (c + 2 < NC) issue_copy(c + 2);
    }

    const int er = lane >> 2;
    const int ec = (lane & 3) * 2;

    if (MODE == 0) {
#pragma unroll
        for (int mf = 0; mf < 4; mf++) {
            const int r0 = bm + wm * 64 + mf * 16 + er;
#pragma unroll
            for (int nf = 0; nf < 4; nf++) {
                const int cc = bn + wn * 32 + nf * 8 + ec;
                *(float2*)(Cf + (size_t)r0 * N + cc)       = make_float2(acc[mf][nf][0], acc[mf][nf][1]);
                *(float2*)(Cf + (size_t)(r0 + 8) * N + cc) = make_float2(acc[mf][nf][2], acc[mf][nf][3]);
            }
        }
        return;
    }

    const int hHead = bn >> 7;   // one head per 128-col tile

    if (MODE == 3) {
#pragma unroll
        for (int mf = 0; mf < 4; mf++) {
            const int s0 = bm + wm * 64 + mf * 16 + er;
#pragma unroll
            for (int nf = 0; nf < 4; nf++) {
                const int col = wn * 32 + nf * 8 + ec;
#pragma unroll
                for (int half2i = 0; half2i < 2; half2i++) {
                    const int sg = s0 + half2i * 8;
                    __half2 h2 = __floats2half2_rn(acc[mf][nf][half2i * 2], acc[mf][nf][half2i * 2 + 1]);
                    *(__half2*)(Oh + ((size_t)sg * Hh + hHead) * D + col) = h2;
                }
            }
        }
        return;
    }

    // MODE 1: RMSNorm + RoPE -> fp16
    float* xt  = (float*)smem;                         // [128][XT_STRIDE]
    float* ssm = (float*)(smem + 128 * XT_STRIDE * 4); // [128][4]

#pragma unroll
    for (int mf = 0; mf < 4; mf++) {
        float s0 = 0.f, s1 = 0.f;
#pragma unroll
        for (int nf = 0; nf < 4; nf++) {
            s0 += acc[mf][nf][0] * acc[mf][nf][0] + acc[mf][nf][1] * acc[mf][nf][1];
            s1 += acc[mf][nf][2] * acc[mf][nf][2] + acc[mf][nf][3] * acc[mf][nf][3];
        }
        s0 += __shfl_xor_sync(0xffffffffu, s0, 1);
        s0 += __shfl_xor_sync(0xffffffffu, s0, 2);
        s1 += __shfl_xor_sync(0xffffffffu, s1, 1);
        s1 += __shfl_xor_sync(0xffffffffu, s1, 2);
        if ((lane & 3) == 0) {
            int r = wm * 64 + mf * 16 + er;
            ssm[r * 4 + wn]       = s0;
            ssm[(r + 8) * 4 + wn] = s1;
        }
    }
    __syncthreads();

    float wv[8];
#pragma unroll
    for (int nf = 0; nf < 4; nf++) {
        wv[nf * 2]     = normw[wn * 32 + nf * 8 + ec];
        wv[nf * 2 + 1] = normw[wn * 32 + nf * 8 + ec + 1];
    }

#pragma unroll
    for (int mf = 0; mf < 4; mf++) {
        const int r0 = wm * 64 + mf * 16 + er, r1 = r0 + 8;
        float inv0 = rsqrtf((ssm[r0 * 4] + ssm[r0 * 4 + 1] + ssm[r0 * 4 + 2] + ssm[r0 * 4 + 3]) * (1.f / D) + 1e-6f);
        float inv1 = rsqrtf((ssm[r1 * 4] + ssm[r1 * 4 + 1] + ssm[r1 * 4 + 2] + ssm[r1 * 4 + 3]) * (1.f / D) + 1e-6f);
#pragma unroll
        for (int nf = 0; nf < 4; nf++) {
            const int col = wn * 32 + nf * 8 + ec;
            xt[r0 * XT_STRIDE + col]     = acc[mf][nf][0] * inv0 * wv[nf * 2];
            xt[r0 * XT_STRIDE + col + 1] = acc[mf][nf][1] * inv0 * wv[nf * 2 + 1];
            xt[r1 * XT_STRIDE + col]     = acc[mf][nf][2] * inv1 * wv[nf * 2];
            xt[r1 * XT_STRIDE + col + 1] = acc[mf][nf][3] * inv1 * wv[nf * 2 + 1];
        }
    }
    __syncthreads();

#pragma unroll
    for (int mf = 0; mf < 4; mf++) {
        const int rbase = wm * 64 + mf * 16 + er;
#pragma unroll
        for (int half2i = 0; half2i < 2; half2i++) {
            const int r = rbase + half2i * 8;
            const int sg = bm + r;
#pragma unroll
            for (int nf = 0; nf < 4; nf++) {
                const int col = wn * 32 + nf * 8 + ec;
                float x0 = xt[r * XT_STRIDE + col];
                float x1 = xt[r * XT_STRIDE + col + 1];
                float p0, p1;
                if (col < 64) {
                    p0 = -xt[r * XT_STRIDE + col + 64];
                    p1 = -xt[r * XT_STRIDE + col + 65];
                } else {
                    p0 = xt[r * XT_STRIDE + col - 64];
                    p1 = xt[r * XT_STRIDE + col - 63];
                }
                float c0 = cosp[(size_t)sg * D + col],     sn0 = sinp[(size_t)sg * D + col];
                float c1 = cosp[(size_t)sg * D + col + 1], sn1 = sinp[(size_t)sg * D + col + 1];
                float v0 = fmaf(x0, c0, p0 * sn0);
                float v1 = fmaf(x1, c1, p1 * sn1);
                *(__half2*)(Oh + ((size_t)sg * Hh + hHead) * D + col) = __floats2half2_rn(v0, v1);
            }
        }
    }
}

// ---------------------------------------------------------------------------
// MMA flash attention, plain fp16: S = Q K^T, O = P V. fp32 softmax.
// 4 warps, 64 queries/CTA, 32-key tiles, 2 CTAs/SM.
// ---------------------------------------------------------------------------
constexpr int AT_SMEM = 49152;   // 2 x 16KB KV + 16KB Q
constexpr float SCALE = 0.088388347648318447f;
constexpr float L2E   = 1.4426950408889634f;

__global__ __launch_bounds__(128, 2)
void attn_mma(const __half* __restrict__ Qf, const __half* __restrict__ Kf,
              const __half* __restrict__ Vf, __half* __restrict__ Out) {
    extern __shared__ char smem[];
    const uint32_t sb = smem_u32(smem);
    const int tid = threadIdx.x;
    const int w = tid >> 5, lane = tid & 31;
    const int h = blockIdx.y, kvh = h >> 1;
    const int q0 = blockIdx.x * 64;

    const uint32_t QB = sb + 32768;

#pragma unroll
    for (int i = 0; i < 8; i++) {
        int idx = tid + i * 128;
        int r = idx >> 4, c = idx & 15;
        const __half* src = Qf + ((size_t)(q0 + r) * HQ + h) * D + c * 8;
        CP_ASYNC16(QB + sw256(r, c), src);
    }
    CP_COMMIT();
    CP_WAIT0();
    __syncthreads();

    uint32_t qf[8][4];
    {
        const int arow = lane & 15, ahi = lane >> 4;
#pragma unroll
        for (int ks = 0; ks < 8; ks++) {
            uint32_t off = sw256(w * 16 + arow, 2 * ks + ahi);
            LDSM_X4(qf[ks][0], qf[ks][1], qf[ks][2], qf[ks][3], QB + off);
        }
    }

    float o[16][4];
#pragma unroll
    for (int nf = 0; nf < 16; nf++)
#pragma unroll
        for (int x = 0; x < 4; x++) o[nf][x] = 0.f;
    float m0 = 0.f, m1 = 0.f, l0 = 0.f, l1 = 0.f;

    int jlo = q0 - (WINDOW - 1);
    if (jlo < 0) jlo = 0;
    jlo &= ~31;
    const int NT = (q0 + 64 - jlo) >> 5;

    auto issue_kv = [&](int t) {
        const int j0 = jlo + t * 32;
        const uint32_t base = sb + (uint32_t)(t & 1) * 16384;
        const __half* srcs[2] = { Kf, Vf };
#pragma unroll
        for (int i = 0; i < 8; i++) {
            int idx = tid + i * 128;
            int ten = idx >> 9;
            int rem = idx & 511;
            int r = rem >> 4, c = rem & 15;
            const __half* src = srcs[ten] + ((size_t)(j0 + r) * HKV + kvh) * D + c * 8;
            CP_ASYNC16(base + ten * 8192 + sw256(r, c), src);
        }
        CP_COMMIT();
    };

    issue_kv(0);
    if (NT > 1) issue_kv(1);

    const int bnrow = (lane & 7) + ((lane >> 4) & 1) * 8;
    const int bhi = (lane >> 3) & 1;
    const int er = lane >> 2, ec = (lane & 3) * 2;
    const int r0g = q0 + w * 16 + er, r1g = r0g + 8;
    const int vg = lane >> 3, vr = lane & 7;

    for (int t = 0; t < NT; t++) {
        if (t < NT - 1) { CP_WAIT1(); } else { CP_WAIT0(); }
        __syncthreads();
        const int j0 = jlo + t * 32;
        const uint32_t base = sb + (uint32_t)(t & 1) * 16384;
        const uint32_t KB = base, VB = base + 8192;

        float s[4][4];
#pragma unroll
        for (int nf = 0; nf < 4; nf++)
#pragma unroll
            for (int x = 0; x < 4; x++) s[nf][x] = 0.f;
#pragma unroll
        for (int ks = 0; ks < 8; ks++) {
            uint32_t kf[2][4];
            const int ch = 2 * ks + bhi;
            LDSM_X4(kf[0][0], kf[0][1], kf[0][2], kf[0][3], KB + sw256(bnrow, ch));
            LDSM_X4(kf[1][0], kf[1][1], kf[1][2], kf[1][3], KB + sw256(16 + bnrow, ch));
#pragma unroll
            for (int nf = 0; nf < 4; nf++) {
                MMA_F16(s[nf], qf[ks], (&kf[nf >> 1][(nf & 1) * 2]));
            }
        }

        float mn0 = m0, mn1 = m1;
#pragma unroll
        for (int nf = 0; nf < 4; nf++) {
#pragma unroll
            for (int cx = 0; cx < 2; cx++) {
                const int jj = j0 + nf * 8 + ec + cx;
                s[nf][cx]     = (jj <= r0g && jj > r0g - WINDOW) ? s[nf][cx] * SCALE     : -1e9f;
                s[nf][2 + cx] = (jj <= r1g && jj > r1g - WINDOW) ? s[nf][2 + cx] * SCALE : -1e9f;
            }
            mn0 = fmaxf(mn0, fmaxf(s[nf][0], s[nf][1]));
            mn1 = fmaxf(mn1, fmaxf(s[nf][2], s[nf][3]));
        }
        mn0 = fmaxf(mn0, __shfl_xor_sync(0xffffffffu, mn0, 1));
        mn0 = fmaxf(mn0, __shfl_xor_sync(0xffffffffu, mn0, 2));
        mn1 = fmaxf(mn1, __shfl_xor_sync(0xffffffffu, mn1, 1));
        mn1 = fmaxf(mn1, __shfl_xor_sync(0xffffffffu, mn1, 2));
        const float a0 = exp2f((m0 - mn0) * L2E);
        const float a1 = exp2f((m1 - mn1) * L2E);
        m0 = mn0; m1 = mn1;

        float rs0 = 0.f, rs1 = 0.f;
        uint32_t ph[2][4];
#pragma unroll
        for (int kk = 0; kk < 2; kk++) {
            float p[2][4];
#pragma unroll
            for (int q2 = 0; q2 < 2; q2++) {
                const int nf = 2 * kk + q2;
                p[q2][0] = exp2f((s[nf][0] - m0) * L2E);
                p[q2][1] = exp2f((s[nf][1] - m0) * L2E);
                p[q2][2] = exp2f((s[nf][2] - m1) * L2E);
                p[q2][3] = exp2f((s[nf][3] - m1) * L2E);
                rs0 += p[q2][0] + p[q2][1];
                rs1 += p[q2][2] + p[q2][3];
            }
            ph[kk][0] = pack_h2(p[0][0], p[0][1]);
            ph[kk][1] = pack_h2(p[0][2], p[0][3]);
            ph[kk][2] = pack_h2(p[1][0], p[1][1]);
            ph[kk][3] = pack_h2(p[1][2], p[1][3]);
        }
        rs0 += __shfl_xor_sync(0xffffffffu, rs0, 1);
        rs0 += __shfl_xor_sync(0xffffffffu, rs0, 2);
        rs1 += __shfl_xor_sync(0xffffffffu, rs1, 1);
        rs1 += __shfl_xor_sync(0xffffffffu, rs1, 2);
        l0 = l0 * a0 + rs0;
        l1 = l1 * a1 + rs1;

#pragma unroll
        for (int nf = 0; nf < 16; nf++) {
            o[nf][0] *= a0; o[nf][1] *= a0;
            o[nf][2] *= a1; o[nf][3] *= a1;
        }

#pragma unroll
        for (int kk = 0; kk < 2; kk++) {
            const int vrow = kk * 16 + (vg & 1) * 8 + vr;
#pragma unroll
            for (int nc = 0; nc < 8; nc++) {
                uint32_t vf[4];
                LDSM_X4_T(vf[0], vf[1], vf[2], vf[3], VB + sw256(vrow, nc * 2 + (vg >> 1)));
                MMA_F16(o[nc * 2],     ph[kk], &vf[0]);
                MMA_F16(o[nc * 2 + 1], ph[kk], &vf[2]);
            }
        }
        __syncthreads();
        if (t + 2 < NT) issue_kv(t + 2);
    }

    const float i0 = 1.f / l0, i1 = 1.f / l1;
#pragma unroll
    for (int nf = 0; nf < 16; nf++) {
        const int cc = nf * 8 + ec;
        *(__half2*)(Out + ((size_t)r0g * HQ + h) * D + cc) = __floats2half2_rn(o[nf][0] * i0, o[nf][1] * i0);
        *(__half2*)(Out + ((size_t)r1g * HQ + h) * D + cc) = __floats2half2_rn(o[nf][2] * i1, o[nf][3] * i1);
    }
}

// ---------------------------------------------------------------------------
extern "C" void kernel_launch(void* const* d_in, const int* in_sizes, int n_in,
                              void* d_out, int out_size) {
    const float* hidden = (const float*)d_in[0];
    const float* cosp   = (const float*)d_in[1];
    const float* sinp   = (const float*)d_in[2];
    const float* Wq     = (const float*)d_in[3];
    const float* Wk     = (const float*)d_in[4];
    const float* Wv     = (const float*)d_in[5];
    const float* Wo     = (const float*)d_in[6];
    const float* qw     = (const float*)d_in[7];
    const float* kw     = (const float*)d_in[8];
    float* out = (float*)d_out;

    __half *hh, *wq, *wk, *wv, *wo, *ah, *qf, *kf, *vf;
    cudaGetSymbolAddress((void**)&hh, g_hh);
    cudaGetSymbolAddress((void**)&wq, g_wq);
    cudaGetSymbolAddress((void**)&wk, g_wk);
    cudaGetSymbolAddress((void**)&wv, g_wv);
    cudaGetSymbolAddress((void**)&wo, g_wo);
    cudaGetSymbolAddress((void**)&ah, g_ah);
    cudaGetSymbolAddress((void**)&qf, g_qf);
    cudaGetSymbolAddress((void**)&kf, g_kf);
    cudaGetSymbolAddress((void**)&vf, g_vf);

    cudaFuncSetAttribute(gemm_fused<0>, cudaFuncAttributeMaxDynamicSharedMemorySize, GEMM_SMEM);
    cudaFuncSetAttribute(gemm_fused<1>, cudaFuncAttributeMaxDynamicSharedMemorySize, GEMM_SMEM);
    cudaFuncSetAttribute(gemm_fused<3>, cudaFuncAttributeMaxDynamicSharedMemorySize, GEMM_SMEM);
    cudaFuncSetAttribute(attn_mma, cudaFuncAttributeMaxDynamicSharedMemorySize, AT_SMEM);

    const int nH = S * HID, nWq = HQ * D * HID, nWk = HKV * D * HID, nWo = HID * HQ * D;
    conv_h<<<nH / 1024, 256>>>(hidden, hh, nH);
    conv_h<<<nWq / 1024, 256>>>(Wq, wq, nWq);
    conv_h<<<nWk / 1024, 256>>>(Wk, wk, nWk);
    conv_h<<<nWk / 1024, 256>>>(Wv, wv, nWk);
    conv_h<<<nWo / 1024, 256>>>(Wo, wo, nWo);

    gemm_fused<1><<<dim3((HQ * D) / 128, S / 128), 256, GEMM_SMEM>>>(
        hh, wq, nullptr, qf, qw, cosp, sinp, HQ * D, HID, HQ);
    gemm_fused<1><<<dim3((HKV * D) / 128, S / 128), 256, GEMM_SMEM>>>(
        hh, wk, nullptr, kf, kw, cosp, sinp, HKV * D, HID, HKV);
    gemm_fused<3><<<dim3((HKV * D) / 128, S / 128), 256, GEMM_SMEM>>>(
        hh, wv, nullptr, vf, nullptr, nullptr, nullptr, HKV * D, HID, HKV);

    attn_mma<<<dim3(S / 64, HQ), 128, AT_SMEM>>>(qf, kf, vf, ah);

    gemm_fused<0><<<dim3(HID / 128, S / 128), 256, GEMM_SMEM>>>(
        ah, wo, out, nullptr, nullptr, nullptr, nullptr, HID, HQ * D, 0);
}

// round 13
// speedup vs baseline: 8.1498x; 1.0875x over previous
#include <cuda_runtime.h>
#include <cuda_bf16.h>
#include <cuda_fp16.h>
#include <math.h>
#include <cstdint>

constexpr int S = 4096, HID = 2048, HQ = 16, HKV = 8, D = 128, WINDOW = 1024;

// fp16 operands
__device__ __half g_hh[(size_t)S * HID];
__device__ __half g_wqkv[(size_t)(HQ + 2 * HKV) * D * HID];   // [4096, 2048]
__device__ __half g_wo[(size_t)HID * HQ * D];
__device__ __half g_ah[(size_t)S * HQ * D];
__device__ __half g_qf[(size_t)S * HQ * D];
__device__ __half g_kf[(size_t)S * HKV * D];
__device__ __half g_vf[(size_t)S * HKV * D];

// ---------------------------------------------------------------------------
__device__ __forceinline__ uint32_t smem_u32(const void* p) {
    uint32_t a;
    asm("{ .reg .u64 t; cvta.to.shared.u64 t, %1; cvt.u32.u64 %0, t; }" : "=r"(a) : "l"(p));
    return a;
}
__device__ __forceinline__ uint32_t swz(uint32_t o) { return o ^ ((o >> 3) & 0x70); }
__device__ __forceinline__ uint32_t sw256(int r, int c) {
    return (uint32_t)(r * 256 + (((c ^ r) & 7) << 4) + ((c & 8) << 4));
}

#define CP_ASYNC16(dst, src) \
    asm volatile("cp.async.cg.shared.global [%0], [%1], 16;" :: "r"(dst), "l"(src))
#define CP_COMMIT() asm volatile("cp.async.commit_group;" ::: "memory")
#define CP_WAIT1()  asm volatile("cp.async.wait_group 1;" ::: "memory")
#define CP_WAIT0()  asm volatile("cp.async.wait_group 0;" ::: "memory")

#define LDSM_X4(r0, r1, r2, r3, addr) \
    asm volatile("ldmatrix.sync.aligned.m8n8.x4.shared.b16 {%0,%1,%2,%3}, [%4];" \
                 : "=r"(r0), "=r"(r1), "=r"(r2), "=r"(r3) : "r"(addr))
#define LDSM_X4_T(r0, r1, r2, r3, addr) \
    asm volatile("ldmatrix.sync.aligned.m8n8.x4.trans.shared.b16 {%0,%1,%2,%3}, [%4];" \
                 : "=r"(r0), "=r"(r1), "=r"(r2), "=r"(r3) : "r"(addr))

#define MMA_F16(d, a, b) \
    asm volatile("mma.sync.aligned.m16n8k16.row.col.f32.f16.f16.f32 " \
                 "{%0,%1,%2,%3},{%4,%5,%6,%7},{%8,%9},{%0,%1,%2,%3};" \
                 : "+f"((d)[0]), "+f"((d)[1]), "+f"((d)[2]), "+f"((d)[3]) \
                 : "r"((a)[0]), "r"((a)[1]), "r"((a)[2]), "r"((a)[3]), \
                   "r"((b)[0]), "r"((b)[1]))

__device__ __forceinline__ uint32_t pack_h2(float a, float b) {
    __half2 t = __floats2half2_rn(a, b);
    return *(uint32_t*)&t;
}

// ---------------------------------------------------------------------------
// Single merged fp32->fp16 convert over all 5 tensors.
// Segments (in 256-float4 blocks): hidden 8192 | Wq 4096 | Wk 2048 | Wv 2048 | Wo 4096
// ---------------------------------------------------------------------------
constexpr int CB_H  = 8192;
constexpr int CB_WQ = CB_H  + 4096;
constexpr int CB_WK = CB_WQ + 2048;
constexpr int CB_WV = CB_WK + 2048;
constexpr int CB_TOTAL = CB_WV + 4096;      // 20480 blocks

__global__ __launch_bounds__(256)
void conv_all(const float* __restrict__ hidden, const float* __restrict__ Wq,
              const float* __restrict__ Wk, const float* __restrict__ Wv,
              const float* __restrict__ Wo,
              __half* __restrict__ hh, __half* __restrict__ wqkv, __half* __restrict__ wo) {
    const int b = blockIdx.x;
    const float* src;
    __half* dst;
    int rel;
    if (b < CB_H)        { src = hidden; dst = hh;                          rel = b; }
    else if (b < CB_WQ)  { src = Wq;     dst = wqkv;                        rel = b - CB_H; }
    else if (b < CB_WK)  { src = Wk;     dst = wqkv + (size_t)HQ * D * HID; rel = b - CB_WQ; }
    else if (b < CB_WV)  { src = Wv;     dst = wqkv + (size_t)(HQ + HKV) * D * HID; rel = b - CB_WK; }
    else                 { src = Wo;     dst = wo;                          rel = b - CB_WV; }
    int i = (rel * 256 + threadIdx.x) * 4;
    float4 v = *(const float4*)(src + i);
    *(__half2*)(dst + i)     = __floats2half2_rn(v.x, v.y);
    *(__half2*)(dst + i + 2) = __floats2half2_rn(v.z, v.w);
}

// ---------------------------------------------------------------------------
// fp16 GEMM with fused epilogues.
// MODE 0: plain fp32 C (Wo projection)
// MODE 4: QKV dispatch per 128-col tile: 0-15 Q norm+rope, 16-23 K norm+rope, 24-31 V conv
// ---------------------------------------------------------------------------
constexpr int TILE_BYTES = 128 * 64 * 2;
constexpr int BUF_BYTES  = 2 * TILE_BYTES;
constexpr int XT_STRIDE  = 132;
constexpr int GEMM_SMEM  = 128 * XT_STRIDE * 4 + 2048;

template<int MODE>
__global__ __launch_bounds__(256, 2)
void gemm_fused(const __half* __restrict__ A, const __half* __restrict__ B,
                float* __restrict__ Cf,
                __half* __restrict__ qf_o, __half* __restrict__ kf_o, __half* __restrict__ vf_o,
                const float* __restrict__ qw, const float* __restrict__ kw,
                const float* __restrict__ cosp, const float* __restrict__ sinp,
                int N, int K) {
    extern __shared__ char smem[];
    const uint32_t sb = smem_u32(smem);
    const int tid = threadIdx.x;
    const int wid = tid >> 5;
    const int lane = tid & 31;
    const int wm = wid >> 2;
    const int wn = wid & 3;
    const int bm = blockIdx.y * 128;
    const int bn = blockIdx.x * 128;

    const __half* srcs[2] = { A, B };
    const int row0s[2] = { bm, bn };

    auto issue_copy = [&](int c) {
        const uint32_t base = sb + (uint32_t)(c & 1) * BUF_BYTES;
        const int k0 = c << 6;
#pragma unroll
        for (int t = 0; t < 2; t++) {
            const __half* src = srcs[t];
            const int row0 = row0s[t];
            const uint32_t tbase = base + t * TILE_BYTES;
#pragma unroll
            for (int i = 0; i < 4; i++) {
                int idx = tid + i * 256;
                int r  = idx >> 3;
                int cc = idx & 7;
                uint32_t dst = tbase + swz((uint32_t)(r * 128 + cc * 16));
                const void* s = src + (size_t)(row0 + r) * K + k0 + cc * 8;
                CP_ASYNC16(dst, s);
            }
        }
        CP_COMMIT();
    };

    float acc[4][4][4];
#pragma unroll
    for (int a = 0; a < 4; a++)
#pragma unroll
        for (int b = 0; b < 4; b++)
#pragma unroll
            for (int x = 0; x < 4; x++) acc[a][b][x] = 0.f;

    const int arow = (lane & 15);
    const int ahi  = lane >> 4;
    uint32_t a_rowoff[4];
#pragma unroll
    for (int mf = 0; mf < 4; mf++)
        a_rowoff[mf] = (uint32_t)((wm * 64 + mf * 16 + arow) * 128);
    const uint32_t arx = (uint32_t)(arow & 7);

    const int bnrow = (lane & 7) + ((lane >> 4) & 1) * 8;
    const int bhi   = (lane >> 3) & 1;
    uint32_t b_rowoff[2];
#pragma unroll
    for (int bf = 0; bf < 2; bf++)
        b_rowoff[bf] = (uint32_t)((wn * 32 + bf * 16 + bnrow) * 128);
    const uint32_t brx = (uint32_t)(bnrow & 7);

    const int NC = K >> 6;
    issue_copy(0);
    if (NC > 1) issue_copy(1);

    for (int c = 0; c < NC; c++) {
        if (c < NC - 1) { CP_WAIT1(); } else { CP_WAIT0(); }
        __syncthreads();

        const uint32_t base = sb + (uint32_t)(c & 1) * BUF_BYTES;
        const uint32_t A_b = base;
        const uint32_t B_b = base + TILE_BYTES;

#pragma unroll
        for (int ks = 0; ks < 4; ks++) {
            uint32_t ah[4][4], bh[2][4];
            const uint32_t ac = (uint32_t)(ks * 2 + ahi);
            const uint32_t bc = (uint32_t)(ks * 2 + bhi);
#pragma unroll
            for (int mf = 0; mf < 4; mf++) {
                uint32_t off = a_rowoff[mf] + ((ac ^ arx) << 4);
                LDSM_X4(ah[mf][0], ah[mf][1], ah[mf][2], ah[mf][3], A_b + off);
            }
#pragma unroll
            for (int bf = 0; bf < 2; bf++) {
                uint32_t off = b_rowoff[bf] + ((bc ^ brx) << 4);
                LDSM_X4(bh[bf][0], bh[bf][1], bh[bf][2], bh[bf][3], B_b + off);
            }
#pragma unroll
            for (int mf = 0; mf < 4; mf++)
#pragma unroll
                for (int nf = 0; nf < 4; nf++) {
                    MMA_F16(acc[mf][nf], ah[mf], (&bh[nf >> 1][(nf & 1) * 2]));
                }
        }
        __syncthreads();
        if (c + 2 < NC) issue_copy(c + 2);
    }

    const int er = lane >> 2;
    const int ec = (lane & 3) * 2;

    if (MODE == 0) {
#pragma unroll
        for (int mf = 0; mf < 4; mf++) {
            const int r0 = bm + wm * 64 + mf * 16 + er;
#pragma unroll
            for (int nf = 0; nf < 4; nf++) {
                const int cc = bn + wn * 32 + nf * 8 + ec;
                *(float2*)(Cf + (size_t)r0 * N + cc)       = make_float2(acc[mf][nf][0], acc[mf][nf][1]);
                *(float2*)(Cf + (size_t)(r0 + 8) * N + cc) = make_float2(acc[mf][nf][2], acc[mf][nf][3]);
            }
        }
        return;
    }

    // MODE 4: per-tile dispatch
    const int nTile = bn >> 7;
    __half* Oh;
    const float* nw = nullptr;
    int Hh, head;
    bool donorm;
    if (nTile < 16)      { Oh = qf_o; nw = qw; Hh = HQ;  head = nTile;      donorm = true; }
    else if (nTile < 24) { Oh = kf_o; nw = kw; Hh = HKV; head = nTile - 16; donorm = true; }
    else                 { Oh = vf_o;          Hh = HKV; head = nTile - 24; donorm = false; }

    if (!donorm) {
#pragma unroll
        for (int mf = 0; mf < 4; mf++) {
            const int s0 = bm + wm * 64 + mf * 16 + er;
#pragma unroll
            for (int nf = 0; nf < 4; nf++) {
                const int col = wn * 32 + nf * 8 + ec;
#pragma unroll
                for (int h2i = 0; h2i < 2; h2i++) {
                    const int sg = s0 + h2i * 8;
                    __half2 h2 = __floats2half2_rn(acc[mf][nf][h2i * 2], acc[mf][nf][h2i * 2 + 1]);
                    *(__half2*)(Oh + ((size_t)sg * Hh + head) * D + col) = h2;
                }
            }
        }
        return;
    }

    // RMSNorm + RoPE
    float* xt  = (float*)smem;
    float* ssm = (float*)(smem + 128 * XT_STRIDE * 4);

#pragma unroll
    for (int mf = 0; mf < 4; mf++) {
        float s0 = 0.f, s1 = 0.f;
#pragma unroll
        for (int nf = 0; nf < 4; nf++) {
            s0 += acc[mf][nf][0] * acc[mf][nf][0] + acc[mf][nf][1] * acc[mf][nf][1];
            s1 += acc[mf][nf][2] * acc[mf][nf][2] + acc[mf][nf][3] * acc[mf][nf][3];
        }
        s0 += __shfl_xor_sync(0xffffffffu, s0, 1);
        s0 += __shfl_xor_sync(0xffffffffu, s0, 2);
        s1 += __shfl_xor_sync(0xffffffffu, s1, 1);
        s1 += __shfl_xor_sync(0xffffffffu, s1, 2);
        if ((lane & 3) == 0) {
            int r = wm * 64 + mf * 16 + er;
            ssm[r * 4 + wn]       = s0;
            ssm[(r + 8) * 4 + wn] = s1;
        }
    }
    __syncthreads();

    float wv2[8];
#pragma unroll
    for (int nf = 0; nf < 4; nf++) {
        wv2[nf * 2]     = nw[wn * 32 + nf * 8 + ec];
        wv2[nf * 2 + 1] = nw[wn * 32 + nf * 8 + ec + 1];
    }

#pragma unroll
    for (int mf = 0; mf < 4; mf++) {
        const int r0 = wm * 64 + mf * 16 + er, r1 = r0 + 8;
        float inv0 = rsqrtf((ssm[r0 * 4] + ssm[r0 * 4 + 1] + ssm[r0 * 4 + 2] + ssm[r0 * 4 + 3]) * (1.f / D) + 1e-6f);
        float inv1 = rsqrtf((ssm[r1 * 4] + ssm[r1 * 4 + 1] + ssm[r1 * 4 + 2] + ssm[r1 * 4 + 3]) * (1.f / D) + 1e-6f);
#pragma unroll
        for (int nf = 0; nf < 4; nf++) {
            const int col = wn * 32 + nf * 8 + ec;
            xt[r0 * XT_STRIDE + col]     = acc[mf][nf][0] * inv0 * wv2[nf * 2];
            xt[r0 * XT_STRIDE + col + 1] = acc[mf][nf][1] * inv0 * wv2[nf * 2 + 1];
            xt[r1 * XT_STRIDE + col]     = acc[mf][nf][2] * inv1 * wv2[nf * 2];
            xt[r1 * XT_STRIDE + col + 1] = acc[mf][nf][3] * inv1 * wv2[nf * 2 + 1];
        }
    }
    __syncthreads();

#pragma unroll
    for (int mf = 0; mf < 4; mf++) {
        const int rbase = wm * 64 + mf * 16 + er;
#pragma unroll
        for (int h2i = 0; h2i < 2; h2i++) {
            const int r = rbase + h2i * 8;
            const int sg = bm + r;
#pragma unroll
            for (int nf = 0; nf < 4; nf++) {
                const int col = wn * 32 + nf * 8 + ec;
                float x0 = xt[r * XT_STRIDE + col];
                float x1 = xt[r * XT_STRIDE + col + 1];
                float p0, p1;
                if (col < 64) {
                    p0 = -xt[r * XT_STRIDE + col + 64];
                    p1 = -xt[r * XT_STRIDE + col + 65];
                } else {
                    p0 = xt[r * XT_STRIDE + col - 64];
                    p1 = xt[r * XT_STRIDE + col - 63];
                }
                float c0 = cosp[(size_t)sg * D + col],     sn0 = sinp[(size_t)sg * D + col];
                float c1 = cosp[(size_t)sg * D + col + 1], sn1 = sinp[(size_t)sg * D + col + 1];
                float v0 = fmaf(x0, c0, p0 * sn0);
                float v1 = fmaf(x1, c1, p1 * sn1);
                *(__half2*)(Oh + ((size_t)sg * Hh + head) * D + col) = __floats2half2_rn(v0, v1);
            }
        }
    }
}

// ---------------------------------------------------------------------------
// MMA flash attention, plain fp16: S = Q K^T, O = P V. fp32 softmax.
// ---------------------------------------------------------------------------
constexpr int AT_SMEM = 49152;
constexpr float SCALE = 0.088388347648318447f;
constexpr float L2E   = 1.4426950408889634f;

__global__ __launch_bounds__(128, 2)
void attn_mma(const __half* __restrict__ Qf, const __half* __restrict__ Kf,
              const __half* __restrict__ Vf, __half* __restrict__ Out) {
    extern __shared__ char smem[];
    const uint32_t sb = smem_u32(smem);
    const int tid = threadIdx.x;
    const int w = tid >> 5, lane = tid & 31;
    const int h = blockIdx.y, kvh = h >> 1;
    const int q0 = blockIdx.x * 64;

    const uint32_t QB = sb + 32768;

#pragma unroll
    for (int i = 0; i < 8; i++) {
        int idx = tid + i * 128;
        int r = idx >> 4, c = idx & 15;
        const __half* src = Qf + ((size_t)(q0 + r) * HQ + h) * D + c * 8;
        CP_ASYNC16(QB + sw256(r, c), src);
    }
    CP_COMMIT();
    CP_WAIT0();
    __syncthreads();

    uint32_t qf[8][4];
    {
        const int arow = lane & 15, ahi = lane >> 4;
#pragma unroll
        for (int ks = 0; ks < 8; ks++) {
            uint32_t off = sw256(w * 16 + arow, 2 * ks + ahi);
            LDSM_X4(qf[ks][0], qf[ks][1], qf[ks][2], qf[ks][3], QB + off);
        }
    }

    float o[16][4];
#pragma unroll
    for (int nf = 0; nf < 16; nf++)
#pragma unroll
        for (int x = 0; x < 4; x++) o[nf][x] = 0.f;
    float m0 = 0.f, m1 = 0.f, l0 = 0.f, l1 = 0.f;

    int jlo = q0 - (WINDOW - 1);
    if (jlo < 0) jlo = 0;
    jlo &= ~31;
    const int NT = (q0 + 64 - jlo) >> 5;

    auto issue_kv = [&](int t) {
        const int j0 = jlo + t * 32;
        const uint32_t base = sb + (uint32_t)(t & 1) * 16384;
        const __half* srcs[2] = { Kf, Vf };
#pragma unroll
        for (int i = 0; i < 8; i++) {
            int idx = tid + i * 128;
            int ten = idx >> 9;
            int rem = idx & 511;
            int r = rem >> 4, c = rem & 15;
            const __half* src = srcs[ten] + ((size_t)(j0 + r) * HKV + kvh) * D + c * 8;
            CP_ASYNC16(base + ten * 8192 + sw256(r, c), src);
        }
        CP_COMMIT();
    };

    issue_kv(0);
    if (NT > 1) issue_kv(1);

    const int bnrow = (lane & 7) + ((lane >> 4) & 1) * 8;
    const int bhi = (lane >> 3) & 1;
    const int er = lane >> 2, ec = (lane & 3) * 2;
    const int r0g = q0 + w * 16 + er, r1g = r0g + 8;
    const int vg = lane >> 3, vr = lane & 7;

    for (int t = 0; t < NT; t++) {
        if (t < NT - 1) { CP_WAIT1(); } else { CP_WAIT0(); }
        __syncthreads();
        const int j0 = jlo + t * 32;
        const uint32_t base = sb + (uint32_t)(t & 1) * 16384;
        const uint32_t KB = base, VB = base + 8192;

        float s[4][4];
#pragma unroll
        for (int nf = 0; nf < 4; nf++)
#pragma unroll
            for (int x = 0; x < 4; x++) s[nf][x] = 0.f;
#pragma unroll
        for (int ks = 0; ks < 8; ks++) {
            uint32_t kf[2][4];
            const int ch = 2 * ks + bhi;
            LDSM_X4(kf[0][0], kf[0][1], kf[0][2], kf[0][3], KB + sw256(bnrow, ch));
            LDSM_X4(kf[1][0], kf[1][1], kf[1][2], kf[1][3], KB + sw256(16 + bnrow, ch));
#pragma unroll
            for (int nf = 0; nf < 4; nf++) {
                MMA_F16(s[nf], qf[ks], (&kf[nf >> 1][(nf & 1) * 2]));
            }
        }

        float mn0 = m0, mn1 = m1;
#pragma unroll
        for (int nf = 0; nf < 4; nf++) {
#pragma unroll
            for (int cx = 0; cx < 2; cx++) {
                const int jj = j0 + nf * 8 + ec + cx;
                s[nf][cx]     = (jj <= r0g && jj > r0g - WINDOW) ? s[nf][cx] * SCALE     : -1e9f;
                s[nf][2 + cx] = (jj <= r1g && jj > r1g - WINDOW) ? s[nf][2 + cx] * SCALE : -1e9f;
            }
            mn0 = fmaxf(mn0, fmaxf(s[nf][0], s[nf][1]));
            mn1 = fmaxf(mn1, fmaxf(s[nf][2], s[nf][3]));
        }
        mn0 = fmaxf(mn0, __shfl_xor_sync(0xffffffffu, mn0, 1));
        mn0 = fmaxf(mn0, __shfl_xor_sync(0xffffffffu, mn0, 2));
        mn1 = fmaxf(mn1, __shfl_xor_sync(0xffffffffu, mn1, 1));
        mn1 = fmaxf(mn1, __shfl_xor_sync(0xffffffffu, mn1, 2));
        const float a0 = exp2f((m0 - mn0) * L2E);
        const float a1 = exp2f((m1 - mn1) * L2E);
        m0 = mn0; m1 = mn1;

        float rs0 = 0.f, rs1 = 0.f;
        uint32_t ph[2][4];
#pragma unroll
        for (int kk = 0; kk < 2; kk++) {
            float p[2][4];
#pragma unroll
            for (int q2 = 0; q2 < 2; q2++) {
                const int nf = 2 * kk + q2;
                p[q2][0] = exp2f((s[nf][0] - m0) * L2E);
                p[q2][1] = exp2f((s[nf][1] - m0) * L2E);
                p[q2][2] = exp2f((s[nf][2] - m1) * L2E);
                p[q2][3] = exp2f((s[nf][3] - m1) * L2E);
                rs0 += p[q2][0] + p[q2][1];
                rs1 += p[q2][2] + p[q2][3];
            }
            ph[kk][0] = pack_h2(p[0][0], p[0][1]);
            ph[kk][1] = pack_h2(p[0][2], p[0][3]);
            ph[kk][2] = pack_h2(p[1][0], p[1][1]);
            ph[kk][3] = pack_h2(p[1][2], p[1][3]);
        }
        rs0 += __shfl_xor_sync(0xffffffffu, rs0, 1);
        rs0 += __shfl_xor_sync(0xffffffffu, rs0, 2);
        rs1 += __shfl_xor_sync(0xffffffffu, rs1, 1);
        rs1 += __shfl_xor_sync(0xffffffffu, rs1, 2);
        l0 = l0 * a0 + rs0;
        l1 = l1 * a1 + rs1;

#pragma unroll
        for (int nf = 0; nf < 16; nf++) {
            o[nf][0] *= a0; o[nf][1] *= a0;
            o[nf][2] *= a1; o[nf][3] *= a1;
        }

#pragma unroll
        for (int kk = 0; kk < 2; kk++) {
            const int vrow = kk * 16 + (vg & 1) * 8 + vr;
#pragma unroll
            for (int nc = 0; nc < 8; nc++) {
                uint32_t vf[4];
                LDSM_X4_T(vf[0], vf[1], vf[2], vf[3], VB + sw256(vrow, nc * 2 + (vg >> 1)));
                MMA_F16(o[nc * 2],     ph[kk], &vf[0]);
                MMA_F16(o[nc * 2 + 1], ph[kk], &vf[2]);
            }
        }
        __syncthreads();
        if (t + 2 < NT) issue_kv(t + 2);
    }

    const float i0 = 1.f / l0, i1 = 1.f / l1;
#pragma unroll
    for (int nf = 0; nf < 16; nf++) {
        const int cc = nf * 8 + ec;
        *(__half2*)(Out + ((size_t)r0g * HQ + h) * D + cc) = __floats2half2_rn(o[nf][0] * i0, o[nf][1] * i0);
        *(__half2*)(Out + ((size_t)r1g * HQ + h) * D + cc) = __floats2half2_rn(o[nf][2] * i1, o[nf][3] * i1);
    }
}

// ---------------------------------------------------------------------------
extern "C" void kernel_launch(void* const* d_in, const int* in_sizes, int n_in,
                              void* d_out, int out_size) {
    const float* hidden = (const float*)d_in[0];
    const float* cosp   = (const float*)d_in[1];
    const float* sinp   = (const float*)d_in[2];
    const float* Wq     = (const float*)d_in[3];
    const float* Wk     = (const float*)d_in[4];
    const float* Wv     = (const float*)d_in[5];
    const float* Wo     = (const float*)d_in[6];
    const float* qw     = (const float*)d_in[7];
    const float* kw     = (const float*)d_in[8];
    float* out = (float*)d_out;

    __half *hh, *wqkv, *wo, *ah, *qf, *kf, *vf;
    cudaGetSymbolAddress((void**)&hh,   g_hh);
    cudaGetSymbolAddress((void**)&wqkv, g_wqkv);
    cudaGetSymbolAddress((void**)&wo,   g_wo);
    cudaGetSymbolAddress((void**)&ah,   g_ah);
    cudaGetSymbolAddress((void**)&qf,   g_qf);
    cudaGetSymbolAddress((void**)&kf,   g_kf);
    cudaGetSymbolAddress((void**)&vf,   g_vf);

    cudaFuncSetAttribute(gemm_fused<0>, cudaFuncAttributeMaxDynamicSharedMemorySize, GEMM_SMEM);
    cudaFuncSetAttribute(gemm_fused<4>, cudaFuncAttributeMaxDynamicSharedMemorySize, GEMM_SMEM);
    cudaFuncSetAttribute(attn_mma, cudaFuncAttributeMaxDynamicSharedMemorySize, AT_SMEM);

    conv_all<<<CB_TOTAL, 256>>>(hidden, Wq, Wk, Wv, Wo, hh, wqkv, wo);

    const int NQKV = (HQ + 2 * HKV) * D;   // 4096
    gemm_fused<4><<<dim3(NQKV / 128, S / 128), 256, GEMM_SMEM>>>(
        hh, wqkv, nullptr, qf, kf, vf, qw, kw, cosp, sinp, NQKV, HID);

    attn_mma<<<dim3(S / 64, HQ), 128, AT_SMEM>>>(qf, kf, vf, ah);

    gemm_fused<0><<<dim3(HID / 128, S / 128), 256, GEMM_SMEM>>>(
        ah, wo, out, nullptr, nullptr, nullptr, nullptr, nullptr, nullptr, nullptr, HID, HQ * D);
}